// round 1
// baseline (speedup 1.0000x reference)
#include <cuda_runtime.h>
#include <math.h>

#define NT  4096
#define DM  512
#define NH  8
#define HD  64
#define DFF 1024

// ---------------- scratch (static device globals; no allocations) ----------
__device__ float g_Q[NT * DM];
__device__ float g_K[NT * DM];
__device__ float g_V[NT * DM];
__device__ float g_attn[NT * DM];
__device__ float g_tmp[NT * DM];
__device__ float g_x1[NT * DM];
__device__ float g_hid[NT * DFF];

// ---------------- 128x128x8 register-tiled SGEMM:  C = A@W + bias ----------
template <bool RELU>
__global__ __launch_bounds__(256) void sgemm_bias(
    const float* __restrict__ A, const float* __restrict__ W,
    const float* __restrict__ bias, float* __restrict__ C,
    int M, int N, int K)
{
    __shared__ float As[8][128];
    __shared__ float Ws[8][128];

    const int tid = threadIdx.x;
    const int m0 = blockIdx.y * 128;
    const int n0 = blockIdx.x * 128;
    const int tx = tid & 15, ty = tid >> 4;

    const int arow = tid >> 1;          // 0..127
    const int acol = (tid & 1) * 4;     // 0 or 4
    const int wrow = tid >> 5;          // 0..7
    const int wcol = (tid & 31) * 4;    // 0..124

    float acc[8][8];
#pragma unroll
    for (int i = 0; i < 8; i++)
#pragma unroll
        for (int j = 0; j < 8; j++) acc[i][j] = 0.f;

    for (int k0 = 0; k0 < K; k0 += 8) {
        float4 a = *(const float4*)&A[(size_t)(m0 + arow) * K + k0 + acol];
        float4 w = *(const float4*)&W[(size_t)(k0 + wrow) * N + n0 + wcol];
        As[acol + 0][arow] = a.x;
        As[acol + 1][arow] = a.y;
        As[acol + 2][arow] = a.z;
        As[acol + 3][arow] = a.w;
        *(float4*)&Ws[wrow][wcol] = w;
        __syncthreads();
#pragma unroll
        for (int k = 0; k < 8; k++) {
            float ar[8], wr[8];
            *(float4*)&ar[0] = *(const float4*)&As[k][ty * 8];
            *(float4*)&ar[4] = *(const float4*)&As[k][ty * 8 + 4];
            *(float4*)&wr[0] = *(const float4*)&Ws[k][tx * 8];
            *(float4*)&wr[4] = *(const float4*)&Ws[k][tx * 8 + 4];
#pragma unroll
            for (int i = 0; i < 8; i++)
#pragma unroll
                for (int j = 0; j < 8; j++)
                    acc[i][j] += ar[i] * wr[j];
        }
        __syncthreads();
    }

#pragma unroll
    for (int i = 0; i < 8; i++) {
        int m = m0 + ty * 8 + i;
#pragma unroll
        for (int j = 0; j < 8; j += 4) {
            int n = n0 + tx * 8 + j;
            float4 b = *(const float4*)&bias[n];
            float4 r;
            r.x = acc[i][j + 0] + b.x;
            r.y = acc[i][j + 1] + b.y;
            r.z = acc[i][j + 2] + b.z;
            r.w = acc[i][j + 3] + b.w;
            if (RELU) {
                r.x = fmaxf(r.x, 0.f); r.y = fmaxf(r.y, 0.f);
                r.z = fmaxf(r.z, 0.f); r.w = fmaxf(r.w, 0.f);
            }
            *(float4*)&C[(size_t)m * N + n] = r;
        }
    }
}

// ---------------- flash attention: 64 Q-rows x 64 KV tiles, fp32 -----------
// Q,K,V in [NT, DM] layout; head h occupies columns [h*64, h*64+64).
// smem: Qt[k][r], KP[k][c] (K^T, reused as P[r][j] after S), Vs[j][c] = 48 KB.
__global__ __launch_bounds__(256, 3) void attn_kernel(
    const float* __restrict__ Q, const float* __restrict__ K,
    const float* __restrict__ V, const float* __restrict__ bias,
    float* __restrict__ O)
{
    __shared__ float Qt[64 * 64];
    __shared__ float KP[64 * 64];
    __shared__ float Vs[64 * 64];

    const int h  = blockIdx.y;
    const int q0 = blockIdx.x * 64;
    const int tid = threadIdx.x;
    const int tx = tid & 15, ty = tid >> 4;

    // load Q tile transposed (k-major) and pre-scaled by 1/sqrt(64)
#pragma unroll
    for (int it = 0; it < 4; it++) {
        int idx = it * 256 + tid;
        int r = idx >> 4, k4 = idx & 15;
        float4 q = *(const float4*)&Q[(size_t)(q0 + r) * DM + h * HD + k4 * 4];
        Qt[(k4 * 4 + 0) * 64 + r] = q.x * 0.125f;
        Qt[(k4 * 4 + 1) * 64 + r] = q.y * 0.125f;
        Qt[(k4 * 4 + 2) * 64 + r] = q.z * 0.125f;
        Qt[(k4 * 4 + 3) * 64 + r] = q.w * 0.125f;
    }

    float m_i[4], l_i[4], o[4][4];
#pragma unroll
    for (int i = 0; i < 4; i++) {
        m_i[i] = -1e30f; l_i[i] = 0.f;
#pragma unroll
        for (int j = 0; j < 4; j++) o[i][j] = 0.f;
    }

    const float* brow = bias + ((size_t)h * NT + q0) * NT;

    for (int kv0 = 0; kv0 < NT; kv0 += 64) {
        __syncthreads();  // protect KP/Vs from previous tile's PV reads
        // load K tile transposed + V tile direct
#pragma unroll
        for (int it = 0; it < 4; it++) {
            int idx = it * 256 + tid;
            int r = idx >> 4, k4 = idx & 15;
            float4 kq = *(const float4*)&K[(size_t)(kv0 + r) * DM + h * HD + k4 * 4];
            KP[(k4 * 4 + 0) * 64 + r] = kq.x;
            KP[(k4 * 4 + 1) * 64 + r] = kq.y;
            KP[(k4 * 4 + 2) * 64 + r] = kq.z;
            KP[(k4 * 4 + 3) * 64 + r] = kq.w;
            float4 vv = *(const float4*)&V[(size_t)(kv0 + r) * DM + h * HD + k4 * 4];
            *(float4*)&Vs[r * 64 + k4 * 4] = vv;
        }
        __syncthreads();

        // S = (Q/8) @ K^T  (thread computes 4x4)
        float s[4][4];
#pragma unroll
        for (int i = 0; i < 4; i++)
#pragma unroll
            for (int j = 0; j < 4; j++) s[i][j] = 0.f;

#pragma unroll 4
        for (int k = 0; k < 64; k++) {
            float4 qv = *(const float4*)&Qt[k * 64 + ty * 4];
            float4 kv = *(const float4*)&KP[k * 64 + tx * 4];
            float qa[4] = {qv.x, qv.y, qv.z, qv.w};
            float ka[4] = {kv.x, kv.y, kv.z, kv.w};
#pragma unroll
            for (int i = 0; i < 4; i++)
#pragma unroll
                for (int j = 0; j < 4; j++)
                    s[i][j] += qa[i] * ka[j];
        }

        // + bias (streamed from HBM, coalesced)
#pragma unroll
        for (int i = 0; i < 4; i++) {
            float4 b = *(const float4*)&brow[(size_t)(ty * 4 + i) * NT + kv0 + tx * 4];
            s[i][0] += b.x; s[i][1] += b.y; s[i][2] += b.z; s[i][3] += b.w;
        }

        // online softmax (rows owned by 16 threads sharing ty; xor-shuffle <16
        // stays inside each half-warp group)
#pragma unroll
        for (int i = 0; i < 4; i++) {
            float rm = fmaxf(fmaxf(s[i][0], s[i][1]), fmaxf(s[i][2], s[i][3]));
            rm = fmaxf(rm, __shfl_xor_sync(0xffffffffu, rm, 8));
            rm = fmaxf(rm, __shfl_xor_sync(0xffffffffu, rm, 4));
            rm = fmaxf(rm, __shfl_xor_sync(0xffffffffu, rm, 2));
            rm = fmaxf(rm, __shfl_xor_sync(0xffffffffu, rm, 1));
            float mn = fmaxf(m_i[i], rm);
            float corr = __expf(m_i[i] - mn);
            m_i[i] = mn;
            float rs = 0.f;
#pragma unroll
            for (int j = 0; j < 4; j++) { s[i][j] = __expf(s[i][j] - mn); rs += s[i][j]; }
            rs += __shfl_xor_sync(0xffffffffu, rs, 8);
            rs += __shfl_xor_sync(0xffffffffu, rs, 4);
            rs += __shfl_xor_sync(0xffffffffu, rs, 2);
            rs += __shfl_xor_sync(0xffffffffu, rs, 1);
            l_i[i] = l_i[i] * corr + rs;
#pragma unroll
            for (int j = 0; j < 4; j++) o[i][j] *= corr;
        }

        __syncthreads();  // everyone done reading KP as K^T
        // store P row-major into the K buffer (conflict-free float4 stores)
#pragma unroll
        for (int i = 0; i < 4; i++)
            *(float4*)&KP[(ty * 4 + i) * 64 + tx * 4] =
                make_float4(s[i][0], s[i][1], s[i][2], s[i][3]);
        __syncthreads();

        // O += P @ V
#pragma unroll 2
        for (int j4 = 0; j4 < 16; j4++) {
            float va[4][4];
#pragma unroll
            for (int jj = 0; jj < 4; jj++)
                *(float4*)&va[jj][0] = *(const float4*)&Vs[(j4 * 4 + jj) * 64 + tx * 4];
#pragma unroll
            for (int i = 0; i < 4; i++) {
                float4 pp = *(const float4*)&KP[(ty * 4 + i) * 64 + j4 * 4];
#pragma unroll
                for (int j = 0; j < 4; j++)
                    o[i][j] += pp.x * va[0][j] + pp.y * va[1][j]
                             + pp.z * va[2][j] + pp.w * va[3][j];
            }
        }
    }

#pragma unroll
    for (int i = 0; i < 4; i++) {
        float inv = 1.0f / l_i[i];
        float4 r = make_float4(o[i][0] * inv, o[i][1] * inv, o[i][2] * inv, o[i][3] * inv);
        *(float4*)&O[(size_t)(q0 + ty * 4 + i) * DM + h * HD + tx * 4] = r;
    }
}

// ---------------- fused residual + LayerNorm (one block per row) -----------
__global__ __launch_bounds__(128) void add_ln_kernel(
    const float* __restrict__ A, const float* __restrict__ B,
    const float* __restrict__ g, const float* __restrict__ be,
    float* __restrict__ out)
{
    __shared__ float red[8];
    const int row = blockIdx.x, tid = threadIdx.x;
    float4 a = *(const float4*)&A[(size_t)row * DM + tid * 4];
    float4 b = *(const float4*)&B[(size_t)row * DM + tid * 4];
    float v[4] = {a.x + b.x, a.y + b.y, a.z + b.z, a.w + b.w};

    float s = v[0] + v[1] + v[2] + v[3];
#pragma unroll
    for (int off = 16; off; off >>= 1) s += __shfl_xor_sync(0xffffffffu, s, off);
    if ((tid & 31) == 0) red[tid >> 5] = s;
    __syncthreads();
    float mu = (red[0] + red[1] + red[2] + red[3]) * (1.f / DM);

    float d[4]; float sq = 0.f;
#pragma unroll
    for (int i = 0; i < 4; i++) { d[i] = v[i] - mu; sq += d[i] * d[i]; }
#pragma unroll
    for (int off = 16; off; off >>= 1) sq += __shfl_xor_sync(0xffffffffu, sq, off);
    if ((tid & 31) == 0) red[4 + (tid >> 5)] = sq;
    __syncthreads();
    float inv = rsqrtf((red[4] + red[5] + red[6] + red[7]) * (1.f / DM) + 1e-5f);

    float4 gg = *(const float4*)&g[tid * 4];
    float4 bb = *(const float4*)&be[tid * 4];
    float4 r;
    r.x = d[0] * inv * gg.x + bb.x;
    r.y = d[1] * inv * gg.y + bb.y;
    r.z = d[2] * inv * gg.z + bb.z;
    r.w = d[3] * inv * gg.w + bb.w;
    *(float4*)&out[(size_t)row * DM + tid * 4] = r;
}

// ---------------- launch ----------------------------------------------------
extern "C" void kernel_launch(void* const* d_in, const int* in_sizes, int n_in,
                              void* d_out, int out_size)
{
    const float* x    = (const float*)d_in[0];
    const float* bias = (const float*)d_in[1];
    const float* Wq = (const float*)d_in[2];  const float* bq = (const float*)d_in[3];
    const float* Wk = (const float*)d_in[4];  const float* bk = (const float*)d_in[5];
    const float* Wv = (const float*)d_in[6];  const float* bv = (const float*)d_in[7];
    const float* Wo = (const float*)d_in[8];  const float* bo = (const float*)d_in[9];
    const float* g1 = (const float*)d_in[10]; const float* b1 = (const float*)d_in[11];
    const float* g2 = (const float*)d_in[12]; const float* b2 = (const float*)d_in[13];
    const float* W1 = (const float*)d_in[14]; const float* c1 = (const float*)d_in[15];
    const float* W2 = (const float*)d_in[16]; const float* c2 = (const float*)d_in[17];
    float* out = (float*)d_out;

    float *Qp, *Kp, *Vp, *attnp, *tmpp, *x1p, *hidp;
    cudaGetSymbolAddress((void**)&Qp,    g_Q);
    cudaGetSymbolAddress((void**)&Kp,    g_K);
    cudaGetSymbolAddress((void**)&Vp,    g_V);
    cudaGetSymbolAddress((void**)&attnp, g_attn);
    cudaGetSymbolAddress((void**)&tmpp,  g_tmp);
    cudaGetSymbolAddress((void**)&x1p,   g_x1);
    cudaGetSymbolAddress((void**)&hidp,  g_hid);

    dim3 blk(256);
    dim3 gProj(DM / 128, NT / 128);   // 4 x 32
    dim3 gFF1(DFF / 128, NT / 128);   // 8 x 32

    sgemm_bias<false><<<gProj, blk>>>(x, Wq, bq, Qp, NT, DM, DM);
    sgemm_bias<false><<<gProj, blk>>>(x, Wk, bk, Kp, NT, DM, DM);
    sgemm_bias<false><<<gProj, blk>>>(x, Wv, bv, Vp, NT, DM, DM);

    attn_kernel<<<dim3(NT / 64, NH), blk>>>(Qp, Kp, Vp, bias, attnp);

    sgemm_bias<false><<<gProj, blk>>>(attnp, Wo, bo, tmpp, NT, DM, DM);
    add_ln_kernel<<<NT, 128>>>(x, tmpp, g1, b1, x1p);

    sgemm_bias<true ><<<gFF1, blk>>>(x1p, W1, c1, hidp, NT, DFF, DM);
    sgemm_bias<false><<<gProj, blk>>>(hidp, W2, c2, tmpp, NT, DM, DFF);
    add_ln_kernel<<<NT, 128>>>(x1p, tmpp, g2, b2, out);
}

// round 2
// speedup vs baseline: 2.9316x; 2.9316x over previous
#include <cuda_runtime.h>
#include <math.h>

#define NT  4096
#define DM  512
#define NH  8
#define HD  64
#define DFF 1024

// ---------------- scratch (static device globals; no allocations) ----------
__device__ float g_Q[NT * DM];
__device__ float g_K[NT * DM];
__device__ float g_V[NT * DM];
__device__ float g_attn[NT * DM];
__device__ float g_tmp[NT * DM];
__device__ float g_x1[NT * DM];
__device__ float g_hid[NT * DFF];

// ---------------- helpers ---------------------------------------------------
__device__ __forceinline__ float f2tf(float x) {
    unsigned u;
    asm("cvt.rna.tf32.f32 %0, %1;" : "=r"(u) : "f"(x));
    return __uint_as_float(u);
}

__device__ __forceinline__ void mma8(float d[4],
                                     float a0, float a1, float a2, float a3,
                                     float b0, float b1) {
    asm("mma.sync.aligned.m16n8k8.row.col.f32.tf32.tf32.f32 "
        "{%0,%1,%2,%3}, {%4,%5,%6,%7}, {%8,%9}, {%0,%1,%2,%3};"
        : "+f"(d[0]), "+f"(d[1]), "+f"(d[2]), "+f"(d[3])
        : "r"(__float_as_uint(a0)), "r"(__float_as_uint(a1)),
          "r"(__float_as_uint(a2)), "r"(__float_as_uint(a3)),
          "r"(__float_as_uint(b0)), "r"(__float_as_uint(b1)));
}

// fast exp for x <= 0 (FMA pipe, avoids MUFU). ~2e-8 rel err.
__device__ __forceinline__ float fast_exp(float x) {
    float y = x * 1.44269504089f;
    y = fmaxf(y, -100.0f);
    float t  = y + 12582912.0f;                 // round-to-nearest int
    int   ni = __float_as_int(t) - 0x4B400000;  // mantissa encodes int
    float f  = y - (t - 12582912.0f);           // f in [-0.5, 0.5]
    float p  = fmaf(f, 0.0013475782f, 0.0096788315f);
    p = fmaf(f, p, 0.0555072548f);
    p = fmaf(f, p, 0.2402211471f);
    p = fmaf(f, p, 0.6931471805f);
    p = fmaf(f, p, 1.0f);
    return __int_as_float(__float_as_int(p) + (ni << 23));
}

// ---------------- tf32 tensor-core GEMM: C = A@W + bias (opt ReLU) ---------
// 128x128 block tile, BK=16, 256 threads = 8 warps (2x4), warp tile 64x32.
template <bool RELU>
__global__ __launch_bounds__(256, 2) void gemm_tc(
    const float* __restrict__ A, const float* __restrict__ W,
    const float* __restrict__ bias, float* __restrict__ C,
    int M, int N, int K)
{
    __shared__ float As[2][128 * 20];   // row-major, stride 20 (pad)
    __shared__ float Ws[2][16 * 136];   // row-major, stride 136 (pad)

    const int tid  = threadIdx.x;
    const int w    = tid >> 5, lane = tid & 31;
    const int g    = lane >> 2, c = lane & 3;
    const int wm   = (w >> 2) * 64;     // warp row offset in tile
    const int wn   = (w & 3) * 32;      // warp col offset in tile
    const int m0   = blockIdx.y * 128;
    const int n0   = blockIdx.x * 128;

    float acc[4][4][4];
#pragma unroll
    for (int t = 0; t < 4; t++)
#pragma unroll
        for (int j = 0; j < 4; j++)
#pragma unroll
            for (int r = 0; r < 4; r++) acc[t][j][r] = 0.f;

    const int aRow0 = tid >> 2,  aC4_0 = tid & 3;          // idx = tid
    const int aRow1 = (tid + 256) >> 2, aC4_1 = (tid + 256) & 3;
    const int wRow0 = tid >> 5,  wC4_0 = tid & 31;
    const int wRow1 = (tid + 256) >> 5, wC4_1 = (tid + 256) & 31;

    float4 ra0, ra1, rw0, rw1;

    // prologue: load tile 0 into buffer 0
    ra0 = *(const float4*)&A[(size_t)(m0 + aRow0) * K + 4 * aC4_0];
    ra1 = *(const float4*)&A[(size_t)(m0 + aRow1) * K + 4 * aC4_1];
    rw0 = *(const float4*)&W[(size_t)wRow0 * N + n0 + 4 * wC4_0];
    rw1 = *(const float4*)&W[(size_t)wRow1 * N + n0 + 4 * wC4_1];
    {
        float4 t0 = make_float4(f2tf(ra0.x), f2tf(ra0.y), f2tf(ra0.z), f2tf(ra0.w));
        float4 t1 = make_float4(f2tf(ra1.x), f2tf(ra1.y), f2tf(ra1.z), f2tf(ra1.w));
        *(float4*)&As[0][aRow0 * 20 + 4 * aC4_0] = t0;
        *(float4*)&As[0][aRow1 * 20 + 4 * aC4_1] = t1;
        float4 u0 = make_float4(f2tf(rw0.x), f2tf(rw0.y), f2tf(rw0.z), f2tf(rw0.w));
        float4 u1 = make_float4(f2tf(rw1.x), f2tf(rw1.y), f2tf(rw1.z), f2tf(rw1.w));
        *(float4*)&Ws[0][wRow0 * 136 + 4 * wC4_0] = u0;
        *(float4*)&Ws[0][wRow1 * 136 + 4 * wC4_1] = u1;
    }
    __syncthreads();

    const int nk = K >> 4;
    for (int kb = 0; kb < nk; kb++) {
        const int cur  = kb & 1;
        const bool more = (kb + 1 < nk);
        if (more) {
            int k1 = (kb + 1) * 16;
            ra0 = *(const float4*)&A[(size_t)(m0 + aRow0) * K + k1 + 4 * aC4_0];
            ra1 = *(const float4*)&A[(size_t)(m0 + aRow1) * K + k1 + 4 * aC4_1];
            rw0 = *(const float4*)&W[(size_t)(k1 + wRow0) * N + n0 + 4 * wC4_0];
            rw1 = *(const float4*)&W[(size_t)(k1 + wRow1) * N + n0 + 4 * wC4_1];
        }
#pragma unroll
        for (int ks = 0; ks < 2; ks++) {
            const int k8 = ks * 8;
            float af[4][4];
#pragma unroll
            for (int t = 0; t < 4; t++) {
                af[t][0] = As[cur][(wm + 16 * t + g) * 20 + k8 + c];
                af[t][1] = As[cur][(wm + 16 * t + g + 8) * 20 + k8 + c];
                af[t][2] = As[cur][(wm + 16 * t + g) * 20 + k8 + c + 4];
                af[t][3] = As[cur][(wm + 16 * t + g + 8) * 20 + k8 + c + 4];
            }
#pragma unroll
            for (int j = 0; j < 4; j++) {
                float b0 = Ws[cur][(k8 + c) * 136 + wn + 8 * j + g];
                float b1 = Ws[cur][(k8 + c + 4) * 136 + wn + 8 * j + g];
#pragma unroll
                for (int t = 0; t < 4; t++)
                    mma8(acc[t][j], af[t][0], af[t][1], af[t][2], af[t][3], b0, b1);
            }
        }
        if (more) {
            const int nxt = cur ^ 1;
            float4 t0 = make_float4(f2tf(ra0.x), f2tf(ra0.y), f2tf(ra0.z), f2tf(ra0.w));
            float4 t1 = make_float4(f2tf(ra1.x), f2tf(ra1.y), f2tf(ra1.z), f2tf(ra1.w));
            *(float4*)&As[nxt][aRow0 * 20 + 4 * aC4_0] = t0;
            *(float4*)&As[nxt][aRow1 * 20 + 4 * aC4_1] = t1;
            float4 u0 = make_float4(f2tf(rw0.x), f2tf(rw0.y), f2tf(rw0.z), f2tf(rw0.w));
            float4 u1 = make_float4(f2tf(rw1.x), f2tf(rw1.y), f2tf(rw1.z), f2tf(rw1.w));
            *(float4*)&Ws[nxt][wRow0 * 136 + 4 * wC4_0] = u0;
            *(float4*)&Ws[nxt][wRow1 * 136 + 4 * wC4_1] = u1;
        }
        __syncthreads();
    }

    // epilogue
#pragma unroll
    for (int t = 0; t < 4; t++) {
        int row0 = m0 + wm + 16 * t + g;
#pragma unroll
        for (int j = 0; j < 4; j++) {
            int col = n0 + wn + 8 * j + 2 * c;
            float2 bv = *(const float2*)&bias[col];
            float2 r0, r1;
            r0.x = acc[t][j][0] + bv.x;  r0.y = acc[t][j][1] + bv.y;
            r1.x = acc[t][j][2] + bv.x;  r1.y = acc[t][j][3] + bv.y;
            if (RELU) {
                r0.x = fmaxf(r0.x, 0.f); r0.y = fmaxf(r0.y, 0.f);
                r1.x = fmaxf(r1.x, 0.f); r1.y = fmaxf(r1.y, 0.f);
            }
            *(float2*)&C[(size_t)row0 * N + col]       = r0;
            *(float2*)&C[(size_t)(row0 + 8) * N + col] = r1;
        }
    }
}

// ---------------- tensor-core flash attention -------------------------------
// 128 Q-rows x 64 KV-cols per tile, 8 warps (each warp owns 16 full rows).
__global__ __launch_bounds__(256, 2) void attn_tc(
    const float* __restrict__ Q, const float* __restrict__ K,
    const float* __restrict__ V, const float* __restrict__ bias,
    float* __restrict__ O)
{
    extern __shared__ float sm[];
    float* Qt = sm;                  // [64 k][128 q]  stride 136
    float* Ks = sm + 64 * 136;       // [64 n][64 k]   stride 68
    float* Vs = Ks + 64 * 68;        // [64 k][64 n]   stride 72
    float* Pt = Vs + 64 * 72;        // [64 k][128 q]  stride 136

    const int tid  = threadIdx.x;
    const int w    = tid >> 5, lane = tid & 31;
    const int g    = lane >> 2, c = lane & 3;
    const int h    = blockIdx.y;
    const int q0   = blockIdx.x * 128;
    const int r0   = 16 * w + g;     // local row of fragment row 0

    // load Q tile, pre-scaled, transposed, tf32-rounded
#pragma unroll
    for (int i = 0; i < 8; i++) {
        int idx = i * 256 + tid;
        int row = idx >> 4, c4 = idx & 15;
        float4 q = *(const float4*)&Q[(size_t)(q0 + row) * DM + h * HD + 4 * c4];
        Qt[(4 * c4 + 0) * 136 + row] = f2tf(q.x * 0.125f);
        Qt[(4 * c4 + 1) * 136 + row] = f2tf(q.y * 0.125f);
        Qt[(4 * c4 + 2) * 136 + row] = f2tf(q.z * 0.125f);
        Qt[(4 * c4 + 3) * 136 + row] = f2tf(q.w * 0.125f);
    }

    float o[8][4];
#pragma unroll
    for (int j = 0; j < 8; j++)
#pragma unroll
        for (int r = 0; r < 4; r++) o[j][r] = 0.f;
    float mr0 = -1e30f, mr1 = -1e30f, lr0 = 0.f, lr1 = 0.f;

    const float* brow0 = bias + ((size_t)h * NT + q0 + r0) * NT;
    const float* brow1 = brow0 + (size_t)8 * NT;

    for (int kv0 = 0; kv0 < NT; kv0 += 64) {
        __syncthreads();
        // stage K (transposed-access layout) and V
#pragma unroll
        for (int i = 0; i < 4; i++) {
            int idx = i * 256 + tid;
            int row = idx >> 4, c4 = idx & 15;
            float4 kq = *(const float4*)&K[(size_t)(kv0 + row) * DM + h * HD + 4 * c4];
            Ks[row * 68 + 4 * c4 + 0] = f2tf(kq.x);
            Ks[row * 68 + 4 * c4 + 1] = f2tf(kq.y);
            Ks[row * 68 + 4 * c4 + 2] = f2tf(kq.z);
            Ks[row * 68 + 4 * c4 + 3] = f2tf(kq.w);
            float4 vq = *(const float4*)&V[(size_t)(kv0 + row) * DM + h * HD + 4 * c4];
            Vs[row * 72 + 4 * c4 + 0] = f2tf(vq.x);
            Vs[row * 72 + 4 * c4 + 1] = f2tf(vq.y);
            Vs[row * 72 + 4 * c4 + 2] = f2tf(vq.z);
            Vs[row * 72 + 4 * c4 + 3] = f2tf(vq.w);
        }
        __syncthreads();

        // S = Q @ K^T  (warp covers its 16 rows x all 64 cols)
        float s[8][4];
#pragma unroll
        for (int j = 0; j < 8; j++)
#pragma unroll
            for (int r = 0; r < 4; r++) s[j][r] = 0.f;

#pragma unroll
        for (int k8 = 0; k8 < 64; k8 += 8) {
            float a0 = Qt[(k8 + c) * 136 + r0];
            float a1 = Qt[(k8 + c) * 136 + r0 + 8];
            float a2 = Qt[(k8 + c + 4) * 136 + r0];
            float a3 = Qt[(k8 + c + 4) * 136 + r0 + 8];
#pragma unroll
            for (int j = 0; j < 8; j++) {
                float b0 = Ks[(8 * j + g) * 68 + k8 + c];
                float b1 = Ks[(8 * j + g) * 68 + k8 + c + 4];
                mma8(s[j], a0, a1, a2, a3, b0, b1);
            }
        }

        // + bias (512 MB HBM stream, float2, full-sector coalesced)
#pragma unroll
        for (int j = 0; j < 8; j++) {
            float2 b0 = *(const float2*)&brow0[kv0 + 8 * j + 2 * c];
            float2 b1 = *(const float2*)&brow1[kv0 + 8 * j + 2 * c];
            s[j][0] += b0.x; s[j][1] += b0.y;
            s[j][2] += b1.x; s[j][3] += b1.y;
        }

        // online softmax, two rows per thread (g, g+8), reduce over c-group
        float rm0 = -1e30f, rm1 = -1e30f;
#pragma unroll
        for (int j = 0; j < 8; j++) {
            rm0 = fmaxf(rm0, fmaxf(s[j][0], s[j][1]));
            rm1 = fmaxf(rm1, fmaxf(s[j][2], s[j][3]));
        }
        rm0 = fmaxf(rm0, __shfl_xor_sync(0xffffffffu, rm0, 1));
        rm0 = fmaxf(rm0, __shfl_xor_sync(0xffffffffu, rm0, 2));
        rm1 = fmaxf(rm1, __shfl_xor_sync(0xffffffffu, rm1, 1));
        rm1 = fmaxf(rm1, __shfl_xor_sync(0xffffffffu, rm1, 2));

        float mn0 = fmaxf(mr0, rm0), mn1 = fmaxf(mr1, rm1);
        float corr0 = fast_exp(mr0 - mn0), corr1 = fast_exp(mr1 - mn1);
        mr0 = mn0; mr1 = mn1;

        float sum0 = 0.f, sum1 = 0.f;
#pragma unroll
        for (int j = 0; j < 8; j++) {
            s[j][0] = fast_exp(s[j][0] - mn0);
            s[j][1] = fast_exp(s[j][1] - mn0);
            s[j][2] = fast_exp(s[j][2] - mn1);
            s[j][3] = fast_exp(s[j][3] - mn1);
            sum0 += s[j][0] + s[j][1];
            sum1 += s[j][2] + s[j][3];
        }
        sum0 += __shfl_xor_sync(0xffffffffu, sum0, 1);
        sum0 += __shfl_xor_sync(0xffffffffu, sum0, 2);
        sum1 += __shfl_xor_sync(0xffffffffu, sum1, 1);
        sum1 += __shfl_xor_sync(0xffffffffu, sum1, 2);
        lr0 = lr0 * corr0 + sum0;
        lr1 = lr1 * corr1 + sum1;
#pragma unroll
        for (int j = 0; j < 8; j++) {
            o[j][0] *= corr0; o[j][1] *= corr0;
            o[j][2] *= corr1; o[j][3] *= corr1;
        }

        // stage P transposed for the PV mma
#pragma unroll
        for (int j = 0; j < 8; j++) {
            Pt[(8 * j + 2 * c + 0) * 136 + r0]     = f2tf(s[j][0]);
            Pt[(8 * j + 2 * c + 1) * 136 + r0]     = f2tf(s[j][1]);
            Pt[(8 * j + 2 * c + 0) * 136 + r0 + 8] = f2tf(s[j][2]);
            Pt[(8 * j + 2 * c + 1) * 136 + r0 + 8] = f2tf(s[j][3]);
        }
        __syncthreads();

        // O += P @ V
#pragma unroll
        for (int k8 = 0; k8 < 64; k8 += 8) {
            float a0 = Pt[(k8 + c) * 136 + r0];
            float a1 = Pt[(k8 + c) * 136 + r0 + 8];
            float a2 = Pt[(k8 + c + 4) * 136 + r0];
            float a3 = Pt[(k8 + c + 4) * 136 + r0 + 8];
#pragma unroll
            for (int j = 0; j < 8; j++) {
                float b0 = Vs[(k8 + c) * 72 + 8 * j + g];
                float b1 = Vs[(k8 + c + 4) * 72 + 8 * j + g];
                mma8(o[j], a0, a1, a2, a3, b0, b1);
            }
        }
    }

    float inv0 = 1.0f / lr0, inv1 = 1.0f / lr1;
    int grow0 = q0 + r0;
#pragma unroll
    for (int j = 0; j < 8; j++) {
        int col = h * HD + 8 * j + 2 * c;
        float2 v0 = make_float2(o[j][0] * inv0, o[j][1] * inv0);
        float2 v1 = make_float2(o[j][2] * inv1, o[j][3] * inv1);
        *(float2*)&O[(size_t)grow0 * DM + col]       = v0;
        *(float2*)&O[(size_t)(grow0 + 8) * DM + col] = v1;
    }
}

// ---------------- fused residual + LayerNorm (one block per row) -----------
__global__ __launch_bounds__(128) void add_ln_kernel(
    const float* __restrict__ A, const float* __restrict__ B,
    const float* __restrict__ g, const float* __restrict__ be,
    float* __restrict__ out)
{
    __shared__ float red[8];
    const int row = blockIdx.x, tid = threadIdx.x;
    float4 a = *(const float4*)&A[(size_t)row * DM + tid * 4];
    float4 b = *(const float4*)&B[(size_t)row * DM + tid * 4];
    float v[4] = {a.x + b.x, a.y + b.y, a.z + b.z, a.w + b.w};

    float s = v[0] + v[1] + v[2] + v[3];
#pragma unroll
    for (int off = 16; off; off >>= 1) s += __shfl_xor_sync(0xffffffffu, s, off);
    if ((tid & 31) == 0) red[tid >> 5] = s;
    __syncthreads();
    float mu = (red[0] + red[1] + red[2] + red[3]) * (1.f / DM);

    float d[4]; float sq = 0.f;
#pragma unroll
    for (int i = 0; i < 4; i++) { d[i] = v[i] - mu; sq += d[i] * d[i]; }
#pragma unroll
    for (int off = 16; off; off >>= 1) sq += __shfl_xor_sync(0xffffffffu, sq, off);
    if ((tid & 31) == 0) red[4 + (tid >> 5)] = sq;
    __syncthreads();
    float inv = rsqrtf((red[4] + red[5] + red[6] + red[7]) * (1.f / DM) + 1e-5f);

    float4 gg = *(const float4*)&g[tid * 4];
    float4 bb = *(const float4*)&be[tid * 4];
    float4 r;
    r.x = d[0] * inv * gg.x + bb.x;
    r.y = d[1] * inv * gg.y + bb.y;
    r.z = d[2] * inv * gg.z + bb.z;
    r.w = d[3] * inv * gg.w + bb.w;
    *(float4*)&out[(size_t)row * DM + tid * 4] = r;
}

// ---------------- launch ----------------------------------------------------
extern "C" void kernel_launch(void* const* d_in, const int* in_sizes, int n_in,
                              void* d_out, int out_size)
{
    const float* x    = (const float*)d_in[0];
    const float* bias = (const float*)d_in[1];
    const float* Wq = (const float*)d_in[2];  const float* bq = (const float*)d_in[3];
    const float* Wk = (const float*)d_in[4];  const float* bk = (const float*)d_in[5];
    const float* Wv = (const float*)d_in[6];  const float* bv = (const float*)d_in[7];
    const float* Wo = (const float*)d_in[8];  const float* bo = (const float*)d_in[9];
    const float* g1 = (const float*)d_in[10]; const float* b1 = (const float*)d_in[11];
    const float* g2 = (const float*)d_in[12]; const float* b2 = (const float*)d_in[13];
    const float* W1 = (const float*)d_in[14]; const float* c1 = (const float*)d_in[15];
    const float* W2 = (const float*)d_in[16]; const float* c2 = (const float*)d_in[17];
    float* out = (float*)d_out;

    float *Qp, *Kp, *Vp, *attnp, *tmpp, *x1p, *hidp;
    cudaGetSymbolAddress((void**)&Qp,    g_Q);
    cudaGetSymbolAddress((void**)&Kp,    g_K);
    cudaGetSymbolAddress((void**)&Vp,    g_V);
    cudaGetSymbolAddress((void**)&attnp, g_attn);
    cudaGetSymbolAddress((void**)&tmpp,  g_tmp);
    cudaGetSymbolAddress((void**)&x1p,   g_x1);
    cudaGetSymbolAddress((void**)&hidp,  g_hid);

    const int ATTN_SMEM = (64 * 136 + 64 * 68 + 64 * 72 + 64 * 136) * 4; // 105472
    cudaFuncSetAttribute(attn_tc, cudaFuncAttributeMaxDynamicSharedMemorySize, ATTN_SMEM);

    dim3 blk(256);
    dim3 gProj(DM / 128, NT / 128);   // 4 x 32
    dim3 gFF1(DFF / 128, NT / 128);   // 8 x 32

    gemm_tc<false><<<gProj, blk>>>(x, Wq, bq, Qp, NT, DM, DM);
    gemm_tc<false><<<gProj, blk>>>(x, Wk, bk, Kp, NT, DM, DM);
    gemm_tc<false><<<gProj, blk>>>(x, Wv, bv, Vp, NT, DM, DM);

    attn_tc<<<dim3(NT / 128, NH), blk, ATTN_SMEM>>>(Qp, Kp, Vp, bias, attnp);

    gemm_tc<false><<<gProj, blk>>>(attnp, Wo, bo, tmpp, NT, DM, DM);
    add_ln_kernel<<<NT, 128>>>(x, tmpp, g1, b1, x1p);

    gemm_tc<true ><<<gFF1, blk>>>(x1p, W1, c1, hidp, NT, DFF, DM);
    gemm_tc<false><<<gProj, blk>>>(hidp, W2, c2, tmpp, NT, DM, DFF);
    add_ln_kernel<<<NT, 128>>>(x1p, tmpp, g2, b2, out);
}

// round 3
// speedup vs baseline: 3.0273x; 1.0326x over previous
#include <cuda_runtime.h>
#include <math.h>

#define NT  4096
#define DM  512
#define NH  8
#define HD  64
#define DFF 1024

// ---------------- scratch (static device globals; no allocations) ----------
__device__ float g_Q[NT * DM];
__device__ float g_K[NT * DM];     // packed: [NH][NT][64] with PK() column order
__device__ float g_V[NT * DM];
__device__ float g_attn[NT * DM];
__device__ float g_tmp[NT * DM];
__device__ float g_x1[NT * DM];
__device__ float g_hid[NT * DFF];

// ---------------- helpers ---------------------------------------------------
__device__ __forceinline__ float f2tf(float x) {
    unsigned u;
    asm("cvt.rna.tf32.f32 %0, %1;" : "=r"(u) : "f"(x));
    return __uint_as_float(u);
}

__device__ __forceinline__ int PKi(int k) {        // pair-packed column index
    return (k & ~7) + 2 * (k & 3) + ((k >> 2) & 1);
}

__device__ __forceinline__ void mma8(float d[4],
                                     float a0, float a1, float a2, float a3,
                                     float b0, float b1) {
    asm("mma.sync.aligned.m16n8k8.row.col.f32.tf32.tf32.f32 "
        "{%0,%1,%2,%3}, {%4,%5,%6,%7}, {%8,%9}, {%0,%1,%2,%3};"
        : "+f"(d[0]), "+f"(d[1]), "+f"(d[2]), "+f"(d[3])
        : "r"(__float_as_uint(a0)), "r"(__float_as_uint(a1)),
          "r"(__float_as_uint(a2)), "r"(__float_as_uint(a3)),
          "r"(__float_as_uint(b0)), "r"(__float_as_uint(b1)));
}

__device__ __forceinline__ void cpa16(unsigned dst, const void* src) {
    asm volatile("cp.async.cg.shared.global [%0], [%1], 16;" :: "r"(dst), "l"(src));
}

// fast exp for x <= 0 (FMA pipe, avoids MUFU). ~2e-8 rel err.
__device__ __forceinline__ float fast_exp(float x) {
    float y = x * 1.44269504089f;
    y = fmaxf(y, -100.0f);
    float t  = y + 12582912.0f;
    int   ni = __float_as_int(t) - 0x4B400000;
    float f  = y - (t - 12582912.0f);
    float p  = fmaf(f, 0.0013475782f, 0.0096788315f);
    p = fmaf(f, p, 0.0555072548f);
    p = fmaf(f, p, 0.2402211471f);
    p = fmaf(f, p, 0.6931471805f);
    p = fmaf(f, p, 1.0f);
    return __int_as_float(__float_as_int(p) + (ni << 23));
}

// ---------------- tf32 tensor-core GEMM: C = A@W + bias --------------------
// MODE: 0 = plain fp32 out, 1 = ReLU fp32 out, 2 = tf32-rounded out,
//       3 = tf32-rounded + head-pair-packed out (for K)
template <int MODE>
__global__ __launch_bounds__(256, 2) void gemm_tc(
    const float* __restrict__ A, const float* __restrict__ W,
    const float* __restrict__ bias, float* __restrict__ C,
    int M, int N, int K)
{
    __shared__ float As[2][128 * 20];
    __shared__ float Ws[2][16 * 136];

    const int tid  = threadIdx.x;
    const int w    = tid >> 5, lane = tid & 31;
    const int g    = lane >> 2, c = lane & 3;
    const int wm   = (w >> 2) * 64;
    const int wn   = (w & 3) * 32;
    const int m0   = blockIdx.y * 128;
    const int n0   = blockIdx.x * 128;

    float acc[4][4][4];
#pragma unroll
    for (int t = 0; t < 4; t++)
#pragma unroll
        for (int j = 0; j < 4; j++)
#pragma unroll
            for (int r = 0; r < 4; r++) acc[t][j][r] = 0.f;

    const int aRow0 = tid >> 2,  aC4_0 = tid & 3;
    const int aRow1 = (tid + 256) >> 2, aC4_1 = (tid + 256) & 3;
    const int wRow0 = tid >> 5,  wC4_0 = tid & 31;
    const int wRow1 = (tid + 256) >> 5, wC4_1 = (tid + 256) & 31;

    float4 ra0, ra1, rw0, rw1;

    ra0 = *(const float4*)&A[(size_t)(m0 + aRow0) * K + 4 * aC4_0];
    ra1 = *(const float4*)&A[(size_t)(m0 + aRow1) * K + 4 * aC4_1];
    rw0 = *(const float4*)&W[(size_t)wRow0 * N + n0 + 4 * wC4_0];
    rw1 = *(const float4*)&W[(size_t)wRow1 * N + n0 + 4 * wC4_1];
    {
        float4 t0 = make_float4(f2tf(ra0.x), f2tf(ra0.y), f2tf(ra0.z), f2tf(ra0.w));
        float4 t1 = make_float4(f2tf(ra1.x), f2tf(ra1.y), f2tf(ra1.z), f2tf(ra1.w));
        *(float4*)&As[0][aRow0 * 20 + 4 * aC4_0] = t0;
        *(float4*)&As[0][aRow1 * 20 + 4 * aC4_1] = t1;
        float4 u0 = make_float4(f2tf(rw0.x), f2tf(rw0.y), f2tf(rw0.z), f2tf(rw0.w));
        float4 u1 = make_float4(f2tf(rw1.x), f2tf(rw1.y), f2tf(rw1.z), f2tf(rw1.w));
        *(float4*)&Ws[0][wRow0 * 136 + 4 * wC4_0] = u0;
        *(float4*)&Ws[0][wRow1 * 136 + 4 * wC4_1] = u1;
    }
    __syncthreads();

    const int nk = K >> 4;
    for (int kb = 0; kb < nk; kb++) {
        const int cur  = kb & 1;
        const bool more = (kb + 1 < nk);
        if (more) {
            int k1 = (kb + 1) * 16;
            ra0 = *(const float4*)&A[(size_t)(m0 + aRow0) * K + k1 + 4 * aC4_0];
            ra1 = *(const float4*)&A[(size_t)(m0 + aRow1) * K + k1 + 4 * aC4_1];
            rw0 = *(const float4*)&W[(size_t)(k1 + wRow0) * N + n0 + 4 * wC4_0];
            rw1 = *(const float4*)&W[(size_t)(k1 + wRow1) * N + n0 + 4 * wC4_1];
        }
#pragma unroll
        for (int ks = 0; ks < 2; ks++) {
            const int k8 = ks * 8;
            float af[4][4];
#pragma unroll
            for (int t = 0; t < 4; t++) {
                af[t][0] = As[cur][(wm + 16 * t + g) * 20 + k8 + c];
                af[t][1] = As[cur][(wm + 16 * t + g + 8) * 20 + k8 + c];
                af[t][2] = As[cur][(wm + 16 * t + g) * 20 + k8 + c + 4];
                af[t][3] = As[cur][(wm + 16 * t + g + 8) * 20 + k8 + c + 4];
            }
#pragma unroll
            for (int j = 0; j < 4; j++) {
                float b0 = Ws[cur][(k8 + c) * 136 + wn + 8 * j + g];
                float b1 = Ws[cur][(k8 + c + 4) * 136 + wn + 8 * j + g];
#pragma unroll
                for (int t = 0; t < 4; t++)
                    mma8(acc[t][j], af[t][0], af[t][1], af[t][2], af[t][3], b0, b1);
            }
        }
        if (more) {
            const int nxt = cur ^ 1;
            float4 t0 = make_float4(f2tf(ra0.x), f2tf(ra0.y), f2tf(ra0.z), f2tf(ra0.w));
            float4 t1 = make_float4(f2tf(ra1.x), f2tf(ra1.y), f2tf(ra1.z), f2tf(ra1.w));
            *(float4*)&As[nxt][aRow0 * 20 + 4 * aC4_0] = t0;
            *(float4*)&As[nxt][aRow1 * 20 + 4 * aC4_1] = t1;
            float4 u0 = make_float4(f2tf(rw0.x), f2tf(rw0.y), f2tf(rw0.z), f2tf(rw0.w));
            float4 u1 = make_float4(f2tf(rw1.x), f2tf(rw1.y), f2tf(rw1.z), f2tf(rw1.w));
            *(float4*)&Ws[nxt][wRow0 * 136 + 4 * wC4_0] = u0;
            *(float4*)&Ws[nxt][wRow1 * 136 + 4 * wC4_1] = u1;
        }
        __syncthreads();
    }

#pragma unroll
    for (int t = 0; t < 4; t++) {
        int row0 = m0 + wm + 16 * t + g;
#pragma unroll
        for (int j = 0; j < 4; j++) {
            int col = n0 + wn + 8 * j + 2 * c;
            float2 bv = *(const float2*)&bias[col];
            float v00 = acc[t][j][0] + bv.x, v01 = acc[t][j][1] + bv.y;
            float v10 = acc[t][j][2] + bv.x, v11 = acc[t][j][3] + bv.y;
            if (MODE == 1) {
                v00 = fmaxf(v00, 0.f); v01 = fmaxf(v01, 0.f);
                v10 = fmaxf(v10, 0.f); v11 = fmaxf(v11, 0.f);
            }
            if (MODE == 3) {
                int hh = col >> 6, dl = col & 63;
                size_t b0 = ((size_t)hh * NT + row0) * 64;
                size_t b1 = ((size_t)hh * NT + row0 + 8) * 64;
                C[b0 + PKi(dl)]     = f2tf(v00);
                C[b0 + PKi(dl + 1)] = f2tf(v01);
                C[b1 + PKi(dl)]     = f2tf(v10);
                C[b1 + PKi(dl + 1)] = f2tf(v11);
            } else if (MODE == 2) {
                *(float2*)&C[(size_t)row0 * N + col] =
                    make_float2(f2tf(v00), f2tf(v01));
                *(float2*)&C[(size_t)(row0 + 8) * N + col] =
                    make_float2(f2tf(v10), f2tf(v11));
            } else {
                *(float2*)&C[(size_t)row0 * N + col]       = make_float2(v00, v01);
                *(float2*)&C[(size_t)(row0 + 8) * N + col] = make_float2(v10, v11);
            }
        }
    }
}

// ---------------- tensor-core flash attention v3 ----------------------------
// 128 Q-rows per CTA, 64-token KV tiles. Q fragments in registers.
// K/V double-buffered via cp.async; bias preloaded into S accumulators.
// smem floats: Ks[2][64*72] | Vs[2][64*72] | Pt[128*72]  = 110592 bytes.
__global__ __launch_bounds__(256, 2) void attn_tc3(
    const float* __restrict__ Q, const float* __restrict__ Kpk,
    const float* __restrict__ V, const float* __restrict__ bias,
    float* __restrict__ O)
{
    extern __shared__ float sm[];
    float* Pt = sm + 4 * 4608;

    const int tid = threadIdx.x;
    const int w = tid >> 5, lane = tid & 31;
    const int g = lane >> 2, c = lane & 3;
    const int h = blockIdx.y;
    const int q0 = blockIdx.x * 128;
    const int r0 = 16 * w + g;
    const unsigned sbase = (unsigned)__cvta_generic_to_shared(sm);

    // Q fragments in registers (pre-rounded tf32 in gmem; *0.125 is exact)
    float qa[8][4];
    {
        const float* q0p = Q + (size_t)(q0 + r0) * DM + h * HD;
        const float* q1p = q0p + 8 * DM;
#pragma unroll
        for (int k8 = 0; k8 < 8; k8++) {
            qa[k8][0] = q0p[8 * k8 + c]     * 0.125f;
            qa[k8][1] = q1p[8 * k8 + c]     * 0.125f;
            qa[k8][2] = q0p[8 * k8 + c + 4] * 0.125f;
            qa[k8][3] = q1p[8 * k8 + c + 4] * 0.125f;
        }
    }

    float o[8][4];
#pragma unroll
    for (int j = 0; j < 8; j++)
#pragma unroll
        for (int r = 0; r < 4; r++) o[j][r] = 0.f;
    float mr0 = -1e30f, mr1 = -1e30f, lr0 = 0.f, lr1 = 0.f;

    const int srow = tid >> 4, sc4 = tid & 15;  // staging decomposition
    const float* kbase = Kpk + (size_t)h * NT * 64;

    // stage tile 0 into buffer 0
    {
        const float* ks = kbase;
        const float* vs = V + (size_t)0 * DM + h * HD;
#pragma unroll
        for (int i = 0; i < 4; i++) {
            int row = srow + i * 16;
            cpa16(sbase + (row * 72 + 4 * sc4) * 4, ks + row * 64 + 4 * sc4);
            cpa16(sbase + (2 * 4608 + row * 72 + 4 * sc4) * 4,
                  vs + (size_t)row * DM + 4 * sc4);
        }
        asm volatile("cp.async.commit_group;" ::: "memory");
    }

    const int p0 = 2 * ((2 * c) & 3) + ((c >> 1) & 1);  // packed pos of col 2c

    for (int t = 0; t < NT / 64; t++) {
        const int kv0 = t * 64;
        const int buf = t & 1;
        __syncthreads();   // all warps done with both buffers' previous contents
        if (t + 1 < NT / 64) {
            const float* ks = kbase + (size_t)(kv0 + 64) * 64;
            const float* vs = V + (size_t)(kv0 + 64) * DM + h * HD;
            const unsigned kd = sbase + (buf ^ 1) * 4608 * 4;
            const unsigned vd = sbase + (2 * 4608 + (buf ^ 1) * 4608) * 4;
#pragma unroll
            for (int i = 0; i < 4; i++) {
                int row = srow + i * 16;
                cpa16(kd + (row * 72 + 4 * sc4) * 4, ks + row * 64 + 4 * sc4);
                cpa16(vd + (row * 72 + 4 * sc4) * 4, vs + (size_t)row * DM + 4 * sc4);
            }
            asm volatile("cp.async.commit_group;" ::: "memory");
            asm volatile("cp.async.wait_group 1;" ::: "memory");
        } else {
            asm volatile("cp.async.wait_group 0;" ::: "memory");
        }
        __syncthreads();   // current buffer visible to all warps

        const float* Ksb = sm + buf * 4608;
        const float* Vsb = sm + 2 * 4608 + buf * 4608;

        // ---- S = Q@K^T + bias : accumulators initialized with bias --------
        float s[8][4];
        const float* bp = bias + ((size_t)h * NT + q0 + r0) * NT + kv0;
#pragma unroll
        for (int j = 0; j < 8; j++) {
            float2 b0 = __ldcs((const float2*)(bp + 8 * j + 2 * c));
            float2 b1 = __ldcs((const float2*)(bp + (size_t)8 * NT + 8 * j + 2 * c));
            s[j][0] = b0.x; s[j][1] = b0.y; s[j][2] = b1.x; s[j][3] = b1.y;
        }
#pragma unroll
        for (int k8 = 0; k8 < 8; k8++) {
#pragma unroll
            for (int j = 0; j < 8; j++) {
                float2 kb = *(const float2*)&Ksb[(8 * j + g) * 72 + 8 * k8 + 2 * c];
                mma8(s[j], qa[k8][0], qa[k8][1], qa[k8][2], qa[k8][3], kb.x, kb.y);
            }
        }

        // ---- online softmax (rows r0 / r0+8, reduce over 4-lane c-group) --
        float rm0 = -1e30f, rm1 = -1e30f;
#pragma unroll
        for (int j = 0; j < 8; j++) {
            rm0 = fmaxf(rm0, fmaxf(s[j][0], s[j][1]));
            rm1 = fmaxf(rm1, fmaxf(s[j][2], s[j][3]));
        }
        rm0 = fmaxf(rm0, __shfl_xor_sync(0xffffffffu, rm0, 1));
        rm0 = fmaxf(rm0, __shfl_xor_sync(0xffffffffu, rm0, 2));
        rm1 = fmaxf(rm1, __shfl_xor_sync(0xffffffffu, rm1, 1));
        rm1 = fmaxf(rm1, __shfl_xor_sync(0xffffffffu, rm1, 2));

        float mn0 = fmaxf(mr0, rm0), mn1 = fmaxf(mr1, rm1);
        float corr0 = fast_exp(mr0 - mn0), corr1 = fast_exp(mr1 - mn1);
        mr0 = mn0; mr1 = mn1;

        float sum0 = 0.f, sum1 = 0.f;
#pragma unroll
        for (int j = 0; j < 8; j++) {
            s[j][0] = fast_exp(s[j][0] - mn0);
            s[j][1] = fast_exp(s[j][1] - mn0);
            s[j][2] = fast_exp(s[j][2] - mn1);
            s[j][3] = fast_exp(s[j][3] - mn1);
            sum0 += s[j][0] + s[j][1];
            sum1 += s[j][2] + s[j][3];
        }
        sum0 += __shfl_xor_sync(0xffffffffu, sum0, 1);
        sum0 += __shfl_xor_sync(0xffffffffu, sum0, 2);
        sum1 += __shfl_xor_sync(0xffffffffu, sum1, 1);
        sum1 += __shfl_xor_sync(0xffffffffu, sum1, 2);
        lr0 = lr0 * corr0 + sum0;
        lr1 = lr1 * corr1 + sum1;
#pragma unroll
        for (int j = 0; j < 8; j++) {
            o[j][0] *= corr0; o[j][1] *= corr0;
            o[j][2] *= corr1; o[j][3] *= corr1;
        }

        // ---- P to smem (pair-packed; warp-private rows -> syncwarp only) --
#pragma unroll
        for (int j = 0; j < 8; j++) {
            float* pr  = &Pt[r0 * 72 + 8 * j];
            float* pr8 = pr + 8 * 72;
            pr [p0]     = f2tf(s[j][0]);
            pr [p0 + 2] = f2tf(s[j][1]);
            pr8[p0]     = f2tf(s[j][2]);
            pr8[p0 + 2] = f2tf(s[j][3]);
        }
        __syncwarp();

        // ---- O += P @ V ----------------------------------------------------
#pragma unroll
        for (int k8 = 0; k8 < 8; k8++) {
            float2 a02 = *(const float2*)&Pt[r0 * 72 + 8 * k8 + 2 * c];
            float2 a13 = *(const float2*)&Pt[(r0 + 8) * 72 + 8 * k8 + 2 * c];
#pragma unroll
            for (int j = 0; j < 8; j++) {
                float vb0 = Vsb[(8 * k8 + c) * 72 + 8 * j + g];
                float vb1 = Vsb[(8 * k8 + c + 4) * 72 + 8 * j + g];
                mma8(o[j], a02.x, a13.x, a02.y, a13.y, vb0, vb1);
            }
        }
    }

    float inv0 = 1.0f / lr0, inv1 = 1.0f / lr1;
    const int grow0 = q0 + r0;
#pragma unroll
    for (int j = 0; j < 8; j++) {
        int col = h * HD + 8 * j + 2 * c;
        *(float2*)&O[(size_t)grow0 * DM + col] =
            make_float2(o[j][0] * inv0, o[j][1] * inv0);
        *(float2*)&O[(size_t)(grow0 + 8) * DM + col] =
            make_float2(o[j][2] * inv1, o[j][3] * inv1);
    }
}

// ---------------- fused residual + LayerNorm (one block per row) -----------
__global__ __launch_bounds__(128) void add_ln_kernel(
    const float* __restrict__ A, const float* __restrict__ B,
    const float* __restrict__ g, const float* __restrict__ be,
    float* __restrict__ out)
{
    __shared__ float red[8];
    const int row = blockIdx.x, tid = threadIdx.x;
    float4 a = *(const float4*)&A[(size_t)row * DM + tid * 4];
    float4 b = *(const float4*)&B[(size_t)row * DM + tid * 4];
    float v[4] = {a.x + b.x, a.y + b.y, a.z + b.z, a.w + b.w};

    float s = v[0] + v[1] + v[2] + v[3];
#pragma unroll
    for (int off = 16; off; off >>= 1) s += __shfl_xor_sync(0xffffffffu, s, off);
    if ((tid & 31) == 0) red[tid >> 5] = s;
    __syncthreads();
    float mu = (red[0] + red[1] + red[2] + red[3]) * (1.f / DM);

    float d[4]; float sq = 0.f;
#pragma unroll
    for (int i = 0; i < 4; i++) { d[i] = v[i] - mu; sq += d[i] * d[i]; }
#pragma unroll
    for (int off = 16; off; off >>= 1) sq += __shfl_xor_sync(0xffffffffu, sq, off);
    if ((tid & 31) == 0) red[4 + (tid >> 5)] = sq;
    __syncthreads();
    float inv = rsqrtf((red[4] + red[5] + red[6] + red[7]) * (1.f / DM) + 1e-5f);

    float4 gg = *(const float4*)&g[tid * 4];
    float4 bb = *(const float4*)&be[tid * 4];
    float4 r;
    r.x = d[0] * inv * gg.x + bb.x;
    r.y = d[1] * inv * gg.y + bb.y;
    r.z = d[2] * inv * gg.z + bb.z;
    r.w = d[3] * inv * gg.w + bb.w;
    *(float4*)&out[(size_t)row * DM + tid * 4] = r;
}

// ---------------- launch ----------------------------------------------------
extern "C" void kernel_launch(void* const* d_in, const int* in_sizes, int n_in,
                              void* d_out, int out_size)
{
    const float* x    = (const float*)d_in[0];
    const float* bias = (const float*)d_in[1];
    const float* Wq = (const float*)d_in[2];  const float* bq = (const float*)d_in[3];
    const float* Wk = (const float*)d_in[4];  const float* bk = (const float*)d_in[5];
    const float* Wv = (const float*)d_in[6];  const float* bv = (const float*)d_in[7];
    const float* Wo = (const float*)d_in[8];  const float* bo = (const float*)d_in[9];
    const float* g1 = (const float*)d_in[10]; const float* b1 = (const float*)d_in[11];
    const float* g2 = (const float*)d_in[12]; const float* b2 = (const float*)d_in[13];
    const float* W1 = (const float*)d_in[14]; const float* c1 = (const float*)d_in[15];
    const float* W2 = (const float*)d_in[16]; const float* c2 = (const float*)d_in[17];
    float* out = (float*)d_out;

    float *Qp, *Kp, *Vp, *attnp, *tmpp, *x1p, *hidp;
    cudaGetSymbolAddress((void**)&Qp,    g_Q);
    cudaGetSymbolAddress((void**)&Kp,    g_K);
    cudaGetSymbolAddress((void**)&Vp,    g_V);
    cudaGetSymbolAddress((void**)&attnp, g_attn);
    cudaGetSymbolAddress((void**)&tmpp,  g_tmp);
    cudaGetSymbolAddress((void**)&x1p,   g_x1);
    cudaGetSymbolAddress((void**)&hidp,  g_hid);

    const int ATTN_SMEM = (2 * 64 * 72 + 2 * 64 * 72 + 128 * 72) * 4; // 110592
    cudaFuncSetAttribute(attn_tc3, cudaFuncAttributeMaxDynamicSharedMemorySize, ATTN_SMEM);

    dim3 blk(256);
    dim3 gProj(DM / 128, NT / 128);
    dim3 gFF1(DFF / 128, NT / 128);

    gemm_tc<2><<<gProj, blk>>>(x, Wq, bq, Qp, NT, DM, DM);   // Q: tf32-rounded
    gemm_tc<3><<<gProj, blk>>>(x, Wk, bk, Kp, NT, DM, DM);   // K: rounded + packed
    gemm_tc<2><<<gProj, blk>>>(x, Wv, bv, Vp, NT, DM, DM);   // V: tf32-rounded

    attn_tc3<<<dim3(NT / 128, NH), blk, ATTN_SMEM>>>(Qp, Kp, Vp, bias, attnp);

    gemm_tc<0><<<gProj, blk>>>(attnp, Wo, bo, tmpp, NT, DM, DM);
    add_ln_kernel<<<NT, 128>>>(x, tmpp, g1, b1, x1p);

    gemm_tc<1><<<gFF1, blk>>>(x1p, W1, c1, hidp, NT, DFF, DM);
    gemm_tc<0><<<gProj, blk>>>(hidp, W2, c2, tmpp, NT, DM, DFF);
    add_ln_kernel<<<NT, 128>>>(x1p, tmpp, g2, b2, out);
}

// round 4
// speedup vs baseline: 3.4325x; 1.1338x over previous
#include <cuda_runtime.h>
#include <math.h>

#define NT  4096
#define DM  512
#define NH  8
#define HD  64
#define DFF 1024

// ---------------- scratch (static device globals; no allocations) ----------
__device__ float g_Q[NT * DM];
__device__ float g_K[NT * DM];     // tile-contiguous pair-packed (see kpk_idx)
__device__ float g_V[NT * DM];     // tile-contiguous pair-packed (see vpk_idx)
__device__ float g_attn[NT * DM];
__device__ float g_tmp[NT * DM];
__device__ float g_x1[NT * DM];
__device__ float g_hid[NT * DFF];

// ---------------- helpers ---------------------------------------------------
__device__ __forceinline__ float f2tf(float x) {
    unsigned u;
    asm("cvt.rna.tf32.f32 %0, %1;" : "=r"(u) : "f"(x));
    return __uint_as_float(u);
}

// K packed: per head, per 64-token tile (contiguous 4096 floats):
// [d8-block(8)][token-in-tile(64)][pair-packed 8 dims]
__device__ __forceinline__ size_t kpk_idx(int h, int tok, int dim) {
    int dc = dim & 7;
    return (size_t)h * NT * 64 + (size_t)(tok >> 6) * 4096
         + (((dim >> 3) * 64 + (tok & 63)) << 3) + 2 * (dc & 3) + (dc >> 2);
}
// V packed: per head, per 8-token block: [n(64)][pair-packed 8 tokens]
__device__ __forceinline__ size_t vpk_idx(int h, int tok, int n) {
    return (size_t)h * NT * 64 + (size_t)(tok >> 3) * 512
         + (n << 3) + 2 * (tok & 3) + ((tok >> 2) & 1);
}

__device__ __forceinline__ void mma8(float d[4],
                                     float a0, float a1, float a2, float a3,
                                     float b0, float b1) {
    asm("mma.sync.aligned.m16n8k8.row.col.f32.tf32.tf32.f32 "
        "{%0,%1,%2,%3}, {%4,%5,%6,%7}, {%8,%9}, {%0,%1,%2,%3};"
        : "+f"(d[0]), "+f"(d[1]), "+f"(d[2]), "+f"(d[3])
        : "r"(__float_as_uint(a0)), "r"(__float_as_uint(a1)),
          "r"(__float_as_uint(a2)), "r"(__float_as_uint(a3)),
          "r"(__float_as_uint(b0)), "r"(__float_as_uint(b1)));
}

__device__ __forceinline__ void cpa16(unsigned dst, const void* src) {
    asm volatile("cp.async.cg.shared.global [%0], [%1], 16;" :: "r"(dst), "l"(src));
}

// fast exp for x <= 0 (FMA pipe, avoids MUFU). ~2e-8 rel err.
__device__ __forceinline__ float fast_exp(float x) {
    float y = x * 1.44269504089f;
    y = fmaxf(y, -100.0f);
    float t  = y + 12582912.0f;
    int   ni = __float_as_int(t) - 0x4B400000;
    float f  = y - (t - 12582912.0f);
    float p  = fmaf(f, 0.0013475782f, 0.0096788315f);
    p = fmaf(f, p, 0.0555072548f);
    p = fmaf(f, p, 0.2402211471f);
    p = fmaf(f, p, 0.6931471805f);
    p = fmaf(f, p, 1.0f);
    return __int_as_float(__float_as_int(p) + (ni << 23));
}

// ==================== shared GEMM mainloop (macro-free via inline) ==========
struct GemmCore {
    float acc[4][4][4];
    int tid, w, lane, g, c, wm, wn;
    __device__ __forceinline__ void init(int tid_) {
        tid = tid_; w = tid >> 5; lane = tid & 31;
        g = lane >> 2; c = lane & 3;
        wm = (w >> 2) * 64; wn = (w & 3) * 32;
#pragma unroll
        for (int t = 0; t < 4; t++)
#pragma unroll
            for (int j = 0; j < 4; j++)
#pragma unroll
                for (int r = 0; r < 4; r++) acc[t][j][r] = 0.f;
    }
    __device__ __forceinline__ void run(
        const float* __restrict__ A, const float* __restrict__ W,
        int m0, int n0, int N, int K,
        float (*As)[128 * 20], float (*Ws)[16 * 136])
    {
        const int aRow0 = tid >> 2,  aC4_0 = tid & 3;
        const int aRow1 = (tid + 256) >> 2, aC4_1 = (tid + 256) & 3;
        const int wRow0 = tid >> 5,  wC4_0 = tid & 31;
        const int wRow1 = (tid + 256) >> 5, wC4_1 = (tid + 256) & 31;
        float4 ra0, ra1, rw0, rw1;

        ra0 = *(const float4*)&A[(size_t)(m0 + aRow0) * K + 4 * aC4_0];
        ra1 = *(const float4*)&A[(size_t)(m0 + aRow1) * K + 4 * aC4_1];
        rw0 = *(const float4*)&W[(size_t)wRow0 * N + n0 + 4 * wC4_0];
        rw1 = *(const float4*)&W[(size_t)wRow1 * N + n0 + 4 * wC4_1];
        {
            *(float4*)&As[0][aRow0 * 20 + 4 * aC4_0] =
                make_float4(f2tf(ra0.x), f2tf(ra0.y), f2tf(ra0.z), f2tf(ra0.w));
            *(float4*)&As[0][aRow1 * 20 + 4 * aC4_1] =
                make_float4(f2tf(ra1.x), f2tf(ra1.y), f2tf(ra1.z), f2tf(ra1.w));
            *(float4*)&Ws[0][wRow0 * 136 + 4 * wC4_0] =
                make_float4(f2tf(rw0.x), f2tf(rw0.y), f2tf(rw0.z), f2tf(rw0.w));
            *(float4*)&Ws[0][wRow1 * 136 + 4 * wC4_1] =
                make_float4(f2tf(rw1.x), f2tf(rw1.y), f2tf(rw1.z), f2tf(rw1.w));
        }
        __syncthreads();

        const int nk = K >> 4;
        for (int kb = 0; kb < nk; kb++) {
            const int cur  = kb & 1;
            const bool more = (kb + 1 < nk);
            if (more) {
                int k1 = (kb + 1) * 16;
                ra0 = *(const float4*)&A[(size_t)(m0 + aRow0) * K + k1 + 4 * aC4_0];
                ra1 = *(const float4*)&A[(size_t)(m0 + aRow1) * K + k1 + 4 * aC4_1];
                rw0 = *(const float4*)&W[(size_t)(k1 + wRow0) * N + n0 + 4 * wC4_0];
                rw1 = *(const float4*)&W[(size_t)(k1 + wRow1) * N + n0 + 4 * wC4_1];
            }
#pragma unroll
            for (int ks = 0; ks < 2; ks++) {
                const int k8 = ks * 8;
                float af[4][4];
#pragma unroll
                for (int t = 0; t < 4; t++) {
                    af[t][0] = As[cur][(wm + 16 * t + g) * 20 + k8 + c];
                    af[t][1] = As[cur][(wm + 16 * t + g + 8) * 20 + k8 + c];
                    af[t][2] = As[cur][(wm + 16 * t + g) * 20 + k8 + c + 4];
                    af[t][3] = As[cur][(wm + 16 * t + g + 8) * 20 + k8 + c + 4];
                }
#pragma unroll
                for (int j = 0; j < 4; j++) {
                    float b0 = Ws[cur][(k8 + c) * 136 + wn + 8 * j + g];
                    float b1 = Ws[cur][(k8 + c + 4) * 136 + wn + 8 * j + g];
#pragma unroll
                    for (int t = 0; t < 4; t++)
                        mma8(acc[t][j], af[t][0], af[t][1], af[t][2], af[t][3], b0, b1);
                }
            }
            if (more) {
                const int nxt = cur ^ 1;
                *(float4*)&As[nxt][aRow0 * 20 + 4 * aC4_0] =
                    make_float4(f2tf(ra0.x), f2tf(ra0.y), f2tf(ra0.z), f2tf(ra0.w));
                *(float4*)&As[nxt][aRow1 * 20 + 4 * aC4_1] =
                    make_float4(f2tf(ra1.x), f2tf(ra1.y), f2tf(ra1.z), f2tf(ra1.w));
                *(float4*)&Ws[nxt][wRow0 * 136 + 4 * wC4_0] =
                    make_float4(f2tf(rw0.x), f2tf(rw0.y), f2tf(rw0.z), f2tf(rw0.w));
                *(float4*)&Ws[nxt][wRow1 * 136 + 4 * wC4_1] =
                    make_float4(f2tf(rw1.x), f2tf(rw1.y), f2tf(rw1.z), f2tf(rw1.w));
            }
            __syncthreads();
        }
    }
};

// ---------------- generic GEMM (modes 0 plain / 1 relu / 2 tf32-out) -------
template <int MODE>
__global__ __launch_bounds__(256, 2) void gemm_tc(
    const float* __restrict__ A, const float* __restrict__ W,
    const float* __restrict__ bias, float* __restrict__ C,
    int M, int N, int K)
{
    __shared__ float As[2][128 * 20];
    __shared__ float Ws[2][16 * 136];
    GemmCore gc; gc.init(threadIdx.x);
    const int m0 = blockIdx.y * 128, n0 = blockIdx.x * 128;
    gc.run(A, W, m0, n0, N, K, As, Ws);

#pragma unroll
    for (int t = 0; t < 4; t++) {
        int row0 = m0 + gc.wm + 16 * t + gc.g;
#pragma unroll
        for (int j = 0; j < 4; j++) {
            int col = n0 + gc.wn + 8 * j + 2 * gc.c;
            float2 bv = *(const float2*)&bias[col];
            float v00 = gc.acc[t][j][0] + bv.x, v01 = gc.acc[t][j][1] + bv.y;
            float v10 = gc.acc[t][j][2] + bv.x, v11 = gc.acc[t][j][3] + bv.y;
            if (MODE == 1) {
                v00 = fmaxf(v00, 0.f); v01 = fmaxf(v01, 0.f);
                v10 = fmaxf(v10, 0.f); v11 = fmaxf(v11, 0.f);
            }
            if (MODE == 2) {
                *(float2*)&C[(size_t)row0 * N + col] = make_float2(f2tf(v00), f2tf(v01));
                *(float2*)&C[(size_t)(row0 + 8) * N + col] = make_float2(f2tf(v10), f2tf(v11));
            } else {
                *(float2*)&C[(size_t)row0 * N + col]       = make_float2(v00, v01);
                *(float2*)&C[(size_t)(row0 + 8) * N + col] = make_float2(v10, v11);
            }
        }
    }
}

// ---------------- fused QKV GEMM: blockIdx.z selects projection -------------
__global__ __launch_bounds__(256, 2) void gemm_qkv(
    const float* __restrict__ x,
    const float* __restrict__ Wq, const float* __restrict__ bq, float* __restrict__ Qo,
    const float* __restrict__ Wk, const float* __restrict__ bk, float* __restrict__ Ko,
    const float* __restrict__ Wv, const float* __restrict__ bv, float* __restrict__ Vo)
{
    __shared__ float As[2][128 * 20];
    __shared__ float Ws[2][16 * 136];
    const int z = blockIdx.z;
    const float* W    = (z == 0) ? Wq : (z == 1) ? Wk : Wv;
    const float* bias = (z == 0) ? bq : (z == 1) ? bk : bv;

    GemmCore gc; gc.init(threadIdx.x);
    const int m0 = blockIdx.y * 128, n0 = blockIdx.x * 128;
    gc.run(x, W, m0, n0, DM, DM, As, Ws);

#pragma unroll
    for (int t = 0; t < 4; t++) {
        int row0 = m0 + gc.wm + 16 * t + gc.g;
#pragma unroll
        for (int j = 0; j < 4; j++) {
            int col = n0 + gc.wn + 8 * j + 2 * gc.c;
            float2 bvv = *(const float2*)&bias[col];
            float v00 = f2tf(gc.acc[t][j][0] + bvv.x), v01 = f2tf(gc.acc[t][j][1] + bvv.y);
            float v10 = f2tf(gc.acc[t][j][2] + bvv.x), v11 = f2tf(gc.acc[t][j][3] + bvv.y);
            if (z == 0) {
                *(float2*)&Qo[(size_t)row0 * DM + col]       = make_float2(v00, v01);
                *(float2*)&Qo[(size_t)(row0 + 8) * DM + col] = make_float2(v10, v11);
            } else if (z == 1) {
                int h = col >> 6, dl = col & 63;
                Ko[kpk_idx(h, row0,     dl)]     = v00;
                Ko[kpk_idx(h, row0,     dl + 1)] = v01;
                Ko[kpk_idx(h, row0 + 8, dl)]     = v10;
                Ko[kpk_idx(h, row0 + 8, dl + 1)] = v11;
            } else {
                int h = col >> 6, dl = col & 63;
                Vo[vpk_idx(h, row0,     dl)]     = v00;
                Vo[vpk_idx(h, row0,     dl + 1)] = v01;
                Vo[vpk_idx(h, row0 + 8, dl)]     = v10;
                Vo[vpk_idx(h, row0 + 8, dl + 1)] = v11;
            }
        }
    }
}

// ---------------- tensor-core flash attention v4 ----------------------------
// 128 Q-rows per CTA, 64-token KV tiles, pair-packed K/V (contiguous tiles),
// P kept in registers and permuted to A-fragments via warp shuffles.
// smem: Ks[2][4096] | Vs[2][4096] floats = 65536 bytes.
__global__ __launch_bounds__(256, 2) void attn_tc4(
    const float* __restrict__ Q, const float* __restrict__ Kpk,
    const float* __restrict__ Vpk, const float* __restrict__ bias,
    float* __restrict__ O)
{
    extern __shared__ float sm[];
    const int tid = threadIdx.x;
    const int w = tid >> 5, lane = tid & 31;
    const int g = lane >> 2, c = lane & 3;
    const int h = blockIdx.y;
    const int q0 = blockIdx.x * 128;
    const int r0 = 16 * w + g;
    const unsigned sbase = (unsigned)__cvta_generic_to_shared(sm);

    // Q fragments in registers (gmem already tf32-rounded; *0.125 exact)
    float qa[8][4];
    {
        const float* q0p = Q + (size_t)(q0 + r0) * DM + h * HD;
        const float* q1p = q0p + 8 * DM;
#pragma unroll
        for (int k8 = 0; k8 < 8; k8++) {
            qa[k8][0] = q0p[8 * k8 + c]     * 0.125f;
            qa[k8][1] = q1p[8 * k8 + c]     * 0.125f;
            qa[k8][2] = q0p[8 * k8 + c + 4] * 0.125f;
            qa[k8][3] = q1p[8 * k8 + c + 4] * 0.125f;
        }
    }

    float o[8][4];
#pragma unroll
    for (int j = 0; j < 8; j++)
#pragma unroll
        for (int r = 0; r < 4; r++) o[j][r] = 0.f;
    float mr0 = -1e30f, mr1 = -1e30f, lr0 = 0.f, lr1 = 0.f;

    const float* kbase = Kpk + (size_t)h * NT * 64;
    const float* vbase = Vpk + (size_t)h * NT * 64;

    // stage tile 0 into buffer 0 (both tiles contiguous 16KB)
    {
        const char* ks = (const char*)kbase;
        const char* vs = (const char*)vbase;
#pragma unroll
        for (int i = 0; i < 4; i++) {
            cpa16(sbase + tid * 16 + i * 4096, ks + tid * 16 + i * 4096);
            cpa16(sbase + 32768 + tid * 16 + i * 4096, vs + tid * 16 + i * 4096);
        }
        asm volatile("cp.async.commit_group;" ::: "memory");
    }

    const int l0 = (g << 2) | (c >> 1);   // shuffle source lanes for P->A
    const int l1 = l0 + 2;
    const bool oddc = (c & 1);

    for (int t = 0; t < NT / 64; t++) {
        const int buf = t & 1;
        __syncthreads();   // all warps done with buffer buf^1 contents
        if (t + 1 < NT / 64) {
            const char* ks = (const char*)(kbase + (size_t)(t + 1) * 4096);
            const char* vs = (const char*)(vbase + (size_t)(t + 1) * 4096);
            const unsigned kd = sbase + (buf ^ 1) * 16384;
            const unsigned vd = sbase + 32768 + (buf ^ 1) * 16384;
#pragma unroll
            for (int i = 0; i < 4; i++) {
                cpa16(kd + tid * 16 + i * 4096, ks + tid * 16 + i * 4096);
                cpa16(vd + tid * 16 + i * 4096, vs + tid * 16 + i * 4096);
            }
            asm volatile("cp.async.commit_group;" ::: "memory");
            asm volatile("cp.async.wait_group 1;" ::: "memory");
        } else {
            asm volatile("cp.async.wait_group 0;" ::: "memory");
        }
        __syncthreads();

        const float* Ksb = sm + buf * 4096;
        const float* Vsb = sm + 8192 + buf * 4096;

        // ---- S = Q@K^T + bias (bias preloaded into accumulators) ----------
        float s[8][4];
        const float* bp = bias + ((size_t)h * NT + q0 + r0) * NT + t * 64;
#pragma unroll
        for (int j = 0; j < 8; j++) {
            float2 b0 = __ldcs((const float2*)(bp + 8 * j + 2 * c));
            float2 b1 = __ldcs((const float2*)(bp + (size_t)8 * NT + 8 * j + 2 * c));
            s[j][0] = b0.x; s[j][1] = b0.y; s[j][2] = b1.x; s[j][3] = b1.y;
        }
#pragma unroll
        for (int k8 = 0; k8 < 8; k8++) {
#pragma unroll
            for (int j = 0; j < 8; j++) {
                float2 kb = *(const float2*)&Ksb[k8 * 512 + (8 * j + g) * 8 + 2 * c];
                mma8(s[j], qa[k8][0], qa[k8][1], qa[k8][2], qa[k8][3], kb.x, kb.y);
            }
        }

        // ---- online softmax (rows r0 / r0+8, reduce over 4-lane c-group) --
        float rm0 = -1e30f, rm1 = -1e30f;
#pragma unroll
        for (int j = 0; j < 8; j++) {
            rm0 = fmaxf(rm0, fmaxf(s[j][0], s[j][1]));
            rm1 = fmaxf(rm1, fmaxf(s[j][2], s[j][3]));
        }
        rm0 = fmaxf(rm0, __shfl_xor_sync(0xffffffffu, rm0, 1));
        rm0 = fmaxf(rm0, __shfl_xor_sync(0xffffffffu, rm0, 2));
        rm1 = fmaxf(rm1, __shfl_xor_sync(0xffffffffu, rm1, 1));
        rm1 = fmaxf(rm1, __shfl_xor_sync(0xffffffffu, rm1, 2));

        float mn0 = fmaxf(mr0, rm0), mn1 = fmaxf(mr1, rm1);
        float corr0 = fast_exp(mr0 - mn0), corr1 = fast_exp(mr1 - mn1);
        mr0 = mn0; mr1 = mn1;

        float sum0 = 0.f, sum1 = 0.f;
#pragma unroll
        for (int j = 0; j < 8; j++) {
            s[j][0] = f2tf(fast_exp(s[j][0] - mn0));
            s[j][1] = f2tf(fast_exp(s[j][1] - mn0));
            s[j][2] = f2tf(fast_exp(s[j][2] - mn1));
            s[j][3] = f2tf(fast_exp(s[j][3] - mn1));
            sum0 += s[j][0] + s[j][1];
            sum1 += s[j][2] + s[j][3];
        }
        sum0 += __shfl_xor_sync(0xffffffffu, sum0, 1);
        sum0 += __shfl_xor_sync(0xffffffffu, sum0, 2);
        sum1 += __shfl_xor_sync(0xffffffffu, sum1, 1);
        sum1 += __shfl_xor_sync(0xffffffffu, sum1, 2);
        lr0 = lr0 * corr0 + sum0;
        lr1 = lr1 * corr1 + sum1;
#pragma unroll
        for (int j = 0; j < 8; j++) {
            o[j][0] *= corr0; o[j][1] *= corr0;
            o[j][2] *= corr1; o[j][3] *= corr1;
        }

        // ---- O += P @ V : P permuted to A-fragments via shuffles ----------
#pragma unroll
        for (int t8 = 0; t8 < 8; t8++) {
            float v00 = __shfl_sync(0xffffffffu, s[t8][0], l0);
            float v01 = __shfl_sync(0xffffffffu, s[t8][1], l0);
            float v10 = __shfl_sync(0xffffffffu, s[t8][2], l0);
            float v11 = __shfl_sync(0xffffffffu, s[t8][3], l0);
            float w00 = __shfl_sync(0xffffffffu, s[t8][0], l1);
            float w01 = __shfl_sync(0xffffffffu, s[t8][1], l1);
            float w10 = __shfl_sync(0xffffffffu, s[t8][2], l1);
            float w11 = __shfl_sync(0xffffffffu, s[t8][3], l1);
            float a0 = oddc ? v01 : v00;
            float a1 = oddc ? v11 : v10;
            float a2 = oddc ? w01 : w00;
            float a3 = oddc ? w11 : w10;
#pragma unroll
            for (int j = 0; j < 8; j++) {
                float2 vb = *(const float2*)&Vsb[t8 * 512 + (8 * j + g) * 8 + 2 * c];
                mma8(o[j], a0, a1, a2, a3, vb.x, vb.y);
            }
        }
    }

    float inv0 = 1.0f / lr0, inv1 = 1.0f / lr1;
    const int grow0 = q0 + r0;
#pragma unroll
    for (int j = 0; j < 8; j++) {
        int col = h * HD + 8 * j + 2 * c;
        *(float2*)&O[(size_t)grow0 * DM + col] =
            make_float2(o[j][0] * inv0, o[j][1] * inv0);
        *(float2*)&O[(size_t)(grow0 + 8) * DM + col] =
            make_float2(o[j][2] * inv1, o[j][3] * inv1);
    }
}

// ---------------- fused residual + LayerNorm (one block per row) -----------
__global__ __launch_bounds__(128) void add_ln_kernel(
    const float* __restrict__ A, const float* __restrict__ B,
    const float* __restrict__ g, const float* __restrict__ be,
    float* __restrict__ out)
{
    __shared__ float red[8];
    const int row = blockIdx.x, tid = threadIdx.x;
    float4 a = *(const float4*)&A[(size_t)row * DM + tid * 4];
    float4 b = *(const float4*)&B[(size_t)row * DM + tid * 4];
    float v[4] = {a.x + b.x, a.y + b.y, a.z + b.z, a.w + b.w};

    float s = v[0] + v[1] + v[2] + v[3];
#pragma unroll
    for (int off = 16; off; off >>= 1) s += __shfl_xor_sync(0xffffffffu, s, off);
    if ((tid & 31) == 0) red[tid >> 5] = s;
    __syncthreads();
    float mu = (red[0] + red[1] + red[2] + red[3]) * (1.f / DM);

    float d[4]; float sq = 0.f;
#pragma unroll
    for (int i = 0; i < 4; i++) { d[i] = v[i] - mu; sq += d[i] * d[i]; }
#pragma unroll
    for (int off = 16; off; off >>= 1) sq += __shfl_xor_sync(0xffffffffu, sq, off);
    if ((tid & 31) == 0) red[4 + (tid >> 5)] = sq;
    __syncthreads();
    float inv = rsqrtf((red[4] + red[5] + red[6] + red[7]) * (1.f / DM) + 1e-5f);

    float4 gg = *(const float4*)&g[tid * 4];
    float4 bb = *(const float4*)&be[tid * 4];
    float4 r;
    r.x = d[0] * inv * gg.x + bb.x;
    r.y = d[1] * inv * gg.y + bb.y;
    r.z = d[2] * inv * gg.z + bb.z;
    r.w = d[3] * inv * gg.w + bb.w;
    *(float4*)&out[(size_t)row * DM + tid * 4] = r;
}

// ---------------- launch ----------------------------------------------------
extern "C" void kernel_launch(void* const* d_in, const int* in_sizes, int n_in,
                              void* d_out, int out_size)
{
    const float* x    = (const float*)d_in[0];
    const float* bias = (const float*)d_in[1];
    const float* Wq = (const float*)d_in[2];  const float* bq = (const float*)d_in[3];
    const float* Wk = (const float*)d_in[4];  const float* bk = (const float*)d_in[5];
    const float* Wv = (const float*)d_in[6];  const float* bv = (const float*)d_in[7];
    const float* Wo = (const float*)d_in[8];  const float* bo = (const float*)d_in[9];
    const float* g1 = (const float*)d_in[10]; const float* b1 = (const float*)d_in[11];
    const float* g2 = (const float*)d_in[12]; const float* b2 = (const float*)d_in[13];
    const float* W1 = (const float*)d_in[14]; const float* c1 = (const float*)d_in[15];
    const float* W2 = (const float*)d_in[16]; const float* c2 = (const float*)d_in[17];
    float* out = (float*)d_out;

    float *Qp, *Kp, *Vp, *attnp, *tmpp, *x1p, *hidp;
    cudaGetSymbolAddress((void**)&Qp,    g_Q);
    cudaGetSymbolAddress((void**)&Kp,    g_K);
    cudaGetSymbolAddress((void**)&Vp,    g_V);
    cudaGetSymbolAddress((void**)&attnp, g_attn);
    cudaGetSymbolAddress((void**)&tmpp,  g_tmp);
    cudaGetSymbolAddress((void**)&x1p,   g_x1);
    cudaGetSymbolAddress((void**)&hidp,  g_hid);

    const int ATTN_SMEM = 65536;
    cudaFuncSetAttribute(attn_tc4, cudaFuncAttributeMaxDynamicSharedMemorySize, ATTN_SMEM);

    dim3 blk(256);
    dim3 gQKV(DM / 128, NT / 128, 3);  // 4 x 32 x 3 = 384 CTAs, one launch
    dim3 gProj(DM / 128, NT / 128);
    dim3 gFF1(DFF / 128, NT / 128);

    gemm_qkv<<<gQKV, blk>>>(x, Wq, bq, Qp, Wk, bk, Kp, Wv, bv, Vp);

    attn_tc4<<<dim3(NT / 128, NH), blk, ATTN_SMEM>>>(Qp, Kp, Vp, bias, attnp);

    gemm_tc<0><<<gProj, blk>>>(attnp, Wo, bo, tmpp, NT, DM, DM);
    add_ln_kernel<<<NT, 128>>>(x, tmpp, g1, b1, x1p);

    gemm_tc<1><<<gFF1, blk>>>(x1p, W1, c1, hidp, NT, DFF, DM);
    gemm_tc<0><<<gProj, blk>>>(hidp, W2, c2, tmpp, NT, DM, DFF);
    add_ln_kernel<<<NT, 128>>>(x1p, tmpp, g2, b2, out);
}

// round 5
// speedup vs baseline: 3.5207x; 1.0257x over previous
#include <cuda_runtime.h>
#include <math.h>

#define NT  4096
#define DM  512
#define NH  8
#define HD  64
#define DFF 1024

// ---------------- scratch (static device globals; no allocations) ----------
__device__ float g_Q[NT * DM];
__device__ float g_K[NT * DM];     // tile-contiguous pair-packed (see kpk_idx)
__device__ float g_V[NT * DM];     // tile-contiguous pair-packed (see vpk_idx)
__device__ float g_attn[NT * DM];
__device__ float g_tmp[NT * DM];
__device__ float g_x1[NT * DM];
__device__ float g_hid[NT * DFF];

// ---------------- helpers ---------------------------------------------------
__device__ __forceinline__ float f2tf(float x) {
    unsigned u;
    asm("cvt.rna.tf32.f32 %0, %1;" : "=r"(u) : "f"(x));
    return __uint_as_float(u);
}

// K packed: per head, per 64-token tile (contiguous 4096 floats):
// [d8-block(8)][token-in-tile(64)][pair-packed 8 dims]
__device__ __forceinline__ size_t kpk_idx(int h, int tok, int dim) {
    int dc = dim & 7;
    return (size_t)h * NT * 64 + (size_t)(tok >> 6) * 4096
         + (((dim >> 3) * 64 + (tok & 63)) << 3) + 2 * (dc & 3) + (dc >> 2);
}
// V packed: per head, per 8-token block: [n(64)][pair-packed 8 tokens]
__device__ __forceinline__ size_t vpk_idx(int h, int tok, int n) {
    return (size_t)h * NT * 64 + (size_t)(tok >> 3) * 512
         + (n << 3) + 2 * (tok & 3) + ((tok >> 2) & 1);
}

__device__ __forceinline__ void mma8(float d[4],
                                     float a0, float a1, float a2, float a3,
                                     float b0, float b1) {
    asm("mma.sync.aligned.m16n8k8.row.col.f32.tf32.tf32.f32 "
        "{%0,%1,%2,%3}, {%4,%5,%6,%7}, {%8,%9}, {%0,%1,%2,%3};"
        : "+f"(d[0]), "+f"(d[1]), "+f"(d[2]), "+f"(d[3])
        : "r"(__float_as_uint(a0)), "r"(__float_as_uint(a1)),
          "r"(__float_as_uint(a2)), "r"(__float_as_uint(a3)),
          "r"(__float_as_uint(b0)), "r"(__float_as_uint(b1)));
}

__device__ __forceinline__ void cpa16(unsigned dst, const void* src) {
    asm volatile("cp.async.cg.shared.global [%0], [%1], 16;" :: "r"(dst), "l"(src));
}

__device__ __forceinline__ void pf_l2(const void* p) {
    asm volatile("prefetch.global.L2 [%0];" :: "l"(p));
}

// fast exp for x <= 0 (FMA pipe, avoids MUFU). ~2e-8 rel err.
__device__ __forceinline__ float fast_exp(float x) {
    float y = x * 1.44269504089f;
    y = fmaxf(y, -100.0f);
    float t  = y + 12582912.0f;
    int   ni = __float_as_int(t) - 0x4B400000;
    float f  = y - (t - 12582912.0f);
    float p  = fmaf(f, 0.0013475782f, 0.0096788315f);
    p = fmaf(f, p, 0.0555072548f);
    p = fmaf(f, p, 0.2402211471f);
    p = fmaf(f, p, 0.6931471805f);
    p = fmaf(f, p, 1.0f);
    return __int_as_float(__float_as_int(p) + (ni << 23));
}

// ==================== shared GEMM mainloop ==================================
struct GemmCore {
    float acc[4][4][4];
    int tid, w, lane, g, c, wm, wn;
    __device__ __forceinline__ void init(int tid_) {
        tid = tid_; w = tid >> 5; lane = tid & 31;
        g = lane >> 2; c = lane & 3;
        wm = (w >> 2) * 64; wn = (w & 3) * 32;
#pragma unroll
        for (int t = 0; t < 4; t++)
#pragma unroll
            for (int j = 0; j < 4; j++)
#pragma unroll
                for (int r = 0; r < 4; r++) acc[t][j][r] = 0.f;
    }
    __device__ __forceinline__ void run(
        const float* __restrict__ A, const float* __restrict__ W,
        int m0, int n0, int N, int K,
        float (*As)[128 * 20], float (*Ws)[16 * 136])
    {
        const int aRow0 = tid >> 2,  aC4_0 = tid & 3;
        const int aRow1 = (tid + 256) >> 2, aC4_1 = (tid + 256) & 3;
        const int wRow0 = tid >> 5,  wC4_0 = tid & 31;
        const int wRow1 = (tid + 256) >> 5, wC4_1 = (tid + 256) & 31;
        float4 ra0, ra1, rw0, rw1;

        ra0 = *(const float4*)&A[(size_t)(m0 + aRow0) * K + 4 * aC4_0];
        ra1 = *(const float4*)&A[(size_t)(m0 + aRow1) * K + 4 * aC4_1];
        rw0 = *(const float4*)&W[(size_t)wRow0 * N + n0 + 4 * wC4_0];
        rw1 = *(const float4*)&W[(size_t)wRow1 * N + n0 + 4 * wC4_1];
        {
            *(float4*)&As[0][aRow0 * 20 + 4 * aC4_0] =
                make_float4(f2tf(ra0.x), f2tf(ra0.y), f2tf(ra0.z), f2tf(ra0.w));
            *(float4*)&As[0][aRow1 * 20 + 4 * aC4_1] =
                make_float4(f2tf(ra1.x), f2tf(ra1.y), f2tf(ra1.z), f2tf(ra1.w));
            *(float4*)&Ws[0][wRow0 * 136 + 4 * wC4_0] =
                make_float4(f2tf(rw0.x), f2tf(rw0.y), f2tf(rw0.z), f2tf(rw0.w));
            *(float4*)&Ws[0][wRow1 * 136 + 4 * wC4_1] =
                make_float4(f2tf(rw1.x), f2tf(rw1.y), f2tf(rw1.z), f2tf(rw1.w));
        }
        __syncthreads();

        const int nk = K >> 4;
        for (int kb = 0; kb < nk; kb++) {
            const int cur  = kb & 1;
            const bool more = (kb + 1 < nk);
            if (more) {
                int k1 = (kb + 1) * 16;
                ra0 = *(const float4*)&A[(size_t)(m0 + aRow0) * K + k1 + 4 * aC4_0];
                ra1 = *(const float4*)&A[(size_t)(m0 + aRow1) * K + k1 + 4 * aC4_1];
                rw0 = *(const float4*)&W[(size_t)(k1 + wRow0) * N + n0 + 4 * wC4_0];
                rw1 = *(const float4*)&W[(size_t)(k1 + wRow1) * N + n0 + 4 * wC4_1];
            }
#pragma unroll
            for (int ks = 0; ks < 2; ks++) {
                const int k8 = ks * 8;
                float af[4][4];
#pragma unroll
                for (int t = 0; t < 4; t++) {
                    af[t][0] = As[cur][(wm + 16 * t + g) * 20 + k8 + c];
                    af[t][1] = As[cur][(wm + 16 * t + g + 8) * 20 + k8 + c];
                    af[t][2] = As[cur][(wm + 16 * t + g) * 20 + k8 + c + 4];
                    af[t][3] = As[cur][(wm + 16 * t + g + 8) * 20 + k8 + c + 4];
                }
#pragma unroll
                for (int j = 0; j < 4; j++) {
                    float b0 = Ws[cur][(k8 + c) * 136 + wn + 8 * j + g];
                    float b1 = Ws[cur][(k8 + c + 4) * 136 + wn + 8 * j + g];
#pragma unroll
                    for (int t = 0; t < 4; t++)
                        mma8(acc[t][j], af[t][0], af[t][1], af[t][2], af[t][3], b0, b1);
                }
            }
            if (more) {
                const int nxt = cur ^ 1;
                *(float4*)&As[nxt][aRow0 * 20 + 4 * aC4_0] =
                    make_float4(f2tf(ra0.x), f2tf(ra0.y), f2tf(ra0.z), f2tf(ra0.w));
                *(float4*)&As[nxt][aRow1 * 20 + 4 * aC4_1] =
                    make_float4(f2tf(ra1.x), f2tf(ra1.y), f2tf(ra1.z), f2tf(ra1.w));
                *(float4*)&Ws[nxt][wRow0 * 136 + 4 * wC4_0] =
                    make_float4(f2tf(rw0.x), f2tf(rw0.y), f2tf(rw0.z), f2tf(rw0.w));
                *(float4*)&Ws[nxt][wRow1 * 136 + 4 * wC4_1] =
                    make_float4(f2tf(rw1.x), f2tf(rw1.y), f2tf(rw1.z), f2tf(rw1.w));
            }
            __syncthreads();
        }
    }
};

// ---------------- generic GEMM (modes 0 plain / 1 relu / 2 tf32-out) -------
template <int MODE>
__global__ __launch_bounds__(256, 2) void gemm_tc(
    const float* __restrict__ A, const float* __restrict__ W,
    const float* __restrict__ bias, float* __restrict__ C,
    int M, int N, int K)
{
    __shared__ float As[2][128 * 20];
    __shared__ float Ws[2][16 * 136];
    GemmCore gc; gc.init(threadIdx.x);
    const int m0 = blockIdx.y * 128, n0 = blockIdx.x * 128;
    gc.run(A, W, m0, n0, N, K, As, Ws);

#pragma unroll
    for (int t = 0; t < 4; t++) {
        int row0 = m0 + gc.wm + 16 * t + gc.g;
#pragma unroll
        for (int j = 0; j < 4; j++) {
            int col = n0 + gc.wn + 8 * j + 2 * gc.c;
            float2 bv = *(const float2*)&bias[col];
            float v00 = gc.acc[t][j][0] + bv.x, v01 = gc.acc[t][j][1] + bv.y;
            float v10 = gc.acc[t][j][2] + bv.x, v11 = gc.acc[t][j][3] + bv.y;
            if (MODE == 1) {
                v00 = fmaxf(v00, 0.f); v01 = fmaxf(v01, 0.f);
                v10 = fmaxf(v10, 0.f); v11 = fmaxf(v11, 0.f);
            }
            if (MODE == 2) {
                *(float2*)&C[(size_t)row0 * N + col] = make_float2(f2tf(v00), f2tf(v01));
                *(float2*)&C[(size_t)(row0 + 8) * N + col] = make_float2(f2tf(v10), f2tf(v11));
            } else {
                *(float2*)&C[(size_t)row0 * N + col]       = make_float2(v00, v01);
                *(float2*)&C[(size_t)(row0 + 8) * N + col] = make_float2(v10, v11);
            }
        }
    }
}

// ---------------- fused QKV GEMM: blockIdx.z selects projection -------------
__global__ __launch_bounds__(256, 2) void gemm_qkv(
    const float* __restrict__ x,
    const float* __restrict__ Wq, const float* __restrict__ bq, float* __restrict__ Qo,
    const float* __restrict__ Wk, const float* __restrict__ bk, float* __restrict__ Ko,
    const float* __restrict__ Wv, const float* __restrict__ bv, float* __restrict__ Vo)
{
    __shared__ float As[2][128 * 20];
    __shared__ float Ws[2][16 * 136];
    const int z = blockIdx.z;
    const float* W    = (z == 0) ? Wq : (z == 1) ? Wk : Wv;
    const float* bias = (z == 0) ? bq : (z == 1) ? bk : bv;

    GemmCore gc; gc.init(threadIdx.x);
    const int m0 = blockIdx.y * 128, n0 = blockIdx.x * 128;
    gc.run(x, W, m0, n0, DM, DM, As, Ws);

#pragma unroll
    for (int t = 0; t < 4; t++) {
        int row0 = m0 + gc.wm + 16 * t + gc.g;
#pragma unroll
        for (int j = 0; j < 4; j++) {
            int col = n0 + gc.wn + 8 * j + 2 * gc.c;
            float2 bvv = *(const float2*)&bias[col];
            float v00 = f2tf(gc.acc[t][j][0] + bvv.x), v01 = f2tf(gc.acc[t][j][1] + bvv.y);
            float v10 = f2tf(gc.acc[t][j][2] + bvv.x), v11 = f2tf(gc.acc[t][j][3] + bvv.y);
            if (z == 0) {
                *(float2*)&Qo[(size_t)row0 * DM + col]       = make_float2(v00, v01);
                *(float2*)&Qo[(size_t)(row0 + 8) * DM + col] = make_float2(v10, v11);
            } else if (z == 1) {
                int h = col >> 6, dl = col & 63;
                Ko[kpk_idx(h, row0,     dl)]     = v00;
                Ko[kpk_idx(h, row0,     dl + 1)] = v01;
                Ko[kpk_idx(h, row0 + 8, dl)]     = v10;
                Ko[kpk_idx(h, row0 + 8, dl + 1)] = v11;
            } else {
                int h = col >> 6, dl = col & 63;
                Vo[vpk_idx(h, row0,     dl)]     = v00;
                Vo[vpk_idx(h, row0,     dl + 1)] = v01;
                Vo[vpk_idx(h, row0 + 8, dl)]     = v10;
                Vo[vpk_idx(h, row0 + 8, dl + 1)] = v11;
            }
        }
    }
}

// ---------------- tensor-core flash attention v5 ----------------------------
// 128 Q-rows per CTA, 64-token KV tiles, triple-buffered cp.async pipeline
// (2 tiles in flight, ONE __syncthreads per tile), L2-prefetched bias,
// warp-uniform softmax-rescale skip. smem: K[3][4096] | V[3][4096] = 96 KB.
__global__ __launch_bounds__(256, 2) void attn_tc5(
    const float* __restrict__ Q, const float* __restrict__ Kpk,
    const float* __restrict__ Vpk, const float* __restrict__ bias,
    float* __restrict__ O)
{
    extern __shared__ float sm[];
    const int tid = threadIdx.x;
    const int lane = tid & 31;
    const int g = lane >> 2, c = lane & 3;
    const int h = blockIdx.y;
    const int q0 = blockIdx.x * 128;
    const int r0 = 16 * (tid >> 5) + g;
    const unsigned sbase = (unsigned)__cvta_generic_to_shared(sm);

    const float* bias0 = bias + ((size_t)h * NT + q0 + r0) * NT;

    // prefetch bias tile 0 into L2 before anything else
    pf_l2(bias0 + 16 * c);
    pf_l2(bias0 + (size_t)8 * NT + 16 * c);

    // Q fragments in registers (gmem already tf32-rounded; *0.125 exact)
    float qa[8][4];
    {
        const float* q0p = Q + (size_t)(q0 + r0) * DM + h * HD;
        const float* q1p = q0p + 8 * DM;
#pragma unroll
        for (int k8 = 0; k8 < 8; k8++) {
            qa[k8][0] = q0p[8 * k8 + c]     * 0.125f;
            qa[k8][1] = q1p[8 * k8 + c]     * 0.125f;
            qa[k8][2] = q0p[8 * k8 + c + 4] * 0.125f;
            qa[k8][3] = q1p[8 * k8 + c + 4] * 0.125f;
        }
    }

    float o[8][4];
#pragma unroll
    for (int j = 0; j < 8; j++)
#pragma unroll
        for (int r = 0; r < 4; r++) o[j][r] = 0.f;
    float mr0 = -1e30f, mr1 = -1e30f, lr0 = 0.f, lr1 = 0.f;

    const float* kbase = Kpk + (size_t)h * NT * 64;
    const float* vbase = Vpk + (size_t)h * NT * 64;

    // stage tiles 0 and 1 (each tile: 16KB K + 16KB V, contiguous)
#pragma unroll
    for (int b = 0; b < 2; b++) {
        const char* ks = (const char*)(kbase + (size_t)b * 4096);
        const char* vs = (const char*)(vbase + (size_t)b * 4096);
#pragma unroll
        for (int i = 0; i < 4; i++) {
            cpa16(sbase + b * 16384 + tid * 16 + i * 4096, ks + tid * 16 + i * 4096);
            cpa16(sbase + 49152 + b * 16384 + tid * 16 + i * 4096, vs + tid * 16 + i * 4096);
        }
        asm volatile("cp.async.commit_group;" ::: "memory");
    }

    const int l0 = (g << 2) | (c >> 1);   // shuffle source lanes for P->A
    const int l1 = l0 + 2;
    const bool oddc = (c & 1);

    for (int t = 0; t < NT / 64; t++) {
        const int buf = t % 3;
        if (t < NT / 64 - 1) {
            asm volatile("cp.async.wait_group 1;" ::: "memory");
        } else {
            asm volatile("cp.async.wait_group 0;" ::: "memory");
        }
        __syncthreads();   // tile t visible AND all warps done with tile t-1

        if (t + 2 < NT / 64) {   // stage tile t+2 into buffer (t+2)%3
            const int b2 = (t + 2) % 3;
            const char* ks = (const char*)(kbase + (size_t)(t + 2) * 4096);
            const char* vs = (const char*)(vbase + (size_t)(t + 2) * 4096);
#pragma unroll
            for (int i = 0; i < 4; i++) {
                cpa16(sbase + b2 * 16384 + tid * 16 + i * 4096, ks + tid * 16 + i * 4096);
                cpa16(sbase + 49152 + b2 * 16384 + tid * 16 + i * 4096, vs + tid * 16 + i * 4096);
            }
            asm volatile("cp.async.commit_group;" ::: "memory");
        }

        const float* Ksb = sm + buf * 4096;
        const float* Vsb = sm + 12288 + buf * 4096;

        // ---- S = Q@K^T + bias (bias preloaded into accumulators) ----------
        float s[8][4];
        const float* bp = bias0 + t * 64;
#pragma unroll
        for (int j = 0; j < 8; j++) {
            float2 b0 = __ldcs((const float2*)(bp + 8 * j + 2 * c));
            float2 b1 = __ldcs((const float2*)(bp + (size_t)8 * NT + 8 * j + 2 * c));
            s[j][0] = b0.x; s[j][1] = b0.y; s[j][2] = b1.x; s[j][3] = b1.y;
        }
#pragma unroll
        for (int k8 = 0; k8 < 8; k8++) {
#pragma unroll
            for (int j = 0; j < 8; j++) {
                float2 kb = *(const float2*)&Ksb[k8 * 512 + (8 * j + g) * 8 + 2 * c];
                mma8(s[j], qa[k8][0], qa[k8][1], qa[k8][2], qa[k8][3], kb.x, kb.y);
            }
        }

        // prefetch next tile's bias into L2 while this tile computes
        if (t + 1 < NT / 64) {
            pf_l2(bp + 64 + 16 * c);
            pf_l2(bp + (size_t)8 * NT + 64 + 16 * c);
        }

        // ---- online softmax (rows r0 / r0+8, reduce over 4-lane c-group) --
        float rm0 = -1e30f, rm1 = -1e30f;
#pragma unroll
        for (int j = 0; j < 8; j++) {
            rm0 = fmaxf(rm0, fmaxf(s[j][0], s[j][1]));
            rm1 = fmaxf(rm1, fmaxf(s[j][2], s[j][3]));
        }
        rm0 = fmaxf(rm0, __shfl_xor_sync(0xffffffffu, rm0, 1));
        rm0 = fmaxf(rm0, __shfl_xor_sync(0xffffffffu, rm0, 2));
        rm1 = fmaxf(rm1, __shfl_xor_sync(0xffffffffu, rm1, 1));
        rm1 = fmaxf(rm1, __shfl_xor_sync(0xffffffffu, rm1, 2));

        // warp-uniform skip: only rescale when some row's max actually moved
        if (__any_sync(0xffffffffu, (rm0 > mr0) || (rm1 > mr1))) {
            float mn0 = fmaxf(mr0, rm0), mn1 = fmaxf(mr1, rm1);
            float corr0 = fast_exp(mr0 - mn0), corr1 = fast_exp(mr1 - mn1);
            mr0 = mn0; mr1 = mn1;
            lr0 *= corr0; lr1 *= corr1;
#pragma unroll
            for (int j = 0; j < 8; j++) {
                o[j][0] *= corr0; o[j][1] *= corr0;
                o[j][2] *= corr1; o[j][3] *= corr1;
            }
        }

        float sum0 = 0.f, sum1 = 0.f;
#pragma unroll
        for (int j = 0; j < 8; j++) {
            s[j][0] = f2tf(fast_exp(s[j][0] - mr0));
            s[j][1] = f2tf(fast_exp(s[j][1] - mr0));
            s[j][2] = f2tf(fast_exp(s[j][2] - mr1));
            s[j][3] = f2tf(fast_exp(s[j][3] - mr1));
            sum0 += s[j][0] + s[j][1];
            sum1 += s[j][2] + s[j][3];
        }
        sum0 += __shfl_xor_sync(0xffffffffu, sum0, 1);
        sum0 += __shfl_xor_sync(0xffffffffu, sum0, 2);
        sum1 += __shfl_xor_sync(0xffffffffu, sum1, 1);
        sum1 += __shfl_xor_sync(0xffffffffu, sum1, 2);
        lr0 += sum0;
        lr1 += sum1;

        // ---- O += P @ V : P permuted to A-fragments via shuffles ----------
#pragma unroll
        for (int t8 = 0; t8 < 8; t8++) {
            float v00 = __shfl_sync(0xffffffffu, s[t8][0], l0);
            float v01 = __shfl_sync(0xffffffffu, s[t8][1], l0);
            float v10 = __shfl_sync(0xffffffffu, s[t8][2], l0);
            float v11 = __shfl_sync(0xffffffffu, s[t8][3], l0);
            float w00 = __shfl_sync(0xffffffffu, s[t8][0], l1);
            float w01 = __shfl_sync(0xffffffffu, s[t8][1], l1);
            float w10 = __shfl_sync(0xffffffffu, s[t8][2], l1);
            float w11 = __shfl_sync(0xffffffffu, s[t8][3], l1);
            float a0 = oddc ? v01 : v00;
            float a1 = oddc ? v11 : v10;
            float a2 = oddc ? w01 : w00;
            float a3 = oddc ? w11 : w10;
#pragma unroll
            for (int j = 0; j < 8; j++) {
                float2 vb = *(const float2*)&Vsb[t8 * 512 + (8 * j + g) * 8 + 2 * c];
                mma8(o[j], a0, a1, a2, a3, vb.x, vb.y);
            }
        }
    }

    float inv0 = 1.0f / lr0, inv1 = 1.0f / lr1;
    const int grow0 = q0 + r0;
#pragma unroll
    for (int j = 0; j < 8; j++) {
        int col = h * HD + 8 * j + 2 * c;
        *(float2*)&O[(size_t)grow0 * DM + col] =
            make_float2(o[j][0] * inv0, o[j][1] * inv0);
        *(float2*)&O[(size_t)(grow0 + 8) * DM + col] =
            make_float2(o[j][2] * inv1, o[j][3] * inv1);
    }
}

// ---------------- fused residual + LayerNorm (one block per row) -----------
__global__ __launch_bounds__(128) void add_ln_kernel(
    const float* __restrict__ A, const float* __restrict__ B,
    const float* __restrict__ g, const float* __restrict__ be,
    float* __restrict__ out)
{
    __shared__ float red[8];
    const int row = blockIdx.x, tid = threadIdx.x;
    float4 a = *(const float4*)&A[(size_t)row * DM + tid * 4];
    float4 b = *(const float4*)&B[(size_t)row * DM + tid * 4];
    float v[4] = {a.x + b.x, a.y + b.y, a.z + b.z, a.w + b.w};

    float s = v[0] + v[1] + v[2] + v[3];
#pragma unroll
    for (int off = 16; off; off >>= 1) s += __shfl_xor_sync(0xffffffffu, s, off);
    if ((tid & 31) == 0) red[tid >> 5] = s;
    __syncthreads();
    float mu = (red[0] + red[1] + red[2] + red[3]) * (1.f / DM);

    float d[4]; float sq = 0.f;
#pragma unroll
    for (int i = 0; i < 4; i++) { d[i] = v[i] - mu; sq += d[i] * d[i]; }
#pragma unroll
    for (int off = 16; off; off >>= 1) sq += __shfl_xor_sync(0xffffffffu, sq, off);
    if ((tid & 31) == 0) red[4 + (tid >> 5)] = sq;
    __syncthreads();
    float inv = rsqrtf((red[4] + red[5] + red[6] + red[7]) * (1.f / DM) + 1e-5f);

    float4 gg = *(const float4*)&g[tid * 4];
    float4 bb = *(const float4*)&be[tid * 4];
    float4 r;
    r.x = d[0] * inv * gg.x + bb.x;
    r.y = d[1] * inv * gg.y + bb.y;
    r.z = d[2] * inv * gg.z + bb.z;
    r.w = d[3] * inv * gg.w + bb.w;
    *(float4*)&out[(size_t)row * DM + tid * 4] = r;
}

// ---------------- launch ----------------------------------------------------
extern "C" void kernel_launch(void* const* d_in, const int* in_sizes, int n_in,
                              void* d_out, int out_size)
{
    const float* x    = (const float*)d_in[0];
    const float* bias = (const float*)d_in[1];
    const float* Wq = (const float*)d_in[2];  const float* bq = (const float*)d_in[3];
    const float* Wk = (const float*)d_in[4];  const float* bk = (const float*)d_in[5];
    const float* Wv = (const float*)d_in[6];  const float* bv = (const float*)d_in[7];
    const float* Wo = (const float*)d_in[8];  const float* bo = (const float*)d_in[9];
    const float* g1 = (const float*)d_in[10]; const float* b1 = (const float*)d_in[11];
    const float* g2 = (const float*)d_in[12]; const float* b2 = (const float*)d_in[13];
    const float* W1 = (const float*)d_in[14]; const float* c1 = (const float*)d_in[15];
    const float* W2 = (const float*)d_in[16]; const float* c2 = (const float*)d_in[17];
    float* out = (float*)d_out;

    float *Qp, *Kp, *Vp, *attnp, *tmpp, *x1p, *hidp;
    cudaGetSymbolAddress((void**)&Qp,    g_Q);
    cudaGetSymbolAddress((void**)&Kp,    g_K);
    cudaGetSymbolAddress((void**)&Vp,    g_V);
    cudaGetSymbolAddress((void**)&attnp, g_attn);
    cudaGetSymbolAddress((void**)&tmpp,  g_tmp);
    cudaGetSymbolAddress((void**)&x1p,   g_x1);
    cudaGetSymbolAddress((void**)&hidp,  g_hid);

    const int ATTN_SMEM = 98304;   // 3x(16KB K + 16KB V)
    cudaFuncSetAttribute(attn_tc5, cudaFuncAttributeMaxDynamicSharedMemorySize, ATTN_SMEM);

    dim3 blk(256);
    dim3 gQKV(DM / 128, NT / 128, 3);
    dim3 gProj(DM / 128, NT / 128);
    dim3 gFF1(DFF / 128, NT / 128);

    gemm_qkv<<<gQKV, blk>>>(x, Wq, bq, Qp, Wk, bk, Kp, Wv, bv, Vp);

    attn_tc5<<<dim3(NT / 128, NH), blk, ATTN_SMEM>>>(Qp, Kp, Vp, bias, attnp);

    gemm_tc<0><<<gProj, blk>>>(attnp, Wo, bo, tmpp, NT, DM, DM);
    add_ln_kernel<<<NT, 128>>>(x, tmpp, g1, b1, x1p);

    gemm_tc<1><<<gFF1, blk>>>(x1p, W1, c1, hidp, NT, DFF, DM);
    gemm_tc<0><<<gProj, blk>>>(hidp, W2, c2, tmpp, NT, DM, DFF);
    add_ln_kernel<<<NT, 128>>>(x1p, tmpp, g2, b2, out);
}

// round 7
// speedup vs baseline: 4.8945x; 1.3902x over previous
#include <cuda_runtime.h>
#include <cuda_fp16.h>
#include <math.h>
#include <stdint.h>

#define NT  4096
#define DM  512
#define NH  8
#define HD  64
#define DFF 1024

// ---------------- scratch (static device globals; no allocations) ----------
__device__ __half g_Q[NT * DM];    // fp16, 0.125-prescaled, pk16-packed dims
__device__ __half g_K[NT * DM];    // fp16, tile-contiguous packed (khalf_idx)
__device__ __half g_V[NT * DM];    // fp16, tile-contiguous packed (vhalf_idx)
__device__ float  g_attn[NT * DM];
__device__ float  g_tmp[NT * DM];
__device__ float  g_x1[NT * DM];
__device__ float  g_hid[NT * DFF];
// transposed fp16 weights, pk16-packed along k (B operands)
__device__ __half g_WqT[DM * DM];
__device__ __half g_WkT[DM * DM];
__device__ __half g_WvT[DM * DM];
__device__ __half g_WoT[DM * DM];
__device__ __half g_W1T[DFF * DM];
__device__ __half g_W2T[DM * DFF];

// ---------------- helpers ---------------------------------------------------
// pk16: within each 16-element k group, order (0,1,8,9),(2,3,10,11),(4,5,12,13),(6,7,14,15)
__host__ __device__ __forceinline__ int ppos(int r) {
    return ((r & 7) >> 1) * 4 + ((r >> 3) & 1) * 2 + (r & 1);
}

__device__ __forceinline__ size_t khalf_idx(int h, int tok, int dim) {
    return (size_t)h * NT * 64 + (size_t)(tok >> 6) * 4096
         + (size_t)((dim >> 4) & 3) * 1024 + (tok & 63) * 16 + ppos(dim & 15);
}
__device__ __forceinline__ size_t vhalf_idx(int h, int tok, int n) {
    return (size_t)h * NT * 64 + (size_t)(tok >> 6) * 4096
         + (size_t)((tok >> 4) & 3) * 1024 + n * 16 + ppos(tok & 15);
}

__device__ __forceinline__ uint32_t h2u(float lo, float hi) {
    uint32_t r;
    asm("cvt.rn.f16x2.f32 %0, %1, %2;" : "=r"(r) : "f"(hi), "f"(lo));
    return r;
}

__device__ __forceinline__ void mma16(float d[4],
                                      uint32_t a0, uint32_t a1, uint32_t a2, uint32_t a3,
                                      uint32_t b0, uint32_t b1) {
    asm("mma.sync.aligned.m16n8k16.row.col.f32.f16.f16.f32 "
        "{%0,%1,%2,%3}, {%4,%5,%6,%7}, {%8,%9}, {%0,%1,%2,%3};"
        : "+f"(d[0]), "+f"(d[1]), "+f"(d[2]), "+f"(d[3])
        : "r"(a0), "r"(a1), "r"(a2), "r"(a3), "r"(b0), "r"(b1));
}

__device__ __forceinline__ void cpa16(unsigned dst, const void* src) {
    asm volatile("cp.async.cg.shared.global [%0], [%1], 16;" :: "r"(dst), "l"(src));
}
__device__ __forceinline__ void pf_l2(const void* p) {
    asm volatile("prefetch.global.L2 [%0];" :: "l"(p));
}

__device__ __forceinline__ float fast_exp(float x) {
    float y = x * 1.44269504089f;
    y = fmaxf(y, -100.0f);
    float t  = y + 12582912.0f;
    int   ni = __float_as_int(t) - 0x4B400000;
    float f  = y - (t - 12582912.0f);
    float p  = fmaf(f, 0.0013475782f, 0.0096788315f);
    p = fmaf(f, p, 0.0555072548f);
    p = fmaf(f, p, 0.2402211471f);
    p = fmaf(f, p, 0.6931471805f);
    p = fmaf(f, p, 1.0f);
    return __int_as_float(__float_as_int(p) + (ni << 23));
}

// ==================== fp16 GEMM mainloop ====================================
// 128x128 tile, BK=32, 8 warps (2x4), warp tile 64x32.
// smem: A[2][8KB] at 0/8192, B[2][8KB] at 16384/24576. Chunk layout per buf:
//   [kk(2)][row(128)][16 halves pk16-packed]   (chunk = 4096 B)
struct GemmCoreH {
    float acc[4][4][4];
    int tid, wid, lane, g, c, wm, wn;
    __device__ __forceinline__ void init(int tid_) {
        tid = tid_; wid = tid >> 5; lane = tid & 31;
        g = lane >> 2; c = lane & 3;
        wm = (wid >> 2) * 64; wn = (wid & 3) * 32;
#pragma unroll
        for (int t = 0; t < 4; t++)
#pragma unroll
            for (int j = 0; j < 4; j++)
#pragma unroll
                for (int r = 0; r < 4; r++) acc[t][j][r] = 0.f;
    }
    __device__ __forceinline__ void stageA(
        const float* __restrict__ A, int m0, int K, int k0,
        char* smc, unsigned abuf)
    {
#pragma unroll
        for (int i = 0; i < 4; i++) {
            int idx = i * 256 + tid;
            int row = idx >> 3, blk = idx & 7;
            float4 v = *(const float4*)&A[(size_t)(m0 + row) * K + k0 + blk * 4];
            int kk = blk >> 2, d = (blk * 4) & 15;
            char* dst = smc + abuf + kk * 4096 + row * 32;
            *(uint32_t*)(dst + ppos(d) * 2)     = h2u(v.x, v.y);
            *(uint32_t*)(dst + ppos(d + 2) * 2) = h2u(v.z, v.w);
        }
    }
    __device__ __forceinline__ void stageB(
        const __half* __restrict__ Bt, int n0, int K, int k0,
        unsigned sb, unsigned bbuf)
    {
#pragma unroll
        for (int i = 0; i < 2; i++) {
            int idx = i * 256 + tid;
            int n = idx >> 2, sub = idx & 3;
            int kk = sub >> 1, part = sub & 1;
            cpa16(sb + bbuf + kk * 4096 + n * 32 + part * 16,
                  Bt + (size_t)(n0 + n) * K + k0 + kk * 16 + part * 8);
        }
        asm volatile("cp.async.commit_group;" ::: "memory");
    }
    __device__ __forceinline__ void run(
        const float* __restrict__ A, const __half* __restrict__ Bt,
        int m0, int n0, int K, char* smc, unsigned sb)
    {
        stageB(Bt, n0, K, 0, sb, 16384u);
        stageA(A, m0, K, 0, smc, 0u);
        asm volatile("cp.async.wait_group 0;" ::: "memory");
        __syncthreads();

        const int nk = K >> 5;
        for (int kb = 0; kb < nk; kb++) {
            const unsigned cur = kb & 1;
            const bool more = (kb + 1 < nk);
            if (more) stageB(Bt, n0, K, (kb + 1) << 5, sb, 16384u + (cur ^ 1) * 8192u);

            const char* aB = smc + cur * 8192u;
            const char* bB = smc + 16384u + cur * 8192u;
#pragma unroll
            for (int kk = 0; kk < 2; kk++) {
                uint32_t af[4][4];
#pragma unroll
                for (int t = 0; t < 4; t++) {
                    uint2 r0 = *(const uint2*)(aB + kk * 4096 + (wm + 16 * t + g) * 32 + c * 8);
                    uint2 r1 = *(const uint2*)(aB + kk * 4096 + (wm + 16 * t + g + 8) * 32 + c * 8);
                    af[t][0] = r0.x; af[t][1] = r1.x; af[t][2] = r0.y; af[t][3] = r1.y;
                }
#pragma unroll
                for (int j = 0; j < 4; j++) {
                    uint2 bv = *(const uint2*)(bB + kk * 4096 + (wn + 8 * j + g) * 32 + c * 8);
#pragma unroll
                    for (int t = 0; t < 4; t++)
                        mma16(acc[t][j], af[t][0], af[t][1], af[t][2], af[t][3], bv.x, bv.y);
                }
            }
            if (more) {
                stageA(A, m0, K, (kb + 1) << 5, smc, (cur ^ 1) * 8192u);
                asm volatile("cp.async.wait_group 0;" ::: "memory");
            }
            __syncthreads();
        }
    }
};

// ---------------- generic GEMM (modes 0 plain / 1 relu), fp32 out ----------
template <int MODE>
__global__ __launch_bounds__(256, 2) void gemm_h(
    const float* __restrict__ A, const __half* __restrict__ Bt,
    const float* __restrict__ bias, float* __restrict__ C, int N, int K)
{
    __shared__ __align__(16) char smem[32768];
    GemmCoreH gc; gc.init(threadIdx.x);
    const int m0 = blockIdx.y * 128, n0 = blockIdx.x * 128;
    gc.run(A, Bt, m0, n0, K, smem, (unsigned)__cvta_generic_to_shared(smem));

#pragma unroll
    for (int t = 0; t < 4; t++) {
        int row0 = m0 + gc.wm + 16 * t + gc.g;
#pragma unroll
        for (int j = 0; j < 4; j++) {
            int col = n0 + gc.wn + 8 * j + 2 * gc.c;
            float2 bv = *(const float2*)&bias[col];
            float v00 = gc.acc[t][j][0] + bv.x, v01 = gc.acc[t][j][1] + bv.y;
            float v10 = gc.acc[t][j][2] + bv.x, v11 = gc.acc[t][j][3] + bv.y;
            if (MODE == 1) {
                v00 = fmaxf(v00, 0.f); v01 = fmaxf(v01, 0.f);
                v10 = fmaxf(v10, 0.f); v11 = fmaxf(v11, 0.f);
            }
            *(float2*)&C[(size_t)row0 * N + col]       = make_float2(v00, v01);
            *(float2*)&C[(size_t)(row0 + 8) * N + col] = make_float2(v10, v11);
        }
    }
}

// ---------------- fused QKV GEMM: z selects projection + output packing ----
__global__ __launch_bounds__(256, 2) void gemm_qkv(
    const float* __restrict__ x,
    const __half* __restrict__ WqT, const float* __restrict__ bq, __half* __restrict__ Qo,
    const __half* __restrict__ WkT, const float* __restrict__ bk, __half* __restrict__ Ko,
    const __half* __restrict__ WvT, const float* __restrict__ bv, __half* __restrict__ Vo)
{
    __shared__ __align__(16) char smem[32768];
    const int z = blockIdx.z;
    const __half* Bt   = (z == 0) ? WqT : (z == 1) ? WkT : WvT;
    const float*  bias = (z == 0) ? bq  : (z == 1) ? bk  : bv;

    GemmCoreH gc; gc.init(threadIdx.x);
    const int m0 = blockIdx.y * 128, n0 = blockIdx.x * 128;
    gc.run(x, Bt, m0, n0, DM, smem, (unsigned)__cvta_generic_to_shared(smem));

#pragma unroll
    for (int t = 0; t < 4; t++) {
        int row0 = m0 + gc.wm + 16 * t + gc.g;
#pragma unroll
        for (int j = 0; j < 4; j++) {
            int col = n0 + gc.wn + 8 * j + 2 * gc.c;
            float2 bvv = *(const float2*)&bias[col];
            float v00 = gc.acc[t][j][0] + bvv.x, v01 = gc.acc[t][j][1] + bvv.y;
            float v10 = gc.acc[t][j][2] + bvv.x, v11 = gc.acc[t][j][3] + bvv.y;
            if (z == 0) {   // Q: 0.125-prescaled, pk16-packed rows
                size_t p0 = (size_t)row0 * DM + (col & ~15) + ppos(col & 15);
                size_t p1 = p0 + (size_t)8 * DM;
                *(uint32_t*)&Qo[p0] = h2u(v00 * 0.125f, v01 * 0.125f);
                *(uint32_t*)&Qo[p1] = h2u(v10 * 0.125f, v11 * 0.125f);
            } else if (z == 1) {  // K packed: dims adjacent -> half2 stores
                int h = col >> 6, dl = col & 63;
                *(uint32_t*)&Ko[khalf_idx(h, row0,     dl)] = h2u(v00, v01);
                *(uint32_t*)&Ko[khalf_idx(h, row0 + 8, dl)] = h2u(v10, v11);
            } else {              // V packed: tokens packed -> scalar stores
                int h = col >> 6, dl = col & 63;
                Vo[vhalf_idx(h, row0,     dl)]     = __float2half_rn(v00);
                Vo[vhalf_idx(h, row0,     dl + 1)] = __float2half_rn(v01);
                Vo[vhalf_idx(h, row0 + 8, dl)]     = __float2half_rn(v10);
                Vo[vhalf_idx(h, row0 + 8, dl + 1)] = __float2half_rn(v11);
            }
        }
    }
}

// ---------------- weight transpose: in[K][N] f32 -> out[N][K] fp16 packed --
__global__ void __launch_bounds__(256) transpose_w(
    const float* __restrict__ in, __half* __restrict__ out, int K, int N)
{
    __shared__ float t[32][33];
    const int n0 = blockIdx.x * 32, k0 = blockIdx.y * 32;
    const int tx = threadIdx.x & 31, ty = threadIdx.x >> 5;
#pragma unroll
    for (int i = 0; i < 4; i++)
        t[ty + 8 * i][tx] = in[(size_t)(k0 + ty + 8 * i) * N + n0 + tx];
    __syncthreads();
    if (tx < 16) {
#pragma unroll
        for (int i = 0; i < 4; i++) {
            int n = ty + 8 * i;
            int kl = 2 * tx;
            int pos = (kl & ~15) + ppos(kl & 15);
            *(uint32_t*)&out[(size_t)(n0 + n) * K + k0 + pos] =
                h2u(t[kl][n], t[kl + 1][n]);
        }
    }
}

// ---------------- fp16 tensor-core flash attention --------------------------
// 128 Q-rows per CTA, 64-token KV tiles, triple-buffered cp.async (8KB K +
// 8KB V per tile), P C-fragments map DIRECTLY to PV A-fragments (no shuffles).
// smem: K[3][8192B] at 0, V[3][8192B] at 24576. Total 49152 B.
__global__ __launch_bounds__(256, 2) void attn_h(
    const __half* __restrict__ Q, const __half* __restrict__ Kpk,
    const __half* __restrict__ Vpk, const float* __restrict__ bias,
    float* __restrict__ O)
{
    extern __shared__ char smc[];
    const int tid = threadIdx.x;
    const int lane = tid & 31;
    const int g = lane >> 2, c = lane & 3;
    const int h = blockIdx.y;
    const int q0 = blockIdx.x * 128;
    const int r0 = 16 * (tid >> 5) + g;
    const unsigned sbase = (unsigned)__cvta_generic_to_shared(smc);

    const float* bias0 = bias + ((size_t)h * NT + q0 + r0) * NT;
    pf_l2(bias0 + 16 * c);
    pf_l2(bias0 + (size_t)8 * NT + 16 * c);

    // Q fragments (4 k16-chunks x 4 half2 regs), prescaled+packed in gmem
    uint32_t qa[4][4];
    {
        const char* qp0 = (const char*)(Q + (size_t)(q0 + r0) * DM + h * HD);
        const char* qp1 = qp0 + (size_t)8 * DM * 2;
#pragma unroll
        for (int kk = 0; kk < 4; kk++) {
            uint2 t0 = *(const uint2*)(qp0 + kk * 32 + c * 8);
            uint2 t1 = *(const uint2*)(qp1 + kk * 32 + c * 8);
            qa[kk][0] = t0.x; qa[kk][1] = t1.x; qa[kk][2] = t0.y; qa[kk][3] = t1.y;
        }
    }

    float o[8][4];
#pragma unroll
    for (int j = 0; j < 8; j++)
#pragma unroll
        for (int r = 0; r < 4; r++) o[j][r] = 0.f;
    float mr0 = -1e30f, mr1 = -1e30f, lr0 = 0.f, lr1 = 0.f;

    const __half* kbase = Kpk + (size_t)h * NT * 64;
    const __half* vbase = Vpk + (size_t)h * NT * 64;

    // stage tiles 0,1 (each: 8KB K + 8KB V, contiguous in gmem)
#pragma unroll
    for (int b = 0; b < 2; b++) {
        const char* ks = (const char*)(kbase + (size_t)b * 4096);
        const char* vs = (const char*)(vbase + (size_t)b * 4096);
        cpa16(sbase + b * 8192 + tid * 16,            ks + tid * 16);
        cpa16(sbase + b * 8192 + 4096 + tid * 16,     ks + 4096 + tid * 16);
        cpa16(sbase + 24576 + b * 8192 + tid * 16,    vs + tid * 16);
        cpa16(sbase + 24576 + b * 8192 + 4096 + tid * 16, vs + 4096 + tid * 16);
        asm volatile("cp.async.commit_group;" ::: "memory");
    }

    for (int t = 0; t < NT / 64; t++) {
        const int buf = t % 3;
        if (t < NT / 64 - 1) {
            asm volatile("cp.async.wait_group 1;" ::: "memory");
        } else {
            asm volatile("cp.async.wait_group 0;" ::: "memory");
        }
        __syncthreads();

        if (t + 2 < NT / 64) {
            const int b2 = (t + 2) % 3;
            const char* ks = (const char*)(kbase + (size_t)(t + 2) * 4096);
            const char* vs = (const char*)(vbase + (size_t)(t + 2) * 4096);
            cpa16(sbase + b2 * 8192 + tid * 16,            ks + tid * 16);
            cpa16(sbase + b2 * 8192 + 4096 + tid * 16,     ks + 4096 + tid * 16);
            cpa16(sbase + 24576 + b2 * 8192 + tid * 16,    vs + tid * 16);
            cpa16(sbase + 24576 + b2 * 8192 + 4096 + tid * 16, vs + 4096 + tid * 16);
            asm volatile("cp.async.commit_group;" ::: "memory");
        }

        const char* Ksb = smc + buf * 8192;
        const char* Vsb = smc + 24576 + buf * 8192;

        // ---- S = Q@K^T + bias (bias preloaded into accumulators) ----------
        float s[8][4];
        const float* bp = bias0 + t * 64;
#pragma unroll
        for (int j = 0; j < 8; j++) {
            float2 b0 = __ldcs((const float2*)(bp + 8 * j + 2 * c));
            float2 b1 = __ldcs((const float2*)(bp + (size_t)8 * NT + 8 * j + 2 * c));
            s[j][0] = b0.x; s[j][1] = b0.y; s[j][2] = b1.x; s[j][3] = b1.y;
        }
#pragma unroll
        for (int kk = 0; kk < 4; kk++) {
#pragma unroll
            for (int j = 0; j < 8; j++) {
                uint2 kb = *(const uint2*)(Ksb + kk * 2048 + (8 * j + g) * 32 + c * 8);
                mma16(s[j], qa[kk][0], qa[kk][1], qa[kk][2], qa[kk][3], kb.x, kb.y);
            }
        }

        if (t + 1 < NT / 64) {
            pf_l2(bp + 64 + 16 * c);
            pf_l2(bp + (size_t)8 * NT + 64 + 16 * c);
        }

        // ---- online softmax (rows r0 / r0+8, reduce over 4-lane c-group) --
        float rm0 = -1e30f, rm1 = -1e30f;
#pragma unroll
        for (int j = 0; j < 8; j++) {
            rm0 = fmaxf(rm0, fmaxf(s[j][0], s[j][1]));
            rm1 = fmaxf(rm1, fmaxf(s[j][2], s[j][3]));
        }
        rm0 = fmaxf(rm0, __shfl_xor_sync(0xffffffffu, rm0, 1));
        rm0 = fmaxf(rm0, __shfl_xor_sync(0xffffffffu, rm0, 2));
        rm1 = fmaxf(rm1, __shfl_xor_sync(0xffffffffu, rm1, 1));
        rm1 = fmaxf(rm1, __shfl_xor_sync(0xffffffffu, rm1, 2));

        if (__any_sync(0xffffffffu, (rm0 > mr0) || (rm1 > mr1))) {
            float mn0 = fmaxf(mr0, rm0), mn1 = fmaxf(mr1, rm1);
            float corr0 = fast_exp(mr0 - mn0), corr1 = fast_exp(mr1 - mn1);
            mr0 = mn0; mr1 = mn1;
            lr0 *= corr0; lr1 *= corr1;
#pragma unroll
            for (int j = 0; j < 8; j++) {
                o[j][0] *= corr0; o[j][1] *= corr0;
                o[j][2] *= corr1; o[j][3] *= corr1;
            }
        }

        float sum0 = 0.f, sum1 = 0.f;
#pragma unroll
        for (int j = 0; j < 8; j++) {
            s[j][0] = fast_exp(s[j][0] - mr0);
            s[j][1] = fast_exp(s[j][1] - mr0);
            s[j][2] = fast_exp(s[j][2] - mr1);
            s[j][3] = fast_exp(s[j][3] - mr1);
            sum0 += s[j][0] + s[j][1];
            sum1 += s[j][2] + s[j][3];
        }
        sum0 += __shfl_xor_sync(0xffffffffu, sum0, 1);
        sum0 += __shfl_xor_sync(0xffffffffu, sum0, 2);
        sum1 += __shfl_xor_sync(0xffffffffu, sum1, 1);
        sum1 += __shfl_xor_sync(0xffffffffu, sum1, 2);
        lr0 += sum0;
        lr1 += sum1;

        // ---- O += P @ V : C-fragments ARE the A-fragments (no shuffles) ---
#pragma unroll
        for (int tk = 0; tk < 4; tk++) {
            uint32_t a0 = h2u(s[2 * tk][0],     s[2 * tk][1]);
            uint32_t a1 = h2u(s[2 * tk][2],     s[2 * tk][3]);
            uint32_t a2 = h2u(s[2 * tk + 1][0], s[2 * tk + 1][1]);
            uint32_t a3 = h2u(s[2 * tk + 1][2], s[2 * tk + 1][3]);
#pragma unroll
            for (int j = 0; j < 8; j++) {
                uint2 vb = *(const uint2*)(Vsb + tk * 2048 + (8 * j + g) * 32 + c * 8);
                mma16(o[j], a0, a1, a2, a3, vb.x, vb.y);
            }
        }
    }

    float inv0 = 1.0f / lr0, inv1 = 1.0f / lr1;
    const int grow0 = q0 + r0;
#pragma unroll
    for (int j = 0; j < 8; j++) {
        int col = h * HD + 8 * j + 2 * c;
        *(float2*)&O[(size_t)grow0 * DM + col] =
            make_float2(o[j][0] * inv0, o[j][1] * inv0);
        *(float2*)&O[(size_t)(grow0 + 8) * DM + col] =
            make_float2(o[j][2] * inv1, o[j][3] * inv1);
    }
}

// ---------------- fused residual + LayerNorm --------------------------------
__global__ __launch_bounds__(128) void add_ln_kernel(
    const float* __restrict__ A, const float* __restrict__ B,
    const float* __restrict__ g, const float* __restrict__ be,
    float* __restrict__ out)
{
    __shared__ float red[8];
    const int row = blockIdx.x, tid = threadIdx.x;
    float4 a = *(const float4*)&A[(size_t)row * DM + tid * 4];
    float4 b = *(const float4*)&B[(size_t)row * DM + tid * 4];
    float v[4] = {a.x + b.x, a.y + b.y, a.z + b.z, a.w + b.w};

    float s = v[0] + v[1] + v[2] + v[3];
#pragma unroll
    for (int off = 16; off; off >>= 1) s += __shfl_xor_sync(0xffffffffu, s, off);
    if ((tid & 31) == 0) red[tid >> 5] = s;
    __syncthreads();
    float mu = (red[0] + red[1] + red[2] + red[3]) * (1.f / DM);

    float d[4]; float sq = 0.f;
#pragma unroll
    for (int i = 0; i < 4; i++) { d[i] = v[i] - mu; sq += d[i] * d[i]; }
#pragma unroll
    for (int off = 16; off; off >>= 1) sq += __shfl_xor_sync(0xffffffffu, sq, off);
    if ((tid & 31) == 0) red[4 + (tid >> 5)] = sq;
    __syncthreads();
    float inv = rsqrtf((red[4] + red[5] + red[6] + red[7]) * (1.f / DM) + 1e-5f);

    float4 gg = *(const float4*)&g[tid * 4];
    float4 bb = *(const float4*)&be[tid * 4];
    float4 r;
    r.x = d[0] * inv * gg.x + bb.x;
    r.y = d[1] * inv * gg.y + bb.y;
    r.z = d[2] * inv * gg.z + bb.z;
    r.w = d[3] * inv * gg.w + bb.w;
    *(float4*)&out[(size_t)row * DM + tid * 4] = r;
}

// ---------------- launch ----------------------------------------------------
extern "C" void kernel_launch(void* const* d_in, const int* in_sizes, int n_in,
                              void* d_out, int out_size)
{
    const float* x    = (const float*)d_in[0];
    const float* bias = (const float*)d_in[1];
    const float* Wq = (const float*)d_in[2];  const float* bq = (const float*)d_in[3];
    const float* Wk = (const float*)d_in[4];  const float* bk = (const float*)d_in[5];
    const float* Wv = (const float*)d_in[6];  const float* bv = (const float*)d_in[7];
    const float* Wo = (const float*)d_in[8];  const float* bo = (const float*)d_in[9];
    const float* g1 = (const float*)d_in[10]; const float* b1 = (const float*)d_in[11];
    const float* g2 = (const float*)d_in[12]; const float* b2 = (const float*)d_in[13];
    const float* W1 = (const float*)d_in[14]; const float* c1 = (const float*)d_in[15];
    const float* W2 = (const float*)d_in[16]; const float* c2 = (const float*)d_in[17];
    float* out = (float*)d_out;

    __half *Qp, *Kp, *Vp, *WqT, *WkT, *WvT, *WoT, *W1T, *W2T;
    float *attnp, *tmpp, *x1p, *hidp;
    cudaGetSymbolAddress((void**)&Qp,    g_Q);
    cudaGetSymbolAddress((void**)&Kp,    g_K);
    cudaGetSymbolAddress((void**)&Vp,    g_V);
    cudaGetSymbolAddress((void**)&attnp, g_attn);
    cudaGetSymbolAddress((void**)&tmpp,  g_tmp);
    cudaGetSymbolAddress((void**)&x1p,   g_x1);
    cudaGetSymbolAddress((void**)&hidp,  g_hid);
    cudaGetSymbolAddress((void**)&WqT,   g_WqT);
    cudaGetSymbolAddress((void**)&WkT,   g_WkT);
    cudaGetSymbolAddress((void**)&WvT,   g_WvT);
    cudaGetSymbolAddress((void**)&WoT,   g_WoT);
    cudaGetSymbolAddress((void**)&W1T,   g_W1T);
    cudaGetSymbolAddress((void**)&W2T,   g_W2T);

    const int ATTN_SMEM = 49152;
    cudaFuncSetAttribute(attn_h, cudaFuncAttributeMaxDynamicSharedMemorySize, ATTN_SMEM);

    // pre-transpose + fp16-pack weights (B operands)
    transpose_w<<<dim3(DM / 32,  DM / 32),  256>>>(Wq, WqT, DM, DM);
    transpose_w<<<dim3(DM / 32,  DM / 32),  256>>>(Wk, WkT, DM, DM);
    transpose_w<<<dim3(DM / 32,  DM / 32),  256>>>(Wv, WvT, DM, DM);
    transpose_w<<<dim3(DM / 32,  DM / 32),  256>>>(Wo, WoT, DM, DM);
    transpose_w<<<dim3(DFF / 32, DM / 32),  256>>>(W1, W1T, DM, DFF);
    transpose_w<<<dim3(DM / 32,  DFF / 32), 256>>>(W2, W2T, DFF, DM);

    dim3 blk(256);
    gemm_qkv<<<dim3(DM / 128, NT / 128, 3), blk>>>(
        x, WqT, bq, Qp, WkT, bk, Kp, WvT, bv, Vp);

    attn_h<<<dim3(NT / 128, NH), blk, ATTN_SMEM>>>(Qp, Kp, Vp, bias, attnp);

    gemm_h<0><<<dim3(DM / 128, NT / 128), blk>>>(attnp, WoT, bo, tmpp, DM, DM);
    add_ln_kernel<<<NT, 128>>>(x, tmpp, g1, b1, x1p);

    gemm_h<1><<<dim3(DFF / 128, NT / 128), blk>>>(x1p, W1T, c1, hidp, DFF, DM);
    gemm_h<0><<<dim3(DM / 128, NT / 128), blk>>>(hidp, W2T, c2, tmpp, DM, DFF);
    add_ln_kernel<<<NT, 128>>>(x1p, tmpp, g2, b2, out);
}

// round 8
// speedup vs baseline: 5.4684x; 1.1173x over previous
#include <cuda_runtime.h>
#include <cuda_fp16.h>
#include <math.h>
#include <stdint.h>

#define NT  4096
#define DM  512
#define NH  8
#define HD  64
#define DFF 1024

// ---------------- scratch (static device globals; no allocations) ----------
__device__ __half g_Q[NT * DM];    // fp16, 0.125-prescaled, pk16-packed dims
__device__ __half g_K[NT * DM];    // fp16, tile-contiguous packed (khalf_idx)
__device__ __half g_V[NT * DM];    // fp16, tile-contiguous packed (vhalf_idx)
__device__ float  g_attn[NT * DM];
__device__ float  g_tmp[NT * DM];
__device__ float  g_x1[NT * DM];
__device__ float  g_hid[NT * DFF];
// transposed fp16 weights, pk16-packed along k (B operands)
__device__ __half g_WqT[DM * DM];
__device__ __half g_WkT[DM * DM];
__device__ __half g_WvT[DM * DM];
__device__ __half g_WoT[DM * DM];
__device__ __half g_W1T[DFF * DM];
__device__ __half g_W2T[DM * DFF];

// ---------------- helpers ---------------------------------------------------
// pk16: within each 16-element k group, order (0,1,8,9),(2,3,10,11),(4,5,12,13),(6,7,14,15)
__host__ __device__ __forceinline__ int ppos(int r) {
    return ((r & 7) >> 1) * 4 + ((r >> 3) & 1) * 2 + (r & 1);
}

// K attn layout: per head, per 64-token tile (4096 halves):
//   token row (64 halves) = [kkp^(tok&1) (2 blocks of 32)][c(4)][kkl(2)][q(4)]
__device__ __forceinline__ size_t khalf_idx(int h, int tok, int dim) {
    int tl = tok & 63;
    int r = dim & 15;
    int c = (r >> 1) & 3, q = ((r >> 3) & 1) * 2 + (r & 1);
    int kkl = (dim >> 4) & 1, kkp = (dim >> 5) & 1;
    return (size_t)h * NT * 64 + (size_t)(tok >> 6) * 4096
         + tl * 64 + ((kkp ^ (tl & 1)) << 5) + c * 8 + kkl * 4 + q;
}
// V attn layout: per head, per 64-token tile: n row (64 halves) =
//   [tkp^(n&1) (2 blocks of 32)][c(4)][tkl(2)][q(4)] over 64 tokens
__device__ __forceinline__ size_t vhalf_idx(int h, int tok, int n) {
    int r = tok & 15;
    int c = (r >> 1) & 3, q = ((r >> 3) & 1) * 2 + (r & 1);
    int tkl = (tok >> 4) & 1, tkp = (tok >> 5) & 1;
    return (size_t)h * NT * 64 + (size_t)(tok >> 6) * 4096
         + n * 64 + ((tkp ^ (n & 1)) << 5) + c * 8 + tkl * 4 + q;
}

__device__ __forceinline__ uint32_t h2u(float lo, float hi) {
    uint32_t r;
    asm("cvt.rn.f16x2.f32 %0, %1, %2;" : "=r"(r) : "f"(hi), "f"(lo));
    return r;
}

__device__ __forceinline__ void mma16(float d[4],
                                      uint32_t a0, uint32_t a1, uint32_t a2, uint32_t a3,
                                      uint32_t b0, uint32_t b1) {
    asm("mma.sync.aligned.m16n8k16.row.col.f32.f16.f16.f32 "
        "{%0,%1,%2,%3}, {%4,%5,%6,%7}, {%8,%9}, {%0,%1,%2,%3};"
        : "+f"(d[0]), "+f"(d[1]), "+f"(d[2]), "+f"(d[3])
        : "r"(a0), "r"(a1), "r"(a2), "r"(a3), "r"(b0), "r"(b1));
}

__device__ __forceinline__ void cpa16(unsigned dst, const void* src) {
    asm volatile("cp.async.cg.shared.global [%0], [%1], 16;" :: "r"(dst), "l"(src));
}
__device__ __forceinline__ void pf_l2(const void* p) {
    asm volatile("prefetch.global.L2 [%0];" :: "l"(p));
}

// MUFU-based exp for x <= 0: one FMA-pipe mul + one MUFU. rel err ~1e-6.
__device__ __forceinline__ float fexp(float x) {
    float r;
    float y = x * 1.4426950408889634f;
    asm("ex2.approx.f32 %0, %1;" : "=f"(r) : "f"(y));
    return r;
}

// ==================== fp16 GEMM mainloop ====================================
// 128x128 tile, BK=32, 8 warps (2x4), warp tile 64x32.
struct GemmCoreH {
    float acc[4][4][4];
    int tid, wid, lane, g, c, wm, wn;
    __device__ __forceinline__ void init(int tid_) {
        tid = tid_; wid = tid >> 5; lane = tid & 31;
        g = lane >> 2; c = lane & 3;
        wm = (wid >> 2) * 64; wn = (wid & 3) * 32;
#pragma unroll
        for (int t = 0; t < 4; t++)
#pragma unroll
            for (int j = 0; j < 4; j++)
#pragma unroll
                for (int r = 0; r < 4; r++) acc[t][j][r] = 0.f;
    }
    __device__ __forceinline__ void stageA(
        const float* __restrict__ A, int m0, int K, int k0,
        char* smc, unsigned abuf)
    {
#pragma unroll
        for (int i = 0; i < 4; i++) {
            int idx = i * 256 + tid;
            int row = idx >> 3, blk = idx & 7;
            float4 v = *(const float4*)&A[(size_t)(m0 + row) * K + k0 + blk * 4];
            int kk = blk >> 2, d = (blk * 4) & 15;
            char* dst = smc + abuf + kk * 4096 + row * 32;
            *(uint32_t*)(dst + ppos(d) * 2)     = h2u(v.x, v.y);
            *(uint32_t*)(dst + ppos(d + 2) * 2) = h2u(v.z, v.w);
        }
    }
    __device__ __forceinline__ void stageB(
        const __half* __restrict__ Bt, int n0, int K, int k0,
        unsigned sb, unsigned bbuf)
    {
#pragma unroll
        for (int i = 0; i < 2; i++) {
            int idx = i * 256 + tid;
            int n = idx >> 2, sub = idx & 3;
            int kk = sub >> 1, part = sub & 1;
            cpa16(sb + bbuf + kk * 4096 + n * 32 + part * 16,
                  Bt + (size_t)(n0 + n) * K + k0 + kk * 16 + part * 8);
        }
        asm volatile("cp.async.commit_group;" ::: "memory");
    }
    __device__ __forceinline__ void run(
        const float* __restrict__ A, const __half* __restrict__ Bt,
        int m0, int n0, int K, char* smc, unsigned sb)
    {
        stageB(Bt, n0, K, 0, sb, 16384u);
        stageA(A, m0, K, 0, smc, 0u);
        asm volatile("cp.async.wait_group 0;" ::: "memory");
        __syncthreads();

        const int nk = K >> 5;
        for (int kb = 0; kb < nk; kb++) {
            const unsigned cur = kb & 1;
            const bool more = (kb + 1 < nk);
            if (more) stageB(Bt, n0, K, (kb + 1) << 5, sb, 16384u + (cur ^ 1) * 8192u);

            const char* aB = smc + cur * 8192u;
            const char* bB = smc + 16384u + cur * 8192u;
#pragma unroll
            for (int kk = 0; kk < 2; kk++) {
                uint32_t af[4][4];
#pragma unroll
                for (int t = 0; t < 4; t++) {
                    uint2 r0 = *(const uint2*)(aB + kk * 4096 + (wm + 16 * t + g) * 32 + c * 8);
                    uint2 r1 = *(const uint2*)(aB + kk * 4096 + (wm + 16 * t + g + 8) * 32 + c * 8);
                    af[t][0] = r0.x; af[t][1] = r1.x; af[t][2] = r0.y; af[t][3] = r1.y;
                }
#pragma unroll
                for (int j = 0; j < 4; j++) {
                    uint2 bv = *(const uint2*)(bB + kk * 4096 + (wn + 8 * j + g) * 32 + c * 8);
#pragma unroll
                    for (int t = 0; t < 4; t++)
                        mma16(acc[t][j], af[t][0], af[t][1], af[t][2], af[t][3], bv.x, bv.y);
                }
            }
            if (more) {
                stageA(A, m0, K, (kb + 1) << 5, smc, (cur ^ 1) * 8192u);
                asm volatile("cp.async.wait_group 0;" ::: "memory");
            }
            __syncthreads();
        }
    }
};

// ---------------- generic GEMM (modes 0 plain / 1 relu), fp32 out ----------
template <int MODE>
__global__ __launch_bounds__(256, 2) void gemm_h(
    const float* __restrict__ A, const __half* __restrict__ Bt,
    const float* __restrict__ bias, float* __restrict__ C, int N, int K)
{
    __shared__ __align__(16) char smem[32768];
    GemmCoreH gc; gc.init(threadIdx.x);
    const int m0 = blockIdx.y * 128, n0 = blockIdx.x * 128;
    gc.run(A, Bt, m0, n0, K, smem, (unsigned)__cvta_generic_to_shared(smem));

#pragma unroll
    for (int t = 0; t < 4; t++) {
        int row0 = m0 + gc.wm + 16 * t + gc.g;
#pragma unroll
        for (int j = 0; j < 4; j++) {
            int col = n0 + gc.wn + 8 * j + 2 * gc.c;
            float2 bv = *(const float2*)&bias[col];
            float v00 = gc.acc[t][j][0] + bv.x, v01 = gc.acc[t][j][1] + bv.y;
            float v10 = gc.acc[t][j][2] + bv.x, v11 = gc.acc[t][j][3] + bv.y;
            if (MODE == 1) {
                v00 = fmaxf(v00, 0.f); v01 = fmaxf(v01, 0.f);
                v10 = fmaxf(v10, 0.f); v11 = fmaxf(v11, 0.f);
            }
            *(float2*)&C[(size_t)row0 * N + col]       = make_float2(v00, v01);
            *(float2*)&C[(size_t)(row0 + 8) * N + col] = make_float2(v10, v11);
        }
    }
}

// ---------------- fused QKV GEMM: z selects projection + output packing ----
__global__ __launch_bounds__(256, 2) void gemm_qkv(
    const float* __restrict__ x,
    const __half* __restrict__ WqT, const float* __restrict__ bq, __half* __restrict__ Qo,
    const __half* __restrict__ WkT, const float* __restrict__ bk, __half* __restrict__ Ko,
    const __half* __restrict__ WvT, const float* __restrict__ bv, __half* __restrict__ Vo)
{
    __shared__ __align__(16) char smem[32768];
    const int z = blockIdx.z;
    const __half* Bt   = (z == 0) ? WqT : (z == 1) ? WkT : WvT;
    const float*  bias = (z == 0) ? bq  : (z == 1) ? bk  : bv;

    GemmCoreH gc; gc.init(threadIdx.x);
    const int m0 = blockIdx.y * 128, n0 = blockIdx.x * 128;
    gc.run(x, Bt, m0, n0, DM, smem, (unsigned)__cvta_generic_to_shared(smem));

#pragma unroll
    for (int t = 0; t < 4; t++) {
        int row0 = m0 + gc.wm + 16 * t + gc.g;
#pragma unroll
        for (int j = 0; j < 4; j++) {
            int col = n0 + gc.wn + 8 * j + 2 * gc.c;
            float2 bvv = *(const float2*)&bias[col];
            float v00 = gc.acc[t][j][0] + bvv.x, v01 = gc.acc[t][j][1] + bvv.y;
            float v10 = gc.acc[t][j][2] + bvv.x, v11 = gc.acc[t][j][3] + bvv.y;
            if (z == 0) {   // Q: 0.125-prescaled, pk16-packed rows
                size_t p0 = (size_t)row0 * DM + (col & ~15) + ppos(col & 15);
                size_t p1 = p0 + (size_t)8 * DM;
                *(uint32_t*)&Qo[p0] = h2u(v00 * 0.125f, v01 * 0.125f);
                *(uint32_t*)&Qo[p1] = h2u(v10 * 0.125f, v11 * 0.125f);
            } else if (z == 1) {  // K packed: dims adjacent -> half2 stores
                int h = col >> 6, dl = col & 63;
                *(uint32_t*)&Ko[khalf_idx(h, row0,     dl)] = h2u(v00, v01);
                *(uint32_t*)&Ko[khalf_idx(h, row0 + 8, dl)] = h2u(v10, v11);
            } else {              // V packed: tokens packed -> scalar stores
                int h = col >> 6, dl = col & 63;
                Vo[vhalf_idx(h, row0,     dl)]     = __float2half_rn(v00);
                Vo[vhalf_idx(h, row0,     dl + 1)] = __float2half_rn(v01);
                Vo[vhalf_idx(h, row0 + 8, dl)]     = __float2half_rn(v10);
                Vo[vhalf_idx(h, row0 + 8, dl + 1)] = __float2half_rn(v11);
            }
        }
    }
}

// ---------------- fused weight transpose: ONE launch for all 6 weights ------
__global__ void __launch_bounds__(256) transpose_all(
    const float* __restrict__ Wq, const float* __restrict__ Wk,
    const float* __restrict__ Wv, const float* __restrict__ Wo,
    const float* __restrict__ W1, const float* __restrict__ W2,
    __half* __restrict__ WqT, __half* __restrict__ WkT,
    __half* __restrict__ WvT, __half* __restrict__ WoT,
    __half* __restrict__ W1T, __half* __restrict__ W2T)
{
    __shared__ float t[32][33];
    const int z = blockIdx.z;
    const float* in; __half* outp; int K, N;
    switch (z) {
        case 0:  in = Wq; outp = WqT; K = DM;  N = DM;  break;
        case 1:  in = Wk; outp = WkT; K = DM;  N = DM;  break;
        case 2:  in = Wv; outp = WvT; K = DM;  N = DM;  break;
        case 3:  in = Wo; outp = WoT; K = DM;  N = DM;  break;
        case 4:  in = W1; outp = W1T; K = DM;  N = DFF; break;
        default: in = W2; outp = W2T; K = DFF; N = DM;  break;
    }
    const int n0 = blockIdx.x * 32, k0 = blockIdx.y * 32;
    if (n0 >= N || k0 >= K) return;
    const int tx = threadIdx.x & 31, ty = threadIdx.x >> 5;
#pragma unroll
    for (int i = 0; i < 4; i++)
        t[ty + 8 * i][tx] = in[(size_t)(k0 + ty + 8 * i) * N + n0 + tx];
    __syncthreads();
    if (tx < 16) {
#pragma unroll
        for (int i = 0; i < 4; i++) {
            int n = ty + 8 * i;
            int kl = 2 * tx;
            int pos = (kl & ~15) + ppos(kl & 15);
            *(uint32_t*)&outp[(size_t)(n0 + n) * K + k0 + pos] =
                h2u(t[kl][n], t[kl + 1][n]);
        }
    }
}

// ---------------- fp16 tensor-core flash attention --------------------------
// 128 Q-rows per CTA, 64-token KV tiles, triple-buffered cp.async.
// K/V fragment loads are LDS.128 with parity swizzle (conflict-free).
// smem: K[3][8192B] at 0, V[3][8192B] at 24576. Total 49152 B.
__global__ __launch_bounds__(256, 2) void attn_h(
    const __half* __restrict__ Q, const __half* __restrict__ Kpk,
    const __half* __restrict__ Vpk, const float* __restrict__ bias,
    float* __restrict__ O)
{
    extern __shared__ char smc[];
    const int tid = threadIdx.x;
    const int lane = tid & 31;
    const int g = lane >> 2, c = lane & 3;
    const int h = blockIdx.y;
    const int q0 = blockIdx.x * 128;
    const int r0 = 16 * (tid >> 5) + g;
    const unsigned sbase = (unsigned)__cvta_generic_to_shared(smc);

    const float* bias0 = bias + ((size_t)h * NT + q0 + r0) * NT;
    pf_l2(bias0 + 16 * c);
    pf_l2(bias0 + (size_t)8 * NT + 16 * c);

    // Q fragments (4 k16-chunks x 4 half2 regs), prescaled+packed in gmem
    uint32_t qa[4][4];
    {
        const char* qp0 = (const char*)(Q + (size_t)(q0 + r0) * DM + h * HD);
        const char* qp1 = qp0 + (size_t)8 * DM * 2;
#pragma unroll
        for (int kk = 0; kk < 4; kk++) {
            uint2 t0 = *(const uint2*)(qp0 + kk * 32 + c * 8);
            uint2 t1 = *(const uint2*)(qp1 + kk * 32 + c * 8);
            qa[kk][0] = t0.x; qa[kk][1] = t1.x; qa[kk][2] = t0.y; qa[kk][3] = t1.y;
        }
    }

    float o[8][4];
#pragma unroll
    for (int j = 0; j < 8; j++)
#pragma unroll
        for (int r = 0; r < 4; r++) o[j][r] = 0.f;
    float mr0 = -1e30f, mr1 = -1e30f, lr0 = 0.f, lr1 = 0.f;

    const __half* kbase = Kpk + (size_t)h * NT * 64;
    const __half* vbase = Vpk + (size_t)h * NT * 64;

#pragma unroll
    for (int b = 0; b < 2; b++) {
        const char* ks = (const char*)(kbase + (size_t)b * 4096);
        const char* vs = (const char*)(vbase + (size_t)b * 4096);
        cpa16(sbase + b * 8192 + tid * 16,            ks + tid * 16);
        cpa16(sbase + b * 8192 + 4096 + tid * 16,     ks + 4096 + tid * 16);
        cpa16(sbase + 24576 + b * 8192 + tid * 16,    vs + tid * 16);
        cpa16(sbase + 24576 + b * 8192 + 4096 + tid * 16, vs + 4096 + tid * 16);
        asm volatile("cp.async.commit_group;" ::: "memory");
    }

    const int swz = (g & 1) << 6;   // parity swizzle offset (bytes)

    for (int t = 0; t < NT / 64; t++) {
        const int buf = t % 3;
        if (t < NT / 64 - 1) {
            asm volatile("cp.async.wait_group 1;" ::: "memory");
        } else {
            asm volatile("cp.async.wait_group 0;" ::: "memory");
        }
        __syncthreads();

        if (t + 2 < NT / 64) {
            const int b2 = (t + 2) % 3;
            const char* ks = (const char*)(kbase + (size_t)(t + 2) * 4096);
            const char* vs = (const char*)(vbase + (size_t)(t + 2) * 4096);
            cpa16(sbase + b2 * 8192 + tid * 16,            ks + tid * 16);
            cpa16(sbase + b2 * 8192 + 4096 + tid * 16,     ks + 4096 + tid * 16);
            cpa16(sbase + 24576 + b2 * 8192 + tid * 16,    vs + tid * 16);
            cpa16(sbase + 24576 + b2 * 8192 + 4096 + tid * 16, vs + 4096 + tid * 16);
            asm volatile("cp.async.commit_group;" ::: "memory");
        }

        const char* Ksb = smc + buf * 8192;
        const char* Vsb = smc + 24576 + buf * 8192;

        // ---- S = Q@K^T + bias (bias preloaded into accumulators) ----------
        float s[8][4];
        const float* bp = bias0 + t * 64;
#pragma unroll
        for (int j = 0; j < 8; j++) {
            float2 b0 = __ldcs((const float2*)(bp + 8 * j + 2 * c));
            float2 b1 = __ldcs((const float2*)(bp + (size_t)8 * NT + 8 * j + 2 * c));
            s[j][0] = b0.x; s[j][1] = b0.y; s[j][2] = b1.x; s[j][3] = b1.y;
        }
#pragma unroll
        for (int kkp = 0; kkp < 2; kkp++) {
            const char* kp = Ksb + c * 16 + (((kkp << 6) ^ swz) & 64) + (kkp ? 0 : 0);
            // address: (8j+g)*128 + c*16 + ((kkp^(g&1))<<6)
#pragma unroll
            for (int j = 0; j < 8; j++) {
                uint4 kb = *(const uint4*)(Ksb + (8 * j + g) * 128 + c * 16 + (((kkp << 6)) ^ swz));
                mma16(s[j], qa[2 * kkp][0], qa[2 * kkp][1], qa[2 * kkp][2], qa[2 * kkp][3], kb.x, kb.y);
                mma16(s[j], qa[2 * kkp + 1][0], qa[2 * kkp + 1][1], qa[2 * kkp + 1][2], qa[2 * kkp + 1][3], kb.z, kb.w);
            }
        }

        if (t + 1 < NT / 64) {
            pf_l2(bp + 64 + 16 * c);
            pf_l2(bp + (size_t)8 * NT + 64 + 16 * c);
        }

        // ---- online softmax (rows r0 / r0+8, reduce over 4-lane c-group) --
        float rm0 = -1e30f, rm1 = -1e30f;
#pragma unroll
        for (int j = 0; j < 8; j++) {
            rm0 = fmaxf(rm0, fmaxf(s[j][0], s[j][1]));
            rm1 = fmaxf(rm1, fmaxf(s[j][2], s[j][3]));
        }
        rm0 = fmaxf(rm0, __shfl_xor_sync(0xffffffffu, rm0, 1));
        rm0 = fmaxf(rm0, __shfl_xor_sync(0xffffffffu, rm0, 2));
        rm1 = fmaxf(rm1, __shfl_xor_sync(0xffffffffu, rm1, 1));
        rm1 = fmaxf(rm1, __shfl_xor_sync(0xffffffffu, rm1, 2));

        if (__any_sync(0xffffffffu, (rm0 > mr0) || (rm1 > mr1))) {
            float mn0 = fmaxf(mr0, rm0), mn1 = fmaxf(mr1, rm1);
            float corr0 = fexp(mr0 - mn0), corr1 = fexp(mr1 - mn1);
            mr0 = mn0; mr1 = mn1;
            lr0 *= corr0; lr1 *= corr1;
#pragma unroll
            for (int j = 0; j < 8; j++) {
                o[j][0] *= corr0; o[j][1] *= corr0;
                o[j][2] *= corr1; o[j][3] *= corr1;
            }
        }

        float sum0 = 0.f, sum1 = 0.f;
#pragma unroll
        for (int j = 0; j < 8; j++) {
            s[j][0] = fexp(s[j][0] - mr0);
            s[j][1] = fexp(s[j][1] - mr0);
            s[j][2] = fexp(s[j][2] - mr1);
            s[j][3] = fexp(s[j][3] - mr1);
            sum0 += s[j][0] + s[j][1];
            sum1 += s[j][2] + s[j][3];
        }
        sum0 += __shfl_xor_sync(0xffffffffu, sum0, 1);
        sum0 += __shfl_xor_sync(0xffffffffu, sum0, 2);
        sum1 += __shfl_xor_sync(0xffffffffu, sum1, 1);
        sum1 += __shfl_xor_sync(0xffffffffu, sum1, 2);
        lr0 += sum0;
        lr1 += sum1;

        // ---- O += P @ V : C-fragments ARE the A-fragments (no shuffles) ---
#pragma unroll
        for (int tkp = 0; tkp < 2; tkp++) {
            uint32_t a00 = h2u(s[4 * tkp + 0][0], s[4 * tkp + 0][1]);
            uint32_t a01 = h2u(s[4 * tkp + 0][2], s[4 * tkp + 0][3]);
            uint32_t a02 = h2u(s[4 * tkp + 1][0], s[4 * tkp + 1][1]);
            uint32_t a03 = h2u(s[4 * tkp + 1][2], s[4 * tkp + 1][3]);
            uint32_t a10 = h2u(s[4 * tkp + 2][0], s[4 * tkp + 2][1]);
            uint32_t a11 = h2u(s[4 * tkp + 2][2], s[4 * tkp + 2][3]);
            uint32_t a12 = h2u(s[4 * tkp + 3][0], s[4 * tkp + 3][1]);
            uint32_t a13 = h2u(s[4 * tkp + 3][2], s[4 * tkp + 3][3]);
#pragma unroll
            for (int j = 0; j < 8; j++) {
                uint4 vb = *(const uint4*)(Vsb + (8 * j + g) * 128 + c * 16 + (((tkp << 6)) ^ swz));
                mma16(o[j], a00, a01, a02, a03, vb.x, vb.y);
                mma16(o[j], a10, a11, a12, a13, vb.z, vb.w);
            }
        }
    }

    float inv0 = 1.0f / lr0, inv1 = 1.0f / lr1;
    const int grow0 = q0 + r0;
#pragma unroll
    for (int j = 0; j < 8; j++) {
        int col = h * HD + 8 * j + 2 * c;
        *(float2*)&O[(size_t)grow0 * DM + col] =
            make_float2(o[j][0] * inv0, o[j][1] * inv0);
        *(float2*)&O[(size_t)(grow0 + 8) * DM + col] =
            make_float2(o[j][2] * inv1, o[j][3] * inv1);
    }
}

// ---------------- fused residual + LayerNorm --------------------------------
__global__ __launch_bounds__(128) void add_ln_kernel(
    const float* __restrict__ A, const float* __restrict__ B,
    const float* __restrict__ g, const float* __restrict__ be,
    float* __restrict__ out)
{
    __shared__ float red[8];
    const int row = blockIdx.x, tid = threadIdx.x;
    float4 a = *(const float4*)&A[(size_t)row * DM + tid * 4];
    float4 b = *(const float4*)&B[(size_t)row * DM + tid * 4];
    float v[4] = {a.x + b.x, a.y + b.y, a.z + b.z, a.w + b.w};

    float s = v[0] + v[1] + v[2] + v[3];
#pragma unroll
    for (int off = 16; off; off >>= 1) s += __shfl_xor_sync(0xffffffffu, s, off);
    if ((tid & 31) == 0) red[tid >> 5] = s;
    __syncthreads();
    float mu = (red[0] + red[1] + red[2] + red[3]) * (1.f / DM);

    float d[4]; float sq = 0.f;
#pragma unroll
    for (int i = 0; i < 4; i++) { d[i] = v[i] - mu; sq += d[i] * d[i]; }
#pragma unroll
    for (int off = 16; off; off >>= 1) sq += __shfl_xor_sync(0xffffffffu, sq, off);
    if ((tid & 31) == 0) red[4 + (tid >> 5)] = sq;
    __syncthreads();
    float inv = rsqrtf((red[4] + red[5] + red[6] + red[7]) * (1.f / DM) + 1e-5f);

    float4 gg = *(const float4*)&g[tid * 4];
    float4 bb = *(const float4*)&be[tid * 4];
    float4 r;
    r.x = d[0] * inv * gg.x + bb.x;
    r.y = d[1] * inv * gg.y + bb.y;
    r.z = d[2] * inv * gg.z + bb.z;
    r.w = d[3] * inv * gg.w + bb.w;
    *(float4*)&out[(size_t)row * DM + tid * 4] = r;
}

// ---------------- launch ----------------------------------------------------
extern "C" void kernel_launch(void* const* d_in, const int* in_sizes, int n_in,
                              void* d_out, int out_size)
{
    const float* x    = (const float*)d_in[0];
    const float* bias = (const float*)d_in[1];
    const float* Wq = (const float*)d_in[2];  const float* bq = (const float*)d_in[3];
    const float* Wk = (const float*)d_in[4];  const float* bk = (const float*)d_in[5];
    const float* Wv = (const float*)d_in[6];  const float* bv = (const float*)d_in[7];
    const float* Wo = (const float*)d_in[8];  const float* bo = (const float*)d_in[9];
    const float* g1 = (const float*)d_in[10]; const float* b1 = (const float*)d_in[11];
    const float* g2 = (const float*)d_in[12]; const float* b2 = (const float*)d_in[13];
    const float* W1 = (const float*)d_in[14]; const float* c1 = (const float*)d_in[15];
    const float* W2 = (const float*)d_in[16]; const float* c2 = (const float*)d_in[17];
    float* out = (float*)d_out;

    __half *Qp, *Kp, *Vp, *WqT, *WkT, *WvT, *WoT, *W1T, *W2T;
    float *attnp, *tmpp, *x1p, *hidp;
    cudaGetSymbolAddress((void**)&Qp,    g_Q);
    cudaGetSymbolAddress((void**)&Kp,    g_K);
    cudaGetSymbolAddress((void**)&Vp,    g_V);
    cudaGetSymbolAddress((void**)&attnp, g_attn);
    cudaGetSymbolAddress((void**)&tmpp,  g_tmp);
    cudaGetSymbolAddress((void**)&x1p,   g_x1);
    cudaGetSymbolAddress((void**)&hidp,  g_hid);
    cudaGetSymbolAddress((void**)&WqT,   g_WqT);
    cudaGetSymbolAddress((void**)&WkT,   g_WkT);
    cudaGetSymbolAddress((void**)&WvT,   g_WvT);
    cudaGetSymbolAddress((void**)&WoT,   g_WoT);
    cudaGetSymbolAddress((void**)&W1T,   g_W1T);
    cudaGetSymbolAddress((void**)&W2T,   g_W2T);

    const int ATTN_SMEM = 49152;
    cudaFuncSetAttribute(attn_h, cudaFuncAttributeMaxDynamicSharedMemorySize, ATTN_SMEM);

    // all six weight transposes in ONE launch
    transpose_all<<<dim3(DFF / 32, DFF / 32, 6), 256>>>(
        Wq, Wk, Wv, Wo, W1, W2, WqT, WkT, WvT, WoT, W1T, W2T);

    dim3 blk(256);
    gemm_qkv<<<dim3(DM / 128, NT / 128, 3), blk>>>(
        x, WqT, bq, Qp, WkT, bk, Kp, WvT, bv, Vp);

    attn_h<<<dim3(NT / 128, NH), blk, ATTN_SMEM>>>(Qp, Kp, Vp, bias, attnp);

    gemm_h<0><<<dim3(DM / 128, NT / 128), blk>>>(attnp, WoT, bo, tmpp, DM, DM);
    add_ln_kernel<<<NT, 128>>>(x, tmpp, g1, b1, x1p);

    gemm_h<1><<<dim3(DFF / 128, NT / 128), blk>>>(x1p, W1T, c1, hidp, DFF, DM);
    gemm_h<0><<<dim3(DM / 128, NT / 128), blk>>>(hidp, W2T, c2, tmpp, DM, DFF);
    add_ln_kernel<<<NT, 128>>>(x1p, tmpp, g2, b2, out);
}

// round 9
// speedup vs baseline: 5.8500x; 1.0698x over previous
#include <cuda_runtime.h>
#include <cuda_fp16.h>
#include <math.h>
#include <stdint.h>

#define NT  4096
#define DM  512
#define NH  8
#define HD  64
#define DFF 1024

// ---------------- scratch (static device globals; no allocations) ----------
__device__ __half g_Q[NT * DM];      // fp16, 0.125-prescaled, pk16-packed
__device__ __half g_K[NT * DM];      // fp16, tile-contiguous packed (khalf_idx)
__device__ __half g_V[NT * DM];      // fp16, tile-contiguous packed (vhalf_idx)
__device__ __half g_x16[NT * DM];    // x packed fp16 (QKV GEMM A operand)
__device__ __half g_attn16[NT * DM]; // attention out packed fp16 (Wo A operand)
__device__ __half g_x116[NT * DM];   // LN1 out packed fp16 (W1 A operand)
__device__ __half g_hid16[NT * DFF]; // FF1 out packed fp16 (W2 A operand)
__device__ float  g_tmp[NT * DM];
__device__ float  g_x1[NT * DM];
// transposed fp16 weights, pk16-packed along k (B operands)
__device__ __half g_WqT[DM * DM];
__device__ __half g_WkT[DM * DM];
__device__ __half g_WvT[DM * DM];
__device__ __half g_WoT[DM * DM];
__device__ __half g_W1T[DFF * DM];
__device__ __half g_W2T[DM * DFF];

// ---------------- helpers ---------------------------------------------------
// pk16: within each 16-element k group, order (0,1,8,9),(2,3,10,11),(4,5,12,13),(6,7,14,15)
__host__ __device__ __forceinline__ int ppos(int r) {
    return ((r & 7) >> 1) * 4 + ((r >> 3) & 1) * 2 + (r & 1);
}

__device__ __forceinline__ size_t khalf_idx(int h, int tok, int dim) {
    int tl = tok & 63;
    int r = dim & 15;
    int c = (r >> 1) & 3, q = ((r >> 3) & 1) * 2 + (r & 1);
    int kkl = (dim >> 4) & 1, kkp = (dim >> 5) & 1;
    return (size_t)h * NT * 64 + (size_t)(tok >> 6) * 4096
         + tl * 64 + ((kkp ^ (tl & 1)) << 5) + c * 8 + kkl * 4 + q;
}
__device__ __forceinline__ size_t vhalf_idx(int h, int tok, int n) {
    int r = tok & 15;
    int c = (r >> 1) & 3, q = ((r >> 3) & 1) * 2 + (r & 1);
    int tkl = (tok >> 4) & 1, tkp = (tok >> 5) & 1;
    return (size_t)h * NT * 64 + (size_t)(tok >> 6) * 4096
         + n * 64 + ((tkp ^ (n & 1)) << 5) + c * 8 + tkl * 4 + q;
}

__device__ __forceinline__ uint32_t h2u(float lo, float hi) {
    uint32_t r;
    asm("cvt.rn.f16x2.f32 %0, %1, %2;" : "=r"(r) : "f"(hi), "f"(lo));
    return r;
}

__device__ __forceinline__ void mma16(float d[4],
                                      uint32_t a0, uint32_t a1, uint32_t a2, uint32_t a3,
                                      uint32_t b0, uint32_t b1) {
    asm("mma.sync.aligned.m16n8k16.row.col.f32.f16.f16.f32 "
        "{%0,%1,%2,%3}, {%4,%5,%6,%7}, {%8,%9}, {%0,%1,%2,%3};"
        : "+f"(d[0]), "+f"(d[1]), "+f"(d[2]), "+f"(d[3])
        : "r"(a0), "r"(a1), "r"(a2), "r"(a3), "r"(b0), "r"(b1));
}

__device__ __forceinline__ void cpa16(unsigned dst, const void* src) {
    asm volatile("cp.async.cg.shared.global [%0], [%1], 16;" :: "r"(dst), "l"(src));
}
__device__ __forceinline__ void pf_l2(const void* p) {
    asm volatile("prefetch.global.L2 [%0];" :: "l"(p));
}

// MUFU-based exp for x <= 0.
__device__ __forceinline__ float fexp(float x) {
    float r;
    float y = x * 1.4426950408889634f;
    asm("ex2.approx.f32 %0, %1;" : "=f"(r) : "f"(y));
    return r;
}

// ==================== fp16 GEMM, all-cp.async, 64x128 tile, 3-stage ========
// smem per stage: A 4KB (64 rows x 64B, kk-swizzled) + B 8KB ([kk][n][32B]).
// 8 warps as 2(m) x 4(n); warp tile 32x32.
template <int MODE>   // 0: fp32 out + bias; 1: bias + relu -> fp16 pk16 out
__global__ __launch_bounds__(256) void gemm16(
    const __half* __restrict__ A16, const __half* __restrict__ Bt,
    const float* __restrict__ bias, void* __restrict__ Cout, int N, int K)
{
    __shared__ __align__(16) char smem[3 * 12288];
    const int tid = threadIdx.x;
    const int wid = tid >> 5, lane = tid & 31;
    const int g = lane >> 2, c = lane & 3;
    const int wm = (wid >> 2) * 32, wn = (wid & 3) * 32;
    const int m0 = blockIdx.y * 64, n0 = blockIdx.x * 128;
    const unsigned sb = (unsigned)__cvta_generic_to_shared(smem);

    float acc[2][4][4];
#pragma unroll
    for (int t = 0; t < 2; t++)
#pragma unroll
        for (int j = 0; j < 4; j++)
#pragma unroll
            for (int r = 0; r < 4; r++) acc[t][j][r] = 0.f;

    // staging decompositions
    const int arow = tid >> 2, apart = tid & 3;       // A: 256 x 16B
    const unsigned adst = arow * 64 +
        (((apart >> 1) ^ ((arow >> 1) & 1)) << 5) + (apart & 1) * 16;

    auto stage = [&](int kb, int st) {
        unsigned s0 = sb + st * 12288;
        cpa16(s0 + adst, A16 + (size_t)(m0 + arow) * K + kb * 32 + apart * 8);
#pragma unroll
        for (int i = 0; i < 2; i++) {
            int idx = i * 256 + tid;
            int n = idx >> 2, sub = idx & 3;
            int kk = sub >> 1, part = sub & 1;
            cpa16(s0 + 4096 + kk * 4096 + n * 32 + part * 16,
                  Bt + (size_t)(n0 + n) * K + kb * 32 + kk * 16 + part * 8);
        }
        asm volatile("cp.async.commit_group;" ::: "memory");
    };

    const int nk = K >> 5;
    stage(0, 0);
    stage(1, 1);

    const int aswz = (g >> 1) & 1;   // fragment-side kk swizzle

    for (int kb = 0; kb < nk; kb++) {
        if (kb + 1 < nk) {
            asm volatile("cp.async.wait_group 1;" ::: "memory");
        } else {
            asm volatile("cp.async.wait_group 0;" ::: "memory");
        }
        __syncthreads();
        if (kb + 2 < nk) stage(kb + 2, (kb + 2) % 3);

        const char* aB = smem + (kb % 3) * 12288;
        const char* bB = aB + 4096;
#pragma unroll
        for (int kk = 0; kk < 2; kk++) {
            const int ko = ((kk ^ aswz) << 5) + c * 8;
            uint32_t af[2][4];
#pragma unroll
            for (int t = 0; t < 2; t++) {
                uint2 r0 = *(const uint2*)(aB + (wm + 16 * t + g) * 64 + ko);
                uint2 r1 = *(const uint2*)(aB + (wm + 16 * t + g + 8) * 64 + ko);
                af[t][0] = r0.x; af[t][1] = r1.x; af[t][2] = r0.y; af[t][3] = r1.y;
            }
#pragma unroll
            for (int j = 0; j < 4; j++) {
                uint2 bv = *(const uint2*)(bB + kk * 4096 + (wn + 8 * j + g) * 32 + c * 8);
#pragma unroll
                for (int t = 0; t < 2; t++)
                    mma16(acc[t][j], af[t][0], af[t][1], af[t][2], af[t][3], bv.x, bv.y);
            }
        }
        __syncthreads();
    }

#pragma unroll
    for (int t = 0; t < 2; t++) {
        int row0 = m0 + wm + 16 * t + g;
#pragma unroll
        for (int j = 0; j < 4; j++) {
            int col = n0 + wn + 8 * j + 2 * c;
            float2 bv = *(const float2*)&bias[col];
            float v00 = acc[t][j][0] + bv.x, v01 = acc[t][j][1] + bv.y;
            float v10 = acc[t][j][2] + bv.x, v11 = acc[t][j][3] + bv.y;
            if (MODE == 0) {
                float* C = (float*)Cout;
                *(float2*)&C[(size_t)row0 * N + col]       = make_float2(v00, v01);
                *(float2*)&C[(size_t)(row0 + 8) * N + col] = make_float2(v10, v11);
            } else {
                v00 = fmaxf(v00, 0.f); v01 = fmaxf(v01, 0.f);
                v10 = fmaxf(v10, 0.f); v11 = fmaxf(v11, 0.f);
                __half* C = (__half*)Cout;
                size_t p = (size_t)row0 * N + (col & ~15) + ppos(col & 15);
                *(uint32_t*)&C[p]                   = h2u(v00, v01);
                *(uint32_t*)&C[p + (size_t)8 * N]   = h2u(v10, v11);
            }
        }
    }
}

// ---------------- fused QKV GEMM (A fp16), z selects projection -------------
__global__ __launch_bounds__(256) void qkv16(
    const __half* __restrict__ x16,
    const __half* __restrict__ WqT, const float* __restrict__ bq, __half* __restrict__ Qo,
    const __half* __restrict__ WkT, const float* __restrict__ bk, __half* __restrict__ Ko,
    const __half* __restrict__ WvT, const float* __restrict__ bv, __half* __restrict__ Vo)
{
    __shared__ __align__(16) char smem[3 * 12288];
    const int z = blockIdx.z;
    const __half* Bt   = (z == 0) ? WqT : (z == 1) ? WkT : WvT;
    const float*  bias = (z == 0) ? bq  : (z == 1) ? bk  : bv;

    const int tid = threadIdx.x;
    const int wid = tid >> 5, lane = tid & 31;
    const int g = lane >> 2, c = lane & 3;
    const int wm = (wid >> 2) * 32, wn = (wid & 3) * 32;
    const int m0 = blockIdx.y * 64, n0 = blockIdx.x * 128;
    const unsigned sb = (unsigned)__cvta_generic_to_shared(smem);

    float acc[2][4][4];
#pragma unroll
    for (int t = 0; t < 2; t++)
#pragma unroll
        for (int j = 0; j < 4; j++)
#pragma unroll
            for (int r = 0; r < 4; r++) acc[t][j][r] = 0.f;

    const int arow = tid >> 2, apart = tid & 3;
    const unsigned adst = arow * 64 +
        (((apart >> 1) ^ ((arow >> 1) & 1)) << 5) + (apart & 1) * 16;

    auto stage = [&](int kb, int st) {
        unsigned s0 = sb + st * 12288;
        cpa16(s0 + adst, x16 + (size_t)(m0 + arow) * DM + kb * 32 + apart * 8);
#pragma unroll
        for (int i = 0; i < 2; i++) {
            int idx = i * 256 + tid;
            int n = idx >> 2, sub = idx & 3;
            int kk = sub >> 1, part = sub & 1;
            cpa16(s0 + 4096 + kk * 4096 + n * 32 + part * 16,
                  Bt + (size_t)(n0 + n) * DM + kb * 32 + kk * 16 + part * 8);
        }
        asm volatile("cp.async.commit_group;" ::: "memory");
    };

    const int nk = DM >> 5;
    stage(0, 0);
    stage(1, 1);
    const int aswz = (g >> 1) & 1;

    for (int kb = 0; kb < nk; kb++) {
        if (kb + 1 < nk) {
            asm volatile("cp.async.wait_group 1;" ::: "memory");
        } else {
            asm volatile("cp.async.wait_group 0;" ::: "memory");
        }
        __syncthreads();
        if (kb + 2 < nk) stage(kb + 2, (kb + 2) % 3);

        const char* aB = smem + (kb % 3) * 12288;
        const char* bB = aB + 4096;
#pragma unroll
        for (int kk = 0; kk < 2; kk++) {
            const int ko = ((kk ^ aswz) << 5) + c * 8;
            uint32_t af[2][4];
#pragma unroll
            for (int t = 0; t < 2; t++) {
                uint2 r0 = *(const uint2*)(aB + (wm + 16 * t + g) * 64 + ko);
                uint2 r1 = *(const uint2*)(aB + (wm + 16 * t + g + 8) * 64 + ko);
                af[t][0] = r0.x; af[t][1] = r1.x; af[t][2] = r0.y; af[t][3] = r1.y;
            }
#pragma unroll
            for (int j = 0; j < 4; j++) {
                uint2 bv2 = *(const uint2*)(bB + kk * 4096 + (wn + 8 * j + g) * 32 + c * 8);
#pragma unroll
                for (int t = 0; t < 2; t++)
                    mma16(acc[t][j], af[t][0], af[t][1], af[t][2], af[t][3], bv2.x, bv2.y);
            }
        }
        __syncthreads();
    }

#pragma unroll
    for (int t = 0; t < 2; t++) {
        int row0 = m0 + wm + 16 * t + g;
#pragma unroll
        for (int j = 0; j < 4; j++) {
            int col = n0 + wn + 8 * j + 2 * c;
            float2 bvv = *(const float2*)&bias[col];
            float v00 = acc[t][j][0] + bvv.x, v01 = acc[t][j][1] + bvv.y;
            float v10 = acc[t][j][2] + bvv.x, v11 = acc[t][j][3] + bvv.y;
            if (z == 0) {
                size_t p0 = (size_t)row0 * DM + (col & ~15) + ppos(col & 15);
                *(uint32_t*)&Qo[p0]                   = h2u(v00 * 0.125f, v01 * 0.125f);
                *(uint32_t*)&Qo[p0 + (size_t)8 * DM]  = h2u(v10 * 0.125f, v11 * 0.125f);
            } else if (z == 1) {
                int h = col >> 6, dl = col & 63;
                *(uint32_t*)&Ko[khalf_idx(h, row0,     dl)] = h2u(v00, v01);
                *(uint32_t*)&Ko[khalf_idx(h, row0 + 8, dl)] = h2u(v10, v11);
            } else {
                int h = col >> 6, dl = col & 63;
                Vo[vhalf_idx(h, row0,     dl)]     = __float2half_rn(v00);
                Vo[vhalf_idx(h, row0,     dl + 1)] = __float2half_rn(v01);
                Vo[vhalf_idx(h, row0 + 8, dl)]     = __float2half_rn(v10);
                Vo[vhalf_idx(h, row0 + 8, dl + 1)] = __float2half_rn(v11);
            }
        }
    }
}

// ---------------- pack x: fp32 [NT][DM] -> fp16 pk16 ------------------------
__global__ void __launch_bounds__(256) pack_x(
    const float* __restrict__ x, __half* __restrict__ o)
{
    int i = blockIdx.x * 256 + threadIdx.x;      // NT*DM/16 threads
    int row = i >> 5, grp = i & 31;
    const float* src = x + (size_t)row * DM + grp * 16;
    uint32_t u[8];
#pragma unroll
    for (int q = 0; q < 4; q++) {
        float4 v = *(const float4*)(src + q * 4);
        int d = q * 4;
        u[ppos(d) >> 1]     = h2u(v.x, v.y);
        u[ppos(d + 2) >> 1] = h2u(v.z, v.w);
    }
    __half* dst = o + (size_t)row * DM + grp * 16;
    *(uint4*)dst       = make_uint4(u[0], u[1], u[2], u[3]);
    *(uint4*)(dst + 8) = make_uint4(u[4], u[5], u[6], u[7]);
}

// ---------------- fused weight transpose: ONE launch for all 6 weights ------
__global__ void __launch_bounds__(256) transpose_all(
    const float* __restrict__ Wq, const float* __restrict__ Wk,
    const float* __restrict__ Wv, const float* __restrict__ Wo,
    const float* __restrict__ W1, const float* __restrict__ W2,
    __half* __restrict__ WqT, __half* __restrict__ WkT,
    __half* __restrict__ WvT, __half* __restrict__ WoT,
    __half* __restrict__ W1T, __half* __restrict__ W2T)
{
    __shared__ float t[32][33];
    const int z = blockIdx.z;
    const float* in; __half* outp; int K, N;
    switch (z) {
        case 0:  in = Wq; outp = WqT; K = DM;  N = DM;  break;
        case 1:  in = Wk; outp = WkT; K = DM;  N = DM;  break;
        case 2:  in = Wv; outp = WvT; K = DM;  N = DM;  break;
        case 3:  in = Wo; outp = WoT; K = DM;  N = DM;  break;
        case 4:  in = W1; outp = W1T; K = DM;  N = DFF; break;
        default: in = W2; outp = W2T; K = DFF; N = DM;  break;
    }
    const int n0 = blockIdx.x * 32, k0 = blockIdx.y * 32;
    if (n0 >= N || k0 >= K) return;
    const int tx = threadIdx.x & 31, ty = threadIdx.x >> 5;
#pragma unroll
    for (int i = 0; i < 4; i++)
        t[ty + 8 * i][tx] = in[(size_t)(k0 + ty + 8 * i) * N + n0 + tx];
    __syncthreads();
    if (tx < 16) {
#pragma unroll
        for (int i = 0; i < 4; i++) {
            int n = ty + 8 * i;
            int kl = 2 * tx;
            int pos = (kl & ~15) + ppos(kl & 15);
            *(uint32_t*)&outp[(size_t)(n0 + n) * K + k0 + pos] =
                h2u(t[kl][n], t[kl + 1][n]);
        }
    }
}

// ---------------- fp16 tensor-core flash attention --------------------------
__global__ __launch_bounds__(256, 2) void attn_h(
    const __half* __restrict__ Q, const __half* __restrict__ Kpk,
    const __half* __restrict__ Vpk, const float* __restrict__ bias,
    __half* __restrict__ O16)
{
    extern __shared__ char smc[];
    const int tid = threadIdx.x;
    const int lane = tid & 31;
    const int g = lane >> 2, c = lane & 3;
    const int h = blockIdx.y;
    const int q0 = blockIdx.x * 128;
    const int r0 = 16 * (tid >> 5) + g;
    const unsigned sbase = (unsigned)__cvta_generic_to_shared(smc);

    const float* bias0 = bias + ((size_t)h * NT + q0 + r0) * NT;
    pf_l2(bias0 + 16 * c);
    pf_l2(bias0 + (size_t)8 * NT + 16 * c);

    uint32_t qa[4][4];
    {
        const char* qp0 = (const char*)(Q + (size_t)(q0 + r0) * DM + h * HD);
        const char* qp1 = qp0 + (size_t)8 * DM * 2;
#pragma unroll
        for (int kk = 0; kk < 4; kk++) {
            uint2 t0 = *(const uint2*)(qp0 + kk * 32 + c * 8);
            uint2 t1 = *(const uint2*)(qp1 + kk * 32 + c * 8);
            qa[kk][0] = t0.x; qa[kk][1] = t1.x; qa[kk][2] = t0.y; qa[kk][3] = t1.y;
        }
    }

    float o[8][4];
#pragma unroll
    for (int j = 0; j < 8; j++)
#pragma unroll
        for (int r = 0; r < 4; r++) o[j][r] = 0.f;
    float mr0 = -1e30f, mr1 = -1e30f, lr0 = 0.f, lr1 = 0.f;

    const __half* kbase = Kpk + (size_t)h * NT * 64;
    const __half* vbase = Vpk + (size_t)h * NT * 64;

#pragma unroll
    for (int b = 0; b < 2; b++) {
        const char* ks = (const char*)(kbase + (size_t)b * 4096);
        const char* vs = (const char*)(vbase + (size_t)b * 4096);
        cpa16(sbase + b * 8192 + tid * 16,            ks + tid * 16);
        cpa16(sbase + b * 8192 + 4096 + tid * 16,     ks + 4096 + tid * 16);
        cpa16(sbase + 24576 + b * 8192 + tid * 16,    vs + tid * 16);
        cpa16(sbase + 24576 + b * 8192 + 4096 + tid * 16, vs + 4096 + tid * 16);
        asm volatile("cp.async.commit_group;" ::: "memory");
    }

    const int swz = (g & 1) << 6;

    for (int t = 0; t < NT / 64; t++) {
        const int buf = t % 3;
        if (t < NT / 64 - 1) {
            asm volatile("cp.async.wait_group 1;" ::: "memory");
        } else {
            asm volatile("cp.async.wait_group 0;" ::: "memory");
        }
        __syncthreads();

        if (t + 2 < NT / 64) {
            const int b2 = (t + 2) % 3;
            const char* ks = (const char*)(kbase + (size_t)(t + 2) * 4096);
            const char* vs = (const char*)(vbase + (size_t)(t + 2) * 4096);
            cpa16(sbase + b2 * 8192 + tid * 16,            ks + tid * 16);
            cpa16(sbase + b2 * 8192 + 4096 + tid * 16,     ks + 4096 + tid * 16);
            cpa16(sbase + 24576 + b2 * 8192 + tid * 16,    vs + tid * 16);
            cpa16(sbase + 24576 + b2 * 8192 + 4096 + tid * 16, vs + 4096 + tid * 16);
            asm volatile("cp.async.commit_group;" ::: "memory");
        }

        const char* Ksb = smc + buf * 8192;
        const char* Vsb = smc + 24576 + buf * 8192;

        float s[8][4];
        const float* bp = bias0 + t * 64;
#pragma unroll
        for (int j = 0; j < 8; j++) {
            float2 b0 = __ldcs((const float2*)(bp + 8 * j + 2 * c));
            float2 b1 = __ldcs((const float2*)(bp + (size_t)8 * NT + 8 * j + 2 * c));
            s[j][0] = b0.x; s[j][1] = b0.y; s[j][2] = b1.x; s[j][3] = b1.y;
        }
#pragma unroll
        for (int kkp = 0; kkp < 2; kkp++) {
#pragma unroll
            for (int j = 0; j < 8; j++) {
                uint4 kb = *(const uint4*)(Ksb + (8 * j + g) * 128 + c * 16 + ((kkp << 6) ^ swz));
                mma16(s[j], qa[2 * kkp][0], qa[2 * kkp][1], qa[2 * kkp][2], qa[2 * kkp][3], kb.x, kb.y);
                mma16(s[j], qa[2 * kkp + 1][0], qa[2 * kkp + 1][1], qa[2 * kkp + 1][2], qa[2 * kkp + 1][3], kb.z, kb.w);
            }
        }

        if (t + 1 < NT / 64) {
            pf_l2(bp + 64 + 16 * c);
            pf_l2(bp + (size_t)8 * NT + 64 + 16 * c);
        }

        float rm0 = -1e30f, rm1 = -1e30f;
#pragma unroll
        for (int j = 0; j < 8; j++) {
            rm0 = fmaxf(rm0, fmaxf(s[j][0], s[j][1]));
            rm1 = fmaxf(rm1, fmaxf(s[j][2], s[j][3]));
        }
        rm0 = fmaxf(rm0, __shfl_xor_sync(0xffffffffu, rm0, 1));
        rm0 = fmaxf(rm0, __shfl_xor_sync(0xffffffffu, rm0, 2));
        rm1 = fmaxf(rm1, __shfl_xor_sync(0xffffffffu, rm1, 1));
        rm1 = fmaxf(rm1, __shfl_xor_sync(0xffffffffu, rm1, 2));

        if (__any_sync(0xffffffffu, (rm0 > mr0) || (rm1 > mr1))) {
            float mn0 = fmaxf(mr0, rm0), mn1 = fmaxf(mr1, rm1);
            float corr0 = fexp(mr0 - mn0), corr1 = fexp(mr1 - mn1);
            mr0 = mn0; mr1 = mn1;
            lr0 *= corr0; lr1 *= corr1;
#pragma unroll
            for (int j = 0; j < 8; j++) {
                o[j][0] *= corr0; o[j][1] *= corr0;
                o[j][2] *= corr1; o[j][3] *= corr1;
            }
        }

        float sum0 = 0.f, sum1 = 0.f;
#pragma unroll
        for (int j = 0; j < 8; j++) {
            s[j][0] = fexp(s[j][0] - mr0);
            s[j][1] = fexp(s[j][1] - mr0);
            s[j][2] = fexp(s[j][2] - mr1);
            s[j][3] = fexp(s[j][3] - mr1);
            sum0 += s[j][0] + s[j][1];
            sum1 += s[j][2] + s[j][3];
        }
        sum0 += __shfl_xor_sync(0xffffffffu, sum0, 1);
        sum0 += __shfl_xor_sync(0xffffffffu, sum0, 2);
        sum1 += __shfl_xor_sync(0xffffffffu, sum1, 1);
        sum1 += __shfl_xor_sync(0xffffffffu, sum1, 2);
        lr0 += sum0;
        lr1 += sum1;

#pragma unroll
        for (int tkp = 0; tkp < 2; tkp++) {
            uint32_t a00 = h2u(s[4 * tkp + 0][0], s[4 * tkp + 0][1]);
            uint32_t a01 = h2u(s[4 * tkp + 0][2], s[4 * tkp + 0][3]);
            uint32_t a02 = h2u(s[4 * tkp + 1][0], s[4 * tkp + 1][1]);
            uint32_t a03 = h2u(s[4 * tkp + 1][2], s[4 * tkp + 1][3]);
            uint32_t a10 = h2u(s[4 * tkp + 2][0], s[4 * tkp + 2][1]);
            uint32_t a11 = h2u(s[4 * tkp + 2][2], s[4 * tkp + 2][3]);
            uint32_t a12 = h2u(s[4 * tkp + 3][0], s[4 * tkp + 3][1]);
            uint32_t a13 = h2u(s[4 * tkp + 3][2], s[4 * tkp + 3][3]);
#pragma unroll
            for (int j = 0; j < 8; j++) {
                uint4 vb = *(const uint4*)(Vsb + (8 * j + g) * 128 + c * 16 + ((tkp << 6) ^ swz));
                mma16(o[j], a00, a01, a02, a03, vb.x, vb.y);
                mma16(o[j], a10, a11, a12, a13, vb.z, vb.w);
            }
        }
    }

    // epilogue: write packed fp16 (Wo GEMM consumes it as A operand)
    float inv0 = 1.0f / lr0, inv1 = 1.0f / lr1;
    const int grow0 = q0 + r0;
#pragma unroll
    for (int j = 0; j < 8; j++) {
        int col = h * HD + 8 * j + 2 * c;
        size_t p = (size_t)grow0 * DM + (col & ~15) + ppos(col & 15);
        *(uint32_t*)&O16[p]                  = h2u(o[j][0] * inv0, o[j][1] * inv0);
        *(uint32_t*)&O16[p + (size_t)8 * DM] = h2u(o[j][2] * inv1, o[j][3] * inv1);
    }
}

// ---------------- warp-per-row residual + LayerNorm -------------------------
template <bool PACK>
__global__ __launch_bounds__(256) void add_ln(
    const float* __restrict__ A, const float* __restrict__ B,
    const float* __restrict__ g, const float* __restrict__ be,
    float* __restrict__ out, __half* __restrict__ out16)
{
    const int row = blockIdx.x * 8 + (threadIdx.x >> 5);
    const int lane = threadIdx.x & 31;
    const float* ap = A + (size_t)row * DM;
    const float* bp = B + (size_t)row * DM;

    float4 v[4];
    float s = 0.f;
#pragma unroll
    for (int i = 0; i < 4; i++) {
        int col = (i * 32 + lane) * 4;
        float4 a = *(const float4*)(ap + col);
        float4 b = *(const float4*)(bp + col);
        v[i] = make_float4(a.x + b.x, a.y + b.y, a.z + b.z, a.w + b.w);
        s += v[i].x + v[i].y + v[i].z + v[i].w;
    }
#pragma unroll
    for (int off = 16; off; off >>= 1) s += __shfl_xor_sync(0xffffffffu, s, off);
    float mu = s * (1.f / DM);

    float sq = 0.f;
#pragma unroll
    for (int i = 0; i < 4; i++) {
        v[i].x -= mu; v[i].y -= mu; v[i].z -= mu; v[i].w -= mu;
        sq += v[i].x * v[i].x + v[i].y * v[i].y + v[i].z * v[i].z + v[i].w * v[i].w;
    }
#pragma unroll
    for (int off = 16; off; off >>= 1) sq += __shfl_xor_sync(0xffffffffu, sq, off);
    float inv = rsqrtf(sq * (1.f / DM) + 1e-5f);

#pragma unroll
    for (int i = 0; i < 4; i++) {
        int col = (i * 32 + lane) * 4;
        float4 gg = *(const float4*)(g + col);
        float4 bb = *(const float4*)(be + col);
        float4 r;
        r.x = v[i].x * inv * gg.x + bb.x;
        r.y = v[i].y * inv * gg.y + bb.y;
        r.z = v[i].z * inv * gg.z + bb.z;
        r.w = v[i].w * inv * gg.w + bb.w;
        *(float4*)(out + (size_t)row * DM + col) = r;
        if (PACK) {
            size_t base = (size_t)row * DM + (col & ~15);
            *(uint32_t*)&out16[base + ppos(col & 15)]       = h2u(r.x, r.y);
            *(uint32_t*)&out16[base + ppos((col + 2) & 15)] = h2u(r.z, r.w);
        }
    }
}

// ---------------- launch ----------------------------------------------------
extern "C" void kernel_launch(void* const* d_in, const int* in_sizes, int n_in,
                              void* d_out, int out_size)
{
    const float* x    = (const float*)d_in[0];
    const float* bias = (const float*)d_in[1];
    const float* Wq = (const float*)d_in[2];  const float* bq = (const float*)d_in[3];
    const float* Wk = (const float*)d_in[4];  const float* bk = (const float*)d_in[5];
    const float* Wv = (const float*)d_in[6];  const float* bv = (const float*)d_in[7];
    const float* Wo = (const float*)d_in[8];  const float* bo = (const float*)d_in[9];
    const float* g1 = (const float*)d_in[10]; const float* b1 = (const float*)d_in[11];
    const float* g2 = (const float*)d_in[12]; const float* b2 = (const float*)d_in[13];
    const float* W1 = (const float*)d_in[14]; const float* c1 = (const float*)d_in[15];
    const float* W2 = (const float*)d_in[16]; const float* c2 = (const float*)d_in[17];
    float* out = (float*)d_out;

    __half *Qp, *Kp, *Vp, *x16p, *attn16p, *x116p, *hid16p;
    __half *WqT, *WkT, *WvT, *WoT, *W1T, *W2T;
    float *tmpp, *x1p;
    cudaGetSymbolAddress((void**)&Qp,     g_Q);
    cudaGetSymbolAddress((void**)&Kp,     g_K);
    cudaGetSymbolAddress((void**)&Vp,     g_V);
    cudaGetSymbolAddress((void**)&x16p,   g_x16);
    cudaGetSymbolAddress((void**)&attn16p, g_attn16);
    cudaGetSymbolAddress((void**)&x116p,  g_x116);
    cudaGetSymbolAddress((void**)&hid16p, g_hid16);
    cudaGetSymbolAddress((void**)&tmpp,   g_tmp);
    cudaGetSymbolAddress((void**)&x1p,    g_x1);
    cudaGetSymbolAddress((void**)&WqT,    g_WqT);
    cudaGetSymbolAddress((void**)&WkT,    g_WkT);
    cudaGetSymbolAddress((void**)&WvT,    g_WvT);
    cudaGetSymbolAddress((void**)&WoT,    g_WoT);
    cudaGetSymbolAddress((void**)&W1T,    g_W1T);
    cudaGetSymbolAddress((void**)&W2T,    g_W2T);

    const int ATTN_SMEM = 49152;
    cudaFuncSetAttribute(attn_h, cudaFuncAttributeMaxDynamicSharedMemorySize, ATTN_SMEM);

    pack_x<<<NT * DM / 16 / 256, 256>>>(x, x16p);
    transpose_all<<<dim3(DFF / 32, DFF / 32, 6), 256>>>(
        Wq, Wk, Wv, Wo, W1, W2, WqT, WkT, WvT, WoT, W1T, W2T);

    dim3 blk(256);
    qkv16<<<dim3(DM / 128, NT / 64, 3), blk>>>(
        x16p, WqT, bq, Qp, WkT, bk, Kp, WvT, bv, Vp);

    attn_h<<<dim3(NT / 128, NH), blk, ATTN_SMEM>>>(Qp, Kp, Vp, bias, attn16p);

    gemm16<0><<<dim3(DM / 128, NT / 64), blk>>>(attn16p, WoT, bo, tmpp, DM, DM);
    add_ln<true><<<NT / 8, 256>>>(x, tmpp, g1, b1, x1p, x116p);

    gemm16<1><<<dim3(DFF / 128, NT / 64), blk>>>(x116p, W1T, c1, hid16p, DFF, DM);
    gemm16<0><<<dim3(DM / 128, NT / 64), blk>>>(hid16p, W2T, c2, tmpp, DM, DFF);
    add_ln<false><<<NT / 8, 256>>>(x1p, tmpp, g2, b2, out, nullptr);
}

// round 10
// speedup vs baseline: 6.0012x; 1.0258x over previous
#include <cuda_runtime.h>
#include <cuda_fp16.h>
#include <math.h>
#include <stdint.h>

#define NT  4096
#define DM  512
#define NH  8
#define HD  64
#define DFF 1024

// ---------------- scratch (static device globals; no allocations) ----------
__device__ __half g_Q[NT * DM];      // fp16, 0.125-prescaled, pk16-packed
__device__ __half g_K[NT * DM];      // fp16, tile-contiguous packed (khalf_idx)
__device__ __half g_V[NT * DM];      // fp16, tile-contiguous packed (vhalf_idx)
__device__ __half g_x16[NT * DM];    // x packed fp16 (QKV GEMM A operand)
__device__ __half g_attn16[NT * DM]; // attention out packed fp16 (Wo A operand)
__device__ __half g_x116[NT * DM];   // LN1 out packed fp16 (W1 A operand)
__device__ __half g_hid16[NT * DFF]; // FF1 out packed fp16 (W2 A operand)
__device__ float  g_tmp[NT * DM];
__device__ float  g_x1[NT * DM];
// transposed fp16 weights, pk16-packed along k (B operands)
__device__ __half g_WqT[DM * DM];
__device__ __half g_WkT[DM * DM];
__device__ __half g_WvT[DM * DM];
__device__ __half g_WoT[DM * DM];
__device__ __half g_W1T[DFF * DM];
__device__ __half g_W2T[DM * DFF];

#define LOG2E 1.4426950408889634f

// ---------------- helpers ---------------------------------------------------
// pk16: within each 16-element k group, order (0,1,8,9),(2,3,10,11),(4,5,12,13),(6,7,14,15)
__host__ __device__ __forceinline__ int ppos(int r) {
    return ((r & 7) >> 1) * 4 + ((r >> 3) & 1) * 2 + (r & 1);
}

__device__ __forceinline__ size_t khalf_idx(int h, int tok, int dim) {
    int tl = tok & 63;
    int r = dim & 15;
    int c = (r >> 1) & 3, q = ((r >> 3) & 1) * 2 + (r & 1);
    int kkl = (dim >> 4) & 1, kkp = (dim >> 5) & 1;
    return (size_t)h * NT * 64 + (size_t)(tok >> 6) * 4096
         + tl * 64 + ((kkp ^ (tl & 1)) << 5) + c * 8 + kkl * 4 + q;
}
__device__ __forceinline__ size_t vhalf_idx(int h, int tok, int n) {
    int r = tok & 15;
    int c = (r >> 1) & 3, q = ((r >> 3) & 1) * 2 + (r & 1);
    int tkl = (tok >> 4) & 1, tkp = (tok >> 5) & 1;
    return (size_t)h * NT * 64 + (size_t)(tok >> 6) * 4096
         + n * 64 + ((tkp ^ (n & 1)) << 5) + c * 8 + tkl * 4 + q;
}

__device__ __forceinline__ uint32_t h2u(float lo, float hi) {
    uint32_t r;
    asm("cvt.rn.f16x2.f32 %0, %1, %2;" : "=r"(r) : "f"(hi), "f"(lo));
    return r;
}

__device__ __forceinline__ uint32_t ex2h2(uint32_t y) {
    uint32_t r;
    asm("ex2.approx.f16x2 %0, %1;" : "=r"(r) : "r"(y));
    return r;
}

__device__ __forceinline__ void mma16(float d[4],
                                      uint32_t a0, uint32_t a1, uint32_t a2, uint32_t a3,
                                      uint32_t b0, uint32_t b1) {
    asm("mma.sync.aligned.m16n8k16.row.col.f32.f16.f16.f32 "
        "{%0,%1,%2,%3}, {%4,%5,%6,%7}, {%8,%9}, {%0,%1,%2,%3};"
        : "+f"(d[0]), "+f"(d[1]), "+f"(d[2]), "+f"(d[3])
        : "r"(a0), "r"(a1), "r"(a2), "r"(a3), "r"(b0), "r"(b1));
}

__device__ __forceinline__ void cpa16(unsigned dst, const void* src) {
    asm volatile("cp.async.cg.shared.global [%0], [%1], 16;" :: "r"(dst), "l"(src));
}
__device__ __forceinline__ void pf_l2(const void* p) {
    asm volatile("prefetch.global.L2 [%0];" :: "l"(p));
}

__device__ __forceinline__ float fexp(float x) {
    float r;
    float y = x * LOG2E;
    asm("ex2.approx.f32 %0, %1;" : "=f"(r) : "f"(y));
    return r;
}

// ==================== fp16 GEMM, all-cp.async, 64x128 tile, 3-stage ========
template <int MODE>   // 0: fp32 out + bias; 1: bias + relu -> fp16 pk16 out
__global__ __launch_bounds__(256) void gemm16(
    const __half* __restrict__ A16, const __half* __restrict__ Bt,
    const float* __restrict__ bias, void* __restrict__ Cout, int N, int K)
{
    __shared__ __align__(16) char smem[3 * 12288];
    const int tid = threadIdx.x;
    const int wid = tid >> 5, lane = tid & 31;
    const int g = lane >> 2, c = lane & 3;
    const int wm = (wid >> 2) * 32, wn = (wid & 3) * 32;
    const int m0 = blockIdx.y * 64, n0 = blockIdx.x * 128;
    const unsigned sb = (unsigned)__cvta_generic_to_shared(smem);

    float acc[2][4][4];
#pragma unroll
    for (int t = 0; t < 2; t++)
#pragma unroll
        for (int j = 0; j < 4; j++)
#pragma unroll
            for (int r = 0; r < 4; r++) acc[t][j][r] = 0.f;

    const int arow = tid >> 2, apart = tid & 3;
    const unsigned adst = arow * 64 +
        (((apart >> 1) ^ ((arow >> 1) & 1)) << 5) + (apart & 1) * 16;

    auto stage = [&](int kb, int st) {
        unsigned s0 = sb + st * 12288;
        cpa16(s0 + adst, A16 + (size_t)(m0 + arow) * K + kb * 32 + apart * 8);
#pragma unroll
        for (int i = 0; i < 2; i++) {
            int idx = i * 256 + tid;
            int n = idx >> 2, sub = idx & 3;
            int kk = sub >> 1, part = sub & 1;
            cpa16(s0 + 4096 + kk * 4096 + n * 32 + part * 16,
                  Bt + (size_t)(n0 + n) * K + kb * 32 + kk * 16 + part * 8);
        }
        asm volatile("cp.async.commit_group;" ::: "memory");
    };

    const int nk = K >> 5;
    stage(0, 0);
    stage(1, 1);
    const int aswz = (g >> 1) & 1;

    for (int kb = 0; kb < nk; kb++) {
        if (kb + 1 < nk) {
            asm volatile("cp.async.wait_group 1;" ::: "memory");
        } else {
            asm volatile("cp.async.wait_group 0;" ::: "memory");
        }
        __syncthreads();
        if (kb + 2 < nk) stage(kb + 2, (kb + 2) % 3);

        const char* aB = smem + (kb % 3) * 12288;
        const char* bB = aB + 4096;
#pragma unroll
        for (int kk = 0; kk < 2; kk++) {
            const int ko = ((kk ^ aswz) << 5) + c * 8;
            uint32_t af[2][4];
#pragma unroll
            for (int t = 0; t < 2; t++) {
                uint2 r0 = *(const uint2*)(aB + (wm + 16 * t + g) * 64 + ko);
                uint2 r1 = *(const uint2*)(aB + (wm + 16 * t + g + 8) * 64 + ko);
                af[t][0] = r0.x; af[t][1] = r1.x; af[t][2] = r0.y; af[t][3] = r1.y;
            }
#pragma unroll
            for (int j = 0; j < 4; j++) {
                uint2 bv = *(const uint2*)(bB + kk * 4096 + (wn + 8 * j + g) * 32 + c * 8);
#pragma unroll
                for (int t = 0; t < 2; t++)
                    mma16(acc[t][j], af[t][0], af[t][1], af[t][2], af[t][3], bv.x, bv.y);
            }
        }
        __syncthreads();
    }

#pragma unroll
    for (int t = 0; t < 2; t++) {
        int row0 = m0 + wm + 16 * t + g;
#pragma unroll
        for (int j = 0; j < 4; j++) {
            int col = n0 + wn + 8 * j + 2 * c;
            float2 bv = *(const float2*)&bias[col];
            float v00 = acc[t][j][0] + bv.x, v01 = acc[t][j][1] + bv.y;
            float v10 = acc[t][j][2] + bv.x, v11 = acc[t][j][3] + bv.y;
            if (MODE == 0) {
                float* C = (float*)Cout;
                *(float2*)&C[(size_t)row0 * N + col]       = make_float2(v00, v01);
                *(float2*)&C[(size_t)(row0 + 8) * N + col] = make_float2(v10, v11);
            } else {
                v00 = fmaxf(v00, 0.f); v01 = fmaxf(v01, 0.f);
                v10 = fmaxf(v10, 0.f); v11 = fmaxf(v11, 0.f);
                __half* C = (__half*)Cout;
                size_t p = (size_t)row0 * N + (col & ~15) + ppos(col & 15);
                *(uint32_t*)&C[p]                   = h2u(v00, v01);
                *(uint32_t*)&C[p + (size_t)8 * N]   = h2u(v10, v11);
            }
        }
    }
}

// ---------------- fused QKV GEMM (A fp16), z selects projection -------------
__global__ __launch_bounds__(256) void qkv16(
    const __half* __restrict__ x16,
    const __half* __restrict__ WqT, const float* __restrict__ bq, __half* __restrict__ Qo,
    const __half* __restrict__ WkT, const float* __restrict__ bk, __half* __restrict__ Ko,
    const __half* __restrict__ WvT, const float* __restrict__ bv, __half* __restrict__ Vo)
{
    __shared__ __align__(16) char smem[3 * 12288];
    const int z = blockIdx.z;
    const __half* Bt   = (z == 0) ? WqT : (z == 1) ? WkT : WvT;
    const float*  bias = (z == 0) ? bq  : (z == 1) ? bk  : bv;

    const int tid = threadIdx.x;
    const int wid = tid >> 5, lane = tid & 31;
    const int g = lane >> 2, c = lane & 3;
    const int wm = (wid >> 2) * 32, wn = (wid & 3) * 32;
    const int m0 = blockIdx.y * 64, n0 = blockIdx.x * 128;
    const unsigned sb = (unsigned)__cvta_generic_to_shared(smem);

    float acc[2][4][4];
#pragma unroll
    for (int t = 0; t < 2; t++)
#pragma unroll
        for (int j = 0; j < 4; j++)
#pragma unroll
            for (int r = 0; r < 4; r++) acc[t][j][r] = 0.f;

    const int arow = tid >> 2, apart = tid & 3;
    const unsigned adst = arow * 64 +
        (((apart >> 1) ^ ((arow >> 1) & 1)) << 5) + (apart & 1) * 16;

    auto stage = [&](int kb, int st) {
        unsigned s0 = sb + st * 12288;
        cpa16(s0 + adst, x16 + (size_t)(m0 + arow) * DM + kb * 32 + apart * 8);
#pragma unroll
        for (int i = 0; i < 2; i++) {
            int idx = i * 256 + tid;
            int n = idx >> 2, sub = idx & 3;
            int kk = sub >> 1, part = sub & 1;
            cpa16(s0 + 4096 + kk * 4096 + n * 32 + part * 16,
                  Bt + (size_t)(n0 + n) * DM + kb * 32 + kk * 16 + part * 8);
        }
        asm volatile("cp.async.commit_group;" ::: "memory");
    };

    const int nk = DM >> 5;
    stage(0, 0);
    stage(1, 1);
    const int aswz = (g >> 1) & 1;

    for (int kb = 0; kb < nk; kb++) {
        if (kb + 1 < nk) {
            asm volatile("cp.async.wait_group 1;" ::: "memory");
        } else {
            asm volatile("cp.async.wait_group 0;" ::: "memory");
        }
        __syncthreads();
        if (kb + 2 < nk) stage(kb + 2, (kb + 2) % 3);

        const char* aB = smem + (kb % 3) * 12288;
        const char* bB = aB + 4096;
#pragma unroll
        for (int kk = 0; kk < 2; kk++) {
            const int ko = ((kk ^ aswz) << 5) + c * 8;
            uint32_t af[2][4];
#pragma unroll
            for (int t = 0; t < 2; t++) {
                uint2 r0 = *(const uint2*)(aB + (wm + 16 * t + g) * 64 + ko);
                uint2 r1 = *(const uint2*)(aB + (wm + 16 * t + g + 8) * 64 + ko);
                af[t][0] = r0.x; af[t][1] = r1.x; af[t][2] = r0.y; af[t][3] = r1.y;
            }
#pragma unroll
            for (int j = 0; j < 4; j++) {
                uint2 bv2 = *(const uint2*)(bB + kk * 4096 + (wn + 8 * j + g) * 32 + c * 8);
#pragma unroll
                for (int t = 0; t < 2; t++)
                    mma16(acc[t][j], af[t][0], af[t][1], af[t][2], af[t][3], bv2.x, bv2.y);
            }
        }
        __syncthreads();
    }

#pragma unroll
    for (int t = 0; t < 2; t++) {
        int row0 = m0 + wm + 16 * t + g;
#pragma unroll
        for (int j = 0; j < 4; j++) {
            int col = n0 + wn + 8 * j + 2 * c;
            float2 bvv = *(const float2*)&bias[col];
            float v00 = acc[t][j][0] + bvv.x, v01 = acc[t][j][1] + bvv.y;
            float v10 = acc[t][j][2] + bvv.x, v11 = acc[t][j][3] + bvv.y;
            if (z == 0) {
                size_t p0 = (size_t)row0 * DM + (col & ~15) + ppos(col & 15);
                *(uint32_t*)&Qo[p0]                   = h2u(v00 * 0.125f, v01 * 0.125f);
                *(uint32_t*)&Qo[p0 + (size_t)8 * DM]  = h2u(v10 * 0.125f, v11 * 0.125f);
            } else if (z == 1) {
                int h = col >> 6, dl = col & 63;
                *(uint32_t*)&Ko[khalf_idx(h, row0,     dl)] = h2u(v00, v01);
                *(uint32_t*)&Ko[khalf_idx(h, row0 + 8, dl)] = h2u(v10, v11);
            } else {
                int h = col >> 6, dl = col & 63;
                Vo[vhalf_idx(h, row0,     dl)]     = __float2half_rn(v00);
                Vo[vhalf_idx(h, row0,     dl + 1)] = __float2half_rn(v01);
                Vo[vhalf_idx(h, row0 + 8, dl)]     = __float2half_rn(v10);
                Vo[vhalf_idx(h, row0 + 8, dl + 1)] = __float2half_rn(v11);
            }
        }
    }
}

// ---------------- pack x: fp32 [NT][DM] -> fp16 pk16 ------------------------
__global__ void __launch_bounds__(256) pack_x(
    const float* __restrict__ x, __half* __restrict__ o)
{
    int i = blockIdx.x * 256 + threadIdx.x;
    int row = i >> 5, grp = i & 31;
    const float* src = x + (size_t)row * DM + grp * 16;
    uint32_t u[8];
#pragma unroll
    for (int q = 0; q < 4; q++) {
        float4 v = *(const float4*)(src + q * 4);
        int d = q * 4;
        u[ppos(d) >> 1]     = h2u(v.x, v.y);
        u[ppos(d + 2) >> 1] = h2u(v.z, v.w);
    }
    __half* dst = o + (size_t)row * DM + grp * 16;
    *(uint4*)dst       = make_uint4(u[0], u[1], u[2], u[3]);
    *(uint4*)(dst + 8) = make_uint4(u[4], u[5], u[6], u[7]);
}

// ---------------- fused weight transpose: ONE launch for all 6 weights ------
__global__ void __launch_bounds__(256) transpose_all(
    const float* __restrict__ Wq, const float* __restrict__ Wk,
    const float* __restrict__ Wv, const float* __restrict__ Wo,
    const float* __restrict__ W1, const float* __restrict__ W2,
    __half* __restrict__ WqT, __half* __restrict__ WkT,
    __half* __restrict__ WvT, __half* __restrict__ WoT,
    __half* __restrict__ W1T, __half* __restrict__ W2T)
{
    __shared__ float t[32][33];
    const int z = blockIdx.z;
    const float* in; __half* outp; int K, N;
    switch (z) {
        case 0:  in = Wq; outp = WqT; K = DM;  N = DM;  break;
        case 1:  in = Wk; outp = WkT; K = DM;  N = DM;  break;
        case 2:  in = Wv; outp = WvT; K = DM;  N = DM;  break;
        case 3:  in = Wo; outp = WoT; K = DM;  N = DM;  break;
        case 4:  in = W1; outp = W1T; K = DM;  N = DFF; break;
        default: in = W2; outp = W2T; K = DFF; N = DM;  break;
    }
    const int n0 = blockIdx.x * 32, k0 = blockIdx.y * 32;
    if (n0 >= N || k0 >= K) return;
    const int tx = threadIdx.x & 31, ty = threadIdx.x >> 5;
#pragma unroll
    for (int i = 0; i < 4; i++)
        t[ty + 8 * i][tx] = in[(size_t)(k0 + ty + 8 * i) * N + n0 + tx];
    __syncthreads();
    if (tx < 16) {
#pragma unroll
        for (int i = 0; i < 4; i++) {
            int n = ty + 8 * i;
            int kl = 2 * tx;
            int pos = (kl & ~15) + ppos(kl & 15);
            *(uint32_t*)&outp[(size_t)(n0 + n) * K + k0 + pos] =
                h2u(t[kl][n], t[kl + 1][n]);
        }
    }
}

// ---------------- fp16 tensor-core flash attention --------------------------
// ex2.f16x2 softmax; row sums via tensor-core ones-mma; P frags built once.
__global__ __launch_bounds__(256, 2) void attn_h(
    const __half* __restrict__ Q, const __half* __restrict__ Kpk,
    const __half* __restrict__ Vpk, const float* __restrict__ bias,
    __half* __restrict__ O16)
{
    extern __shared__ char smc[];
    const int tid = threadIdx.x;
    const int lane = tid & 31;
    const int g = lane >> 2, c = lane & 3;
    const int h = blockIdx.y;
    const int q0 = blockIdx.x * 128;
    const int r0 = 16 * (tid >> 5) + g;
    const unsigned sbase = (unsigned)__cvta_generic_to_shared(smc);
    const uint32_t ONES2 = 0x3C003C00u;

    const float* bias0 = bias + ((size_t)h * NT + q0 + r0) * NT;
    pf_l2(bias0 + 16 * c);
    pf_l2(bias0 + (size_t)8 * NT + 16 * c);

    uint32_t qa[4][4];
    {
        const char* qp0 = (const char*)(Q + (size_t)(q0 + r0) * DM + h * HD);
        const char* qp1 = qp0 + (size_t)8 * DM * 2;
#pragma unroll
        for (int kk = 0; kk < 4; kk++) {
            uint2 t0 = *(const uint2*)(qp0 + kk * 32 + c * 8);
            uint2 t1 = *(const uint2*)(qp1 + kk * 32 + c * 8);
            qa[kk][0] = t0.x; qa[kk][1] = t1.x; qa[kk][2] = t0.y; qa[kk][3] = t1.y;
        }
    }

    float o[8][4];
#pragma unroll
    for (int j = 0; j < 8; j++)
#pragma unroll
        for (int r = 0; r < 4; r++) o[j][r] = 0.f;
    float lacc[4] = {0.f, 0.f, 0.f, 0.f};
    float mr0 = -1e30f, mr1 = -1e30f;

    const __half* kbase = Kpk + (size_t)h * NT * 64;
    const __half* vbase = Vpk + (size_t)h * NT * 64;

#pragma unroll
    for (int b = 0; b < 2; b++) {
        const char* ks = (const char*)(kbase + (size_t)b * 4096);
        const char* vs = (const char*)(vbase + (size_t)b * 4096);
        cpa16(sbase + b * 8192 + tid * 16,            ks + tid * 16);
        cpa16(sbase + b * 8192 + 4096 + tid * 16,     ks + 4096 + tid * 16);
        cpa16(sbase + 24576 + b * 8192 + tid * 16,    vs + tid * 16);
        cpa16(sbase + 24576 + b * 8192 + 4096 + tid * 16, vs + 4096 + tid * 16);
        asm volatile("cp.async.commit_group;" ::: "memory");
    }

    const int swz = (g & 1) << 6;

    for (int t = 0; t < NT / 64; t++) {
        const int buf = t % 3;
        if (t < NT / 64 - 1) {
            asm volatile("cp.async.wait_group 1;" ::: "memory");
        } else {
            asm volatile("cp.async.wait_group 0;" ::: "memory");
        }
        __syncthreads();

        if (t + 2 < NT / 64) {
            const int b2 = (t + 2) % 3;
            const char* ks = (const char*)(kbase + (size_t)(t + 2) * 4096);
            const char* vs = (const char*)(vbase + (size_t)(t + 2) * 4096);
            cpa16(sbase + b2 * 8192 + tid * 16,            ks + tid * 16);
            cpa16(sbase + b2 * 8192 + 4096 + tid * 16,     ks + 4096 + tid * 16);
            cpa16(sbase + 24576 + b2 * 8192 + tid * 16,    vs + tid * 16);
            cpa16(sbase + 24576 + b2 * 8192 + 4096 + tid * 16, vs + 4096 + tid * 16);
            asm volatile("cp.async.commit_group;" ::: "memory");
        }

        const char* Ksb = smc + buf * 8192;
        const char* Vsb = smc + 24576 + buf * 8192;

        // ---- S = Q@K^T + bias ----------------------------------------------
        float s[8][4];
        const float* bp = bias0 + t * 64;
#pragma unroll
        for (int j = 0; j < 8; j++) {
            float2 b0 = __ldcs((const float2*)(bp + 8 * j + 2 * c));
            float2 b1 = __ldcs((const float2*)(bp + (size_t)8 * NT + 8 * j + 2 * c));
            s[j][0] = b0.x; s[j][1] = b0.y; s[j][2] = b1.x; s[j][3] = b1.y;
        }
#pragma unroll
        for (int kkp = 0; kkp < 2; kkp++) {
#pragma unroll
            for (int j = 0; j < 8; j++) {
                uint4 kb = *(const uint4*)(Ksb + (8 * j + g) * 128 + c * 16 + ((kkp << 6) ^ swz));
                mma16(s[j], qa[2 * kkp][0], qa[2 * kkp][1], qa[2 * kkp][2], qa[2 * kkp][3], kb.x, kb.y);
                mma16(s[j], qa[2 * kkp + 1][0], qa[2 * kkp + 1][1], qa[2 * kkp + 1][2], qa[2 * kkp + 1][3], kb.z, kb.w);
            }
        }

        if (t + 1 < NT / 64) {
            pf_l2(bp + 64 + 16 * c);
            pf_l2(bp + (size_t)8 * NT + 64 + 16 * c);
        }

        // ---- row max (c-group reduce) ---------------------------------------
        float rm0 = -1e30f, rm1 = -1e30f;
#pragma unroll
        for (int j = 0; j < 8; j++) {
            rm0 = fmaxf(rm0, fmaxf(s[j][0], s[j][1]));
            rm1 = fmaxf(rm1, fmaxf(s[j][2], s[j][3]));
        }
        rm0 = fmaxf(rm0, __shfl_xor_sync(0xffffffffu, rm0, 1));
        rm0 = fmaxf(rm0, __shfl_xor_sync(0xffffffffu, rm0, 2));
        rm1 = fmaxf(rm1, __shfl_xor_sync(0xffffffffu, rm1, 1));
        rm1 = fmaxf(rm1, __shfl_xor_sync(0xffffffffu, rm1, 2));

        if (__any_sync(0xffffffffu, (rm0 > mr0) || (rm1 > mr1))) {
            float mn0 = fmaxf(mr0, rm0), mn1 = fmaxf(mr1, rm1);
            float corr0 = fexp(mr0 - mn0), corr1 = fexp(mr1 - mn1);
            mr0 = mn0; mr1 = mn1;
            lacc[0] *= corr0; lacc[1] *= corr0;
            lacc[2] *= corr1; lacc[3] *= corr1;
#pragma unroll
            for (int j = 0; j < 8; j++) {
                o[j][0] *= corr0; o[j][1] *= corr0;
                o[j][2] *= corr1; o[j][3] *= corr1;
            }
        }

        // ---- P = exp(S - m) directly as fp16x2 PV A-fragments --------------
        const float mlog0 = mr0 * LOG2E, mlog1 = mr1 * LOG2E;
        uint32_t pf[8][2];
#pragma unroll
        for (int j = 0; j < 8; j++) {
            float y00 = fmaf(s[j][0], LOG2E, -mlog0);
            float y01 = fmaf(s[j][1], LOG2E, -mlog0);
            float y10 = fmaf(s[j][2], LOG2E, -mlog1);
            float y11 = fmaf(s[j][3], LOG2E, -mlog1);
            pf[j][0] = ex2h2(h2u(y00, y01));
            pf[j][1] = ex2h2(h2u(y10, y11));
        }

        // ---- O += P @ V ; l += P @ ones (tensor-core row sums) -------------
#pragma unroll
        for (int tkp = 0; tkp < 2; tkp++) {
            uint32_t a00 = pf[4 * tkp + 0][0], a01 = pf[4 * tkp + 0][1];
            uint32_t a02 = pf[4 * tkp + 1][0], a03 = pf[4 * tkp + 1][1];
            uint32_t a10 = pf[4 * tkp + 2][0], a11 = pf[4 * tkp + 2][1];
            uint32_t a12 = pf[4 * tkp + 3][0], a13 = pf[4 * tkp + 3][1];
            mma16(lacc, a00, a01, a02, a03, ONES2, ONES2);
            mma16(lacc, a10, a11, a12, a13, ONES2, ONES2);
#pragma unroll
            for (int j = 0; j < 8; j++) {
                uint4 vb = *(const uint4*)(Vsb + (8 * j + g) * 128 + c * 16 + ((tkp << 6) ^ swz));
                mma16(o[j], a00, a01, a02, a03, vb.x, vb.y);
                mma16(o[j], a10, a11, a12, a13, vb.z, vb.w);
            }
        }
    }

    // epilogue: write packed fp16 (Wo GEMM consumes it as A operand)
    float inv0 = 1.0f / lacc[0], inv1 = 1.0f / lacc[2];
    const int grow0 = q0 + r0;
#pragma unroll
    for (int j = 0; j < 8; j++) {
        int col = h * HD + 8 * j + 2 * c;
        size_t p = (size_t)grow0 * DM + (col & ~15) + ppos(col & 15);
        *(uint32_t*)&O16[p]                  = h2u(o[j][0] * inv0, o[j][1] * inv0);
        *(uint32_t*)&O16[p + (size_t)8 * DM] = h2u(o[j][2] * inv1, o[j][3] * inv1);
    }
}

// ---------------- warp-per-row residual + LayerNorm -------------------------
template <bool PACK>
__global__ __launch_bounds__(256) void add_ln(
    const float* __restrict__ A, const float* __restrict__ B,
    const float* __restrict__ g, const float* __restrict__ be,
    float* __restrict__ out, __half* __restrict__ out16)
{
    const int row = blockIdx.x * 8 + (threadIdx.x >> 5);
    const int lane = threadIdx.x & 31;
    const float* ap = A + (size_t)row * DM;
    const float* bp = B + (size_t)row * DM;

    float4 v[4];
    float s = 0.f;
#pragma unroll
    for (int i = 0; i < 4; i++) {
        int col = (i * 32 + lane) * 4;
        float4 a = *(const float4*)(ap + col);
        float4 b = *(const float4*)(bp + col);
        v[i] = make_float4(a.x + b.x, a.y + b.y, a.z + b.z, a.w + b.w);
        s += v[i].x + v[i].y + v[i].z + v[i].w;
    }
#pragma unroll
    for (int off = 16; off; off >>= 1) s += __shfl_xor_sync(0xffffffffu, s, off);
    float mu = s * (1.f / DM);

    float sq = 0.f;
#pragma unroll
    for (int i = 0; i < 4; i++) {
        v[i].x -= mu; v[i].y -= mu; v[i].z -= mu; v[i].w -= mu;
        sq += v[i].x * v[i].x + v[i].y * v[i].y + v[i].z * v[i].z + v[i].w * v[i].w;
    }
#pragma unroll
    for (int off = 16; off; off >>= 1) sq += __shfl_xor_sync(0xffffffffu, sq, off);
    float inv = rsqrtf(sq * (1.f / DM) + 1e-5f);

#pragma unroll
    for (int i = 0; i < 4; i++) {
        int col = (i * 32 + lane) * 4;
        float4 gg = *(const float4*)(g + col);
        float4 bb = *(const float4*)(be + col);
        float4 r;
        r.x = v[i].x * inv * gg.x + bb.x;
        r.y = v[i].y * inv * gg.y + bb.y;
        r.z = v[i].z * inv * gg.z + bb.z;
        r.w = v[i].w * inv * gg.w + bb.w;
        *(float4*)(out + (size_t)row * DM + col) = r;
        if (PACK) {
            size_t base = (size_t)row * DM + (col & ~15);
            *(uint32_t*)&out16[base + ppos(col & 15)]       = h2u(r.x, r.y);
            *(uint32_t*)&out16[base + ppos((col + 2) & 15)] = h2u(r.z, r.w);
        }
    }
}

// ---------------- launch ----------------------------------------------------
extern "C" void kernel_launch(void* const* d_in, const int* in_sizes, int n_in,
                              void* d_out, int out_size)
{
    const float* x    = (const float*)d_in[0];
    const float* bias = (const float*)d_in[1];
    const float* Wq = (const float*)d_in[2];  const float* bq = (const float*)d_in[3];
    const float* Wk = (const float*)d_in[4];  const float* bk = (const float*)d_in[5];
    const float* Wv = (const float*)d_in[6];  const float* bv = (const float*)d_in[7];
    const float* Wo = (const float*)d_in[8];  const float* bo = (const float*)d_in[9];
    const float* g1 = (const float*)d_in[10]; const float* b1 = (const float*)d_in[11];
    const float* g2 = (const float*)d_in[12]; const float* b2 = (const float*)d_in[13];
    const float* W1 = (const float*)d_in[14]; const float* c1 = (const float*)d_in[15];
    const float* W2 = (const float*)d_in[16]; const float* c2 = (const float*)d_in[17];
    float* out = (float*)d_out;

    __half *Qp, *Kp, *Vp, *x16p, *attn16p, *x116p, *hid16p;
    __half *WqT, *WkT, *WvT, *WoT, *W1T, *W2T;
    float *tmpp, *x1p;
    cudaGetSymbolAddress((void**)&Qp,     g_Q);
    cudaGetSymbolAddress((void**)&Kp,     g_K);
    cudaGetSymbolAddress((void**)&Vp,     g_V);
    cudaGetSymbolAddress((void**)&x16p,   g_x16);
    cudaGetSymbolAddress((void**)&attn16p, g_attn16);
    cudaGetSymbolAddress((void**)&x116p,  g_x116);
    cudaGetSymbolAddress((void**)&hid16p, g_hid16);
    cudaGetSymbolAddress((void**)&tmpp,   g_tmp);
    cudaGetSymbolAddress((void**)&x1p,    g_x1);
    cudaGetSymbolAddress((void**)&WqT,    g_WqT);
    cudaGetSymbolAddress((void**)&WkT,    g_WkT);
    cudaGetSymbolAddress((void**)&WvT,    g_WvT);
    cudaGetSymbolAddress((void**)&WoT,    g_WoT);
    cudaGetSymbolAddress((void**)&W1T,    g_W1T);
    cudaGetSymbolAddress((void**)&W2T,    g_W2T);

    const int ATTN_SMEM = 49152;
    cudaFuncSetAttribute(attn_h, cudaFuncAttributeMaxDynamicSharedMemorySize, ATTN_SMEM);

    pack_x<<<NT * DM / 16 / 256, 256>>>(x, x16p);
    transpose_all<<<dim3(DFF / 32, DFF / 32, 6), 256>>>(
        Wq, Wk, Wv, Wo, W1, W2, WqT, WkT, WvT, WoT, W1T, W2T);

    dim3 blk(256);
    qkv16<<<dim3(DM / 128, NT / 64, 3), blk>>>(
        x16p, WqT, bq, Qp, WkT, bk, Kp, WvT, bv, Vp);

    attn_h<<<dim3(NT / 128, NH), blk, ATTN_SMEM>>>(Qp, Kp, Vp, bias, attn16p);

    gemm16<0><<<dim3(DM / 128, NT / 64), blk>>>(attn16p, WoT, bo, tmpp, DM, DM);
    add_ln<true><<<NT / 8, 256>>>(x, tmpp, g1, b1, x1p, x116p);

    gemm16<1><<<dim3(DFF / 128, NT / 64), blk>>>(x116p, W1T, c1, hid16p, DFF, DM);
    gemm16<0><<<dim3(DM / 128, NT / 64), blk>>>(hid16p, W2T, c2, tmpp, DM, DFF);
    add_ln<false><<<NT / 8, 256>>>(x1p, tmpp, g2, b2, out, nullptr);
}

// round 11
// speedup vs baseline: 7.1902x; 1.1981x over previous
#include <cuda_runtime.h>
#include <cuda_fp16.h>
#include <math.h>
#include <stdint.h>

#define NT  4096
#define DM  512
#define NH  8
#define HD  64
#define DFF 1024

// ---------------- scratch (static device globals; no allocations) ----------
__device__ __half g_Q[NT * DM];      // fp16, 0.125-prescaled, pk16-packed
__device__ __half g_K[NT * DM];      // fp16, tile-contiguous packed (khalf_idx)
__device__ __half g_V[NT * DM];      // fp16, tile-contiguous packed (vhalf_idx)
__device__ __half g_x16[NT * DM];    // x packed fp16 (QKV GEMM A operand)
__device__ __half g_attn16[NT * DM]; // attention out packed fp16 (Wo A operand)
__device__ __half g_x116[NT * DM];   // LN1 out packed fp16 (W1 A operand)
__device__ __half g_hid16[NT * DFF]; // FF1 out packed fp16 (W2 A operand)
__device__ float  g_tmp[NT * DM];
__device__ float  g_x1[NT * DM];
// transposed fp16 weights, pk16-packed along k (B operands)
__device__ __half g_WqT[DM * DM];
__device__ __half g_WkT[DM * DM];
__device__ __half g_WvT[DM * DM];
__device__ __half g_WoT[DM * DM];
__device__ __half g_W1T[DFF * DM];
__device__ __half g_W2T[DM * DFF];

#define LOG2E 1.4426950408889634f

// ---------------- helpers ---------------------------------------------------
__host__ __device__ __forceinline__ int ppos(int r) {
    return ((r & 7) >> 1) * 4 + ((r >> 3) & 1) * 2 + (r & 1);
}

__device__ __forceinline__ size_t khalf_idx(int h, int tok, int dim) {
    int tl = tok & 63;
    int r = dim & 15;
    int c = (r >> 1) & 3, q = ((r >> 3) & 1) * 2 + (r & 1);
    int kkl = (dim >> 4) & 1, kkp = (dim >> 5) & 1;
    return (size_t)h * NT * 64 + (size_t)(tok >> 6) * 4096
         + tl * 64 + ((kkp ^ (tl & 1)) << 5) + c * 8 + kkl * 4 + q;
}
__device__ __forceinline__ size_t vhalf_idx(int h, int tok, int n) {
    int r = tok & 15;
    int c = (r >> 1) & 3, q = ((r >> 3) & 1) * 2 + (r & 1);
    int tkl = (tok >> 4) & 1, tkp = (tok >> 5) & 1;
    return (size_t)h * NT * 64 + (size_t)(tok >> 6) * 4096
         + n * 64 + ((tkp ^ (n & 1)) << 5) + c * 8 + tkl * 4 + q;
}

__device__ __forceinline__ uint32_t h2u(float lo, float hi) {
    uint32_t r;
    asm("cvt.rn.f16x2.f32 %0, %1, %2;" : "=r"(r) : "f"(hi), "f"(lo));
    return r;
}

__device__ __forceinline__ uint32_t ex2h2(uint32_t y) {
    uint32_t r;
    asm("ex2.approx.f16x2 %0, %1;" : "=r"(r) : "r"(y));
    return r;
}

__device__ __forceinline__ void mma16(float d[4],
                                      uint32_t a0, uint32_t a1, uint32_t a2, uint32_t a3,
                                      uint32_t b0, uint32_t b1) {
    asm("mma.sync.aligned.m16n8k16.row.col.f32.f16.f16.f32 "
        "{%0,%1,%2,%3}, {%4,%5,%6,%7}, {%8,%9}, {%0,%1,%2,%3};"
        : "+f"(d[0]), "+f"(d[1]), "+f"(d[2]), "+f"(d[3])
        : "r"(a0), "r"(a1), "r"(a2), "r"(a3), "r"(b0), "r"(b1));
}

__device__ __forceinline__ void cpa16(unsigned dst, const void* src) {
    asm volatile("cp.async.cg.shared.global [%0], [%1], 16;" :: "r"(dst), "l"(src));
}

__device__ __forceinline__ float fexp(float x) {
    float r;
    float y = x * LOG2E;
    asm("ex2.approx.f32 %0, %1;" : "=f"(r) : "f"(y));
    return r;
}

// ==================== fp16 GEMM, all-cp.async, 64x128 tile, 3-stage ========
template <int MODE>   // 0: fp32 out + bias; 1: bias + relu -> fp16 pk16 out
__global__ __launch_bounds__(256) void gemm16(
    const __half* __restrict__ A16, const __half* __restrict__ Bt,
    const float* __restrict__ bias, void* __restrict__ Cout, int N, int K)
{
    __shared__ __align__(16) char smem[3 * 12288];
    const int tid = threadIdx.x;
    const int wid = tid >> 5, lane = tid & 31;
    const int g = lane >> 2, c = lane & 3;
    const int wm = (wid >> 2) * 32, wn = (wid & 3) * 32;
    const int m0 = blockIdx.y * 64, n0 = blockIdx.x * 128;
    const unsigned sb = (unsigned)__cvta_generic_to_shared(smem);

    float acc[2][4][4];
#pragma unroll
    for (int t = 0; t < 2; t++)
#pragma unroll
        for (int j = 0; j < 4; j++)
#pragma unroll
            for (int r = 0; r < 4; r++) acc[t][j][r] = 0.f;

    const int arow = tid >> 2, apart = tid & 3;
    const unsigned adst = arow * 64 +
        (((apart >> 1) ^ ((arow >> 1) & 1)) << 5) + (apart & 1) * 16;

    auto stage = [&](int kb, int st) {
        unsigned s0 = sb + st * 12288;
        cpa16(s0 + adst, A16 + (size_t)(m0 + arow) * K + kb * 32 + apart * 8);
#pragma unroll
        for (int i = 0; i < 2; i++) {
            int idx = i * 256 + tid;
            int n = idx >> 2, sub = idx & 3;
            int kk = sub >> 1, part = sub & 1;
            cpa16(s0 + 4096 + kk * 4096 + n * 32 + part * 16,
                  Bt + (size_t)(n0 + n) * K + kb * 32 + kk * 16 + part * 8);
        }
        asm volatile("cp.async.commit_group;" ::: "memory");
    };

    const int nk = K >> 5;
    stage(0, 0);
    stage(1, 1);
    const int aswz = (g >> 1) & 1;

    for (int kb = 0; kb < nk; kb++) {
        if (kb + 1 < nk) {
            asm volatile("cp.async.wait_group 1;" ::: "memory");
        } else {
            asm volatile("cp.async.wait_group 0;" ::: "memory");
        }
        __syncthreads();
        if (kb + 2 < nk) stage(kb + 2, (kb + 2) % 3);

        const char* aB = smem + (kb % 3) * 12288;
        const char* bB = aB + 4096;
#pragma unroll
        for (int kk = 0; kk < 2; kk++) {
            const int ko = ((kk ^ aswz) << 5) + c * 8;
            uint32_t af[2][4];
#pragma unroll
            for (int t = 0; t < 2; t++) {
                uint2 r0 = *(const uint2*)(aB + (wm + 16 * t + g) * 64 + ko);
                uint2 r1 = *(const uint2*)(aB + (wm + 16 * t + g + 8) * 64 + ko);
                af[t][0] = r0.x; af[t][1] = r1.x; af[t][2] = r0.y; af[t][3] = r1.y;
            }
#pragma unroll
            for (int j = 0; j < 4; j++) {
                uint2 bv = *(const uint2*)(bB + kk * 4096 + (wn + 8 * j + g) * 32 + c * 8);
#pragma unroll
                for (int t = 0; t < 2; t++)
                    mma16(acc[t][j], af[t][0], af[t][1], af[t][2], af[t][3], bv.x, bv.y);
            }
        }
        __syncthreads();
    }

#pragma unroll
    for (int t = 0; t < 2; t++) {
        int row0 = m0 + wm + 16 * t + g;
#pragma unroll
        for (int j = 0; j < 4; j++) {
            int col = n0 + wn + 8 * j + 2 * c;
            float2 bv = *(const float2*)&bias[col];
            float v00 = acc[t][j][0] + bv.x, v01 = acc[t][j][1] + bv.y;
            float v10 = acc[t][j][2] + bv.x, v11 = acc[t][j][3] + bv.y;
            if (MODE == 0) {
                float* C = (float*)Cout;
                *(float2*)&C[(size_t)row0 * N + col]       = make_float2(v00, v01);
                *(float2*)&C[(size_t)(row0 + 8) * N + col] = make_float2(v10, v11);
            } else {
                v00 = fmaxf(v00, 0.f); v01 = fmaxf(v01, 0.f);
                v10 = fmaxf(v10, 0.f); v11 = fmaxf(v11, 0.f);
                __half* C = (__half*)Cout;
                size_t p = (size_t)row0 * N + (col & ~15) + ppos(col & 15);
                *(uint32_t*)&C[p]                   = h2u(v00, v01);
                *(uint32_t*)&C[p + (size_t)8 * N]   = h2u(v10, v11);
            }
        }
    }
}

// ---------------- fused QKV GEMM (A fp16), z selects projection -------------
__global__ __launch_bounds__(256) void qkv16(
    const __half* __restrict__ x16,
    const __half* __restrict__ WqT, const float* __restrict__ bq, __half* __restrict__ Qo,
    const __half* __restrict__ WkT, const float* __restrict__ bk, __half* __restrict__ Ko,
    const __half* __restrict__ WvT, const float* __restrict__ bv, __half* __restrict__ Vo)
{
    __shared__ __align__(16) char smem[3 * 12288];
    const int z = blockIdx.z;
    const __half* Bt   = (z == 0) ? WqT : (z == 1) ? WkT : WvT;
    const float*  bias = (z == 0) ? bq  : (z == 1) ? bk  : bv;

    const int tid = threadIdx.x;
    const int wid = tid >> 5, lane = tid & 31;
    const int g = lane >> 2, c = lane & 3;
    const int wm = (wid >> 2) * 32, wn = (wid & 3) * 32;
    const int m0 = blockIdx.y * 64, n0 = blockIdx.x * 128;
    const unsigned sb = (unsigned)__cvta_generic_to_shared(smem);

    float acc[2][4][4];
#pragma unroll
    for (int t = 0; t < 2; t++)
#pragma unroll
        for (int j = 0; j < 4; j++)
#pragma unroll
            for (int r = 0; r < 4; r++) acc[t][j][r] = 0.f;

    const int arow = tid >> 2, apart = tid & 3;
    const unsigned adst = arow * 64 +
        (((apart >> 1) ^ ((arow >> 1) & 1)) << 5) + (apart & 1) * 16;

    auto stage = [&](int kb, int st) {
        unsigned s0 = sb + st * 12288;
        cpa16(s0 + adst, x16 + (size_t)(m0 + arow) * DM + kb * 32 + apart * 8);
#pragma unroll
        for (int i = 0; i < 2; i++) {
            int idx = i * 256 + tid;
            int n = idx >> 2, sub = idx & 3;
            int kk = sub >> 1, part = sub & 1;
            cpa16(s0 + 4096 + kk * 4096 + n * 32 + part * 16,
                  Bt + (size_t)(n0 + n) * DM + kb * 32 + kk * 16 + part * 8);
        }
        asm volatile("cp.async.commit_group;" ::: "memory");
    };

    const int nk = DM >> 5;
    stage(0, 0);
    stage(1, 1);
    const int aswz = (g >> 1) & 1;

    for (int kb = 0; kb < nk; kb++) {
        if (kb + 1 < nk) {
            asm volatile("cp.async.wait_group 1;" ::: "memory");
        } else {
            asm volatile("cp.async.wait_group 0;" ::: "memory");
        }
        __syncthreads();
        if (kb + 2 < nk) stage(kb + 2, (kb + 2) % 3);

        const char* aB = smem + (kb % 3) * 12288;
        const char* bB = aB + 4096;
#pragma unroll
        for (int kk = 0; kk < 2; kk++) {
            const int ko = ((kk ^ aswz) << 5) + c * 8;
            uint32_t af[2][4];
#pragma unroll
            for (int t = 0; t < 2; t++) {
                uint2 r0 = *(const uint2*)(aB + (wm + 16 * t + g) * 64 + ko);
                uint2 r1 = *(const uint2*)(aB + (wm + 16 * t + g + 8) * 64 + ko);
                af[t][0] = r0.x; af[t][1] = r1.x; af[t][2] = r0.y; af[t][3] = r1.y;
            }
#pragma unroll
            for (int j = 0; j < 4; j++) {
                uint2 bv2 = *(const uint2*)(bB + kk * 4096 + (wn + 8 * j + g) * 32 + c * 8);
#pragma unroll
                for (int t = 0; t < 2; t++)
                    mma16(acc[t][j], af[t][0], af[t][1], af[t][2], af[t][3], bv2.x, bv2.y);
            }
        }
        __syncthreads();
    }

#pragma unroll
    for (int t = 0; t < 2; t++) {
        int row0 = m0 + wm + 16 * t + g;
#pragma unroll
        for (int j = 0; j < 4; j++) {
            int col = n0 + wn + 8 * j + 2 * c;
            float2 bvv = *(const float2*)&bias[col];
            float v00 = acc[t][j][0] + bvv.x, v01 = acc[t][j][1] + bvv.y;
            float v10 = acc[t][j][2] + bvv.x, v11 = acc[t][j][3] + bvv.y;
            if (z == 0) {
                size_t p0 = (size_t)row0 * DM + (col & ~15) + ppos(col & 15);
                *(uint32_t*)&Qo[p0]                   = h2u(v00 * 0.125f, v01 * 0.125f);
                *(uint32_t*)&Qo[p0 + (size_t)8 * DM]  = h2u(v10 * 0.125f, v11 * 0.125f);
            } else if (z == 1) {
                int h = col >> 6, dl = col & 63;
                *(uint32_t*)&Ko[khalf_idx(h, row0,     dl)] = h2u(v00, v01);
                *(uint32_t*)&Ko[khalf_idx(h, row0 + 8, dl)] = h2u(v10, v11);
            } else {
                int h = col >> 6, dl = col & 63;
                Vo[vhalf_idx(h, row0,     dl)]     = __float2half_rn(v00);
                Vo[vhalf_idx(h, row0,     dl + 1)] = __float2half_rn(v01);
                Vo[vhalf_idx(h, row0 + 8, dl)]     = __float2half_rn(v10);
                Vo[vhalf_idx(h, row0 + 8, dl + 1)] = __float2half_rn(v11);
            }
        }
    }
}

// ---------------- pack x: fp32 [NT][DM] -> fp16 pk16 ------------------------
__global__ void __launch_bounds__(256) pack_x(
    const float* __restrict__ x, __half* __restrict__ o)
{
    int i = blockIdx.x * 256 + threadIdx.x;
    int row = i >> 5, grp = i & 31;
    const float* src = x + (size_t)row * DM + grp * 16;
    uint32_t u[8];
#pragma unroll
    for (int q = 0; q < 4; q++) {
        float4 v = *(const float4*)(src + q * 4);
        int d = q * 4;
        u[ppos(d) >> 1]     = h2u(v.x, v.y);
        u[ppos(d + 2) >> 1] = h2u(v.z, v.w);
    }
    __half* dst = o + (size_t)row * DM + grp * 16;
    *(uint4*)dst       = make_uint4(u[0], u[1], u[2], u[3]);
    *(uint4*)(dst + 8) = make_uint4(u[4], u[5], u[6], u[7]);
}

// ---------------- fused weight transpose: ONE launch for all 6 weights ------
__global__ void __launch_bounds__(256) transpose_all(
    const float* __restrict__ Wq, const float* __restrict__ Wk,
    const float* __restrict__ Wv, const float* __restrict__ Wo,
    const float* __restrict__ W1, const float* __restrict__ W2,
    __half* __restrict__ WqT, __half* __restrict__ WkT,
    __half* __restrict__ WvT, __half* __restrict__ WoT,
    __half* __restrict__ W1T, __half* __restrict__ W2T)
{
    __shared__ float t[32][33];
    const int z = blockIdx.z;
    const float* in; __half* outp; int K, N;
    switch (z) {
        case 0:  in = Wq; outp = WqT; K = DM;  N = DM;  break;
        case 1:  in = Wk; outp = WkT; K = DM;  N = DM;  break;
        case 2:  in = Wv; outp = WvT; K = DM;  N = DM;  break;
        case 3:  in = Wo; outp = WoT; K = DM;  N = DM;  break;
        case 4:  in = W1; outp = W1T; K = DM;  N = DFF; break;
        default: in = W2; outp = W2T; K = DFF; N = DM;  break;
    }
    const int n0 = blockIdx.x * 32, k0 = blockIdx.y * 32;
    if (n0 >= N || k0 >= K) return;
    const int tx = threadIdx.x & 31, ty = threadIdx.x >> 5;
#pragma unroll
    for (int i = 0; i < 4; i++)
        t[ty + 8 * i][tx] = in[(size_t)(k0 + ty + 8 * i) * N + n0 + tx];
    __syncthreads();
    if (tx < 16) {
#pragma unroll
        for (int i = 0; i < 4; i++) {
            int n = ty + 8 * i;
            int kl = 2 * tx;
            int pos = (kl & ~15) + ppos(kl & 15);
            *(uint32_t*)&outp[(size_t)(n0 + n) * K + k0 + pos] =
                h2u(t[kl][n], t[kl + 1][n]);
        }
    }
}

// ---------------- fp16 tensor-core flash attention --------------------------
// K/V AND bias cp.async double-buffered; one wait+sync per tile; bias read
// from smem (288B row stride -> conflict-free LDS.64).
// stage = K 8KB | V 8KB | bias 36.864KB = 53248 B; two stages = 106496 B.
#define ASTG 53248
__global__ __launch_bounds__(256, 2) void attn_h(
    const __half* __restrict__ Q, const __half* __restrict__ Kpk,
    const __half* __restrict__ Vpk, const float* __restrict__ bias,
    __half* __restrict__ O16)
{
    extern __shared__ char smc[];
    const int tid = threadIdx.x;
    const int lane = tid & 31;
    const int g = lane >> 2, c = lane & 3;
    const int h = blockIdx.y;
    const int q0 = blockIdx.x * 128;
    const int r0 = 16 * (tid >> 5) + g;
    const unsigned sbase = (unsigned)__cvta_generic_to_shared(smc);
    const uint32_t ONES2 = 0x3C003C00u;

    uint32_t qa[4][4];
    {
        const char* qp0 = (const char*)(Q + (size_t)(q0 + r0) * DM + h * HD);
        const char* qp1 = qp0 + (size_t)8 * DM * 2;
#pragma unroll
        for (int kk = 0; kk < 4; kk++) {
            uint2 t0 = *(const uint2*)(qp0 + kk * 32 + c * 8);
            uint2 t1 = *(const uint2*)(qp1 + kk * 32 + c * 8);
            qa[kk][0] = t0.x; qa[kk][1] = t1.x; qa[kk][2] = t0.y; qa[kk][3] = t1.y;
        }
    }

    float o[8][4];
#pragma unroll
    for (int j = 0; j < 8; j++)
#pragma unroll
        for (int r = 0; r < 4; r++) o[j][r] = 0.f;
    float lacc[4] = {0.f, 0.f, 0.f, 0.f};
    float mr0 = -1e30f, mr1 = -1e30f;

    const __half* kbase = Kpk + (size_t)h * NT * 64;
    const __half* vbase = Vpk + (size_t)h * NT * 64;
    const float*  bbase = bias + ((size_t)h * NT + q0) * NT;

    // stage tile t into buffer t&1 : K, V, and 128x64 fp32 bias (stride 288B)
    auto stage = [&](int t) {
        const unsigned s0 = sbase + (t & 1) * ASTG;
        const char* ks = (const char*)(kbase + (size_t)t * 4096);
        const char* vs = (const char*)(vbase + (size_t)t * 4096);
        cpa16(s0 + tid * 16,         ks + tid * 16);
        cpa16(s0 + 4096 + tid * 16,  ks + 4096 + tid * 16);
        cpa16(s0 + 8192 + tid * 16,  vs + tid * 16);
        cpa16(s0 + 12288 + tid * 16, vs + 4096 + tid * 16);
        const float* bsrc = bbase + t * 64;
#pragma unroll
        for (int i = 0; i < 8; i++) {
            int idx = i * 256 + tid;
            int row = idx >> 4, cc = idx & 15;
            cpa16(s0 + 16384 + row * 288 + cc * 16,
                  bsrc + (size_t)row * NT + cc * 4);
        }
        asm volatile("cp.async.commit_group;" ::: "memory");
    };

    stage(0);
    const int swz = (g & 1) << 6;

    for (int t = 0; t < NT / 64; t++) {
        asm volatile("cp.async.wait_group 0;" ::: "memory");
        __syncthreads();              // tile t ready; tile t-1 buffers free
        if (t + 1 < NT / 64) stage(t + 1);   // overlaps with compute below

        const char* Ksb = smc + (t & 1) * ASTG;
        const char* Vsb = Ksb + 8192;
        const char* Bsb = Ksb + 16384;

        // ---- S = Q@K^T + bias (bias from smem) ------------------------------
        float s[8][4];
        const char* br0 = Bsb + r0 * 288 + 8 * c;
        const char* br1 = Bsb + (r0 + 8) * 288 + 8 * c;
#pragma unroll
        for (int j = 0; j < 8; j++) {
            float2 b0 = *(const float2*)(br0 + 32 * j);
            float2 b1 = *(const float2*)(br1 + 32 * j);
            s[j][0] = b0.x; s[j][1] = b0.y; s[j][2] = b1.x; s[j][3] = b1.y;
        }
#pragma unroll
        for (int kkp = 0; kkp < 2; kkp++) {
#pragma unroll
            for (int j = 0; j < 8; j++) {
                uint4 kb = *(const uint4*)(Ksb + (8 * j + g) * 128 + c * 16 + ((kkp << 6) ^ swz));
                mma16(s[j], qa[2 * kkp][0], qa[2 * kkp][1], qa[2 * kkp][2], qa[2 * kkp][3], kb.x, kb.y);
                mma16(s[j], qa[2 * kkp + 1][0], qa[2 * kkp + 1][1], qa[2 * kkp + 1][2], qa[2 * kkp + 1][3], kb.z, kb.w);
            }
        }

        // ---- row max (c-group reduce) ---------------------------------------
        float rm0 = -1e30f, rm1 = -1e30f;
#pragma unroll
        for (int j = 0; j < 8; j++) {
            rm0 = fmaxf(rm0, fmaxf(s[j][0], s[j][1]));
            rm1 = fmaxf(rm1, fmaxf(s[j][2], s[j][3]));
        }
        rm0 = fmaxf(rm0, __shfl_xor_sync(0xffffffffu, rm0, 1));
        rm0 = fmaxf(rm0, __shfl_xor_sync(0xffffffffu, rm0, 2));
        rm1 = fmaxf(rm1, __shfl_xor_sync(0xffffffffu, rm1, 1));
        rm1 = fmaxf(rm1, __shfl_xor_sync(0xffffffffu, rm1, 2));

        if (__any_sync(0xffffffffu, (rm0 > mr0) || (rm1 > mr1))) {
            float mn0 = fmaxf(mr0, rm0), mn1 = fmaxf(mr1, rm1);
            float corr0 = fexp(mr0 - mn0), corr1 = fexp(mr1 - mn1);
            mr0 = mn0; mr1 = mn1;
            lacc[0] *= corr0; lacc[1] *= corr0;
            lacc[2] *= corr1; lacc[3] *= corr1;
#pragma unroll
            for (int j = 0; j < 8; j++) {
                o[j][0] *= corr0; o[j][1] *= corr0;
                o[j][2] *= corr1; o[j][3] *= corr1;
            }
        }

        // ---- P = exp2(S*log2e - m*log2e) as fp16x2 PV A-fragments ----------
        const float mlog0 = mr0 * LOG2E, mlog1 = mr1 * LOG2E;
        uint32_t pf[8][2];
#pragma unroll
        for (int j = 0; j < 8; j++) {
            float y00 = fmaf(s[j][0], LOG2E, -mlog0);
            float y01 = fmaf(s[j][1], LOG2E, -mlog0);
            float y10 = fmaf(s[j][2], LOG2E, -mlog1);
            float y11 = fmaf(s[j][3], LOG2E, -mlog1);
            pf[j][0] = ex2h2(h2u(y00, y01));
            pf[j][1] = ex2h2(h2u(y10, y11));
        }

        // ---- O += P @ V ; l += P @ ones -------------------------------------
#pragma unroll
        for (int tkp = 0; tkp < 2; tkp++) {
            uint32_t a00 = pf[4 * tkp + 0][0], a01 = pf[4 * tkp + 0][1];
            uint32_t a02 = pf[4 * tkp + 1][0], a03 = pf[4 * tkp + 1][1];
            uint32_t a10 = pf[4 * tkp + 2][0], a11 = pf[4 * tkp + 2][1];
            uint32_t a12 = pf[4 * tkp + 3][0], a13 = pf[4 * tkp + 3][1];
            mma16(lacc, a00, a01, a02, a03, ONES2, ONES2);
            mma16(lacc, a10, a11, a12, a13, ONES2, ONES2);
#pragma unroll
            for (int j = 0; j < 8; j++) {
                uint4 vb = *(const uint4*)(Vsb + (8 * j + g) * 128 + c * 16 + ((tkp << 6) ^ swz));
                mma16(o[j], a00, a01, a02, a03, vb.x, vb.y);
                mma16(o[j], a10, a11, a12, a13, vb.z, vb.w);
            }
        }
    }

    float inv0 = 1.0f / lacc[0], inv1 = 1.0f / lacc[2];
    const int grow0 = q0 + r0;
#pragma unroll
    for (int j = 0; j < 8; j++) {
        int col = h * HD + 8 * j + 2 * c;
        size_t p = (size_t)grow0 * DM + (col & ~15) + ppos(col & 15);
        *(uint32_t*)&O16[p]                  = h2u(o[j][0] * inv0, o[j][1] * inv0);
        *(uint32_t*)&O16[p + (size_t)8 * DM] = h2u(o[j][2] * inv1, o[j][3] * inv1);
    }
}

// ---------------- warp-per-row residual + LayerNorm -------------------------
template <bool PACK>
__global__ __launch_bounds__(256) void add_ln(
    const float* __restrict__ A, const float* __restrict__ B,
    const float* __restrict__ g, const float* __restrict__ be,
    float* __restrict__ out, __half* __restrict__ out16)
{
    const int row = blockIdx.x * 8 + (threadIdx.x >> 5);
    const int lane = threadIdx.x & 31;
    const float* ap = A + (size_t)row * DM;
    const float* bp = B + (size_t)row * DM;

    float4 v[4];
    float s = 0.f;
#pragma unroll
    for (int i = 0; i < 4; i++) {
        int col = (i * 32 + lane) * 4;
        float4 a = *(const float4*)(ap + col);
        float4 b = *(const float4*)(bp + col);
        v[i] = make_float4(a.x + b.x, a.y + b.y, a.z + b.z, a.w + b.w);
        s += v[i].x + v[i].y + v[i].z + v[i].w;
    }
#pragma unroll
    for (int off = 16; off; off >>= 1) s += __shfl_xor_sync(0xffffffffu, s, off);
    float mu = s * (1.f / DM);

    float sq = 0.f;
#pragma unroll
    for (int i = 0; i < 4; i++) {
        v[i].x -= mu; v[i].y -= mu; v[i].z -= mu; v[i].w -= mu;
        sq += v[i].x * v[i].x + v[i].y * v[i].y + v[i].z * v[i].z + v[i].w * v[i].w;
    }
#pragma unroll
    for (int off = 16; off; off >>= 1) sq += __shfl_xor_sync(0xffffffffu, sq, off);
    float inv = rsqrtf(sq * (1.f / DM) + 1e-5f);

#pragma unroll
    for (int i = 0; i < 4; i++) {
        int col = (i * 32 + lane) * 4;
        float4 gg = *(const float4*)(g + col);
        float4 bb = *(const float4*)(be + col);
        float4 r;
        r.x = v[i].x * inv * gg.x + bb.x;
        r.y = v[i].y * inv * gg.y + bb.y;
        r.z = v[i].z * inv * gg.z + bb.z;
        r.w = v[i].w * inv * gg.w + bb.w;
        *(float4*)(out + (size_t)row * DM + col) = r;
        if (PACK) {
            size_t base = (size_t)row * DM + (col & ~15);
            *(uint32_t*)&out16[base + ppos(col & 15)]       = h2u(r.x, r.y);
            *(uint32_t*)&out16[base + ppos((col + 2) & 15)] = h2u(r.z, r.w);
        }
    }
}

// ---------------- launch ----------------------------------------------------
extern "C" void kernel_launch(void* const* d_in, const int* in_sizes, int n_in,
                              void* d_out, int out_size)
{
    const float* x    = (const float*)d_in[0];
    const float* bias = (const float*)d_in[1];
    const float* Wq = (const float*)d_in[2];  const float* bq = (const float*)d_in[3];
    const float* Wk = (const float*)d_in[4];  const float* bk = (const float*)d_in[5];
    const float* Wv = (const float*)d_in[6];  const float* bv = (const float*)d_in[7];
    const float* Wo = (const float*)d_in[8];  const float* bo = (const float*)d_in[9];
    const float* g1 = (const float*)d_in[10]; const float* b1 = (const float*)d_in[11];
    const float* g2 = (const float*)d_in[12]; const float* b2 = (const float*)d_in[13];
    const float* W1 = (const float*)d_in[14]; const float* c1 = (const float*)d_in[15];
    const float* W2 = (const float*)d_in[16]; const float* c2 = (const float*)d_in[17];
    float* out = (float*)d_out;

    __half *Qp, *Kp, *Vp, *x16p, *attn16p, *x116p, *hid16p;
    __half *WqT, *WkT, *WvT, *WoT, *W1T, *W2T;
    float *tmpp, *x1p;
    cudaGetSymbolAddress((void**)&Qp,     g_Q);
    cudaGetSymbolAddress((void**)&Kp,     g_K);
    cudaGetSymbolAddress((void**)&Vp,     g_V);
    cudaGetSymbolAddress((void**)&x16p,   g_x16);
    cudaGetSymbolAddress((void**)&attn16p, g_attn16);
    cudaGetSymbolAddress((void**)&x116p,  g_x116);
    cudaGetSymbolAddress((void**)&hid16p, g_hid16);
    cudaGetSymbolAddress((void**)&tmpp,   g_tmp);
    cudaGetSymbolAddress((void**)&x1p,    g_x1);
    cudaGetSymbolAddress((void**)&WqT,    g_WqT);
    cudaGetSymbolAddress((void**)&WkT,    g_WkT);
    cudaGetSymbolAddress((void**)&WvT,    g_WvT);
    cudaGetSymbolAddress((void**)&WoT,    g_WoT);
    cudaGetSymbolAddress((void**)&W1T,    g_W1T);
    cudaGetSymbolAddress((void**)&W2T,    g_W2T);

    const int ATTN_SMEM = 2 * ASTG;   // 106496
    cudaFuncSetAttribute(attn_h, cudaFuncAttributeMaxDynamicSharedMemorySize, ATTN_SMEM);

    pack_x<<<NT * DM / 16 / 256, 256>>>(x, x16p);
    transpose_all<<<dim3(DFF / 32, DFF / 32, 6), 256>>>(
        Wq, Wk, Wv, Wo, W1, W2, WqT, WkT, WvT, WoT, W1T, W2T);

    dim3 blk(256);
    qkv16<<<dim3(DM / 128, NT / 64, 3), blk>>>(
        x16p, WqT, bq, Qp, WkT, bk, Kp, WvT, bv, Vp);

    attn_h<<<dim3(NT / 128, NH), blk, ATTN_SMEM>>>(Qp, Kp, Vp, bias, attn16p);

    gemm16<0><<<dim3(DM / 128, NT / 64), blk>>>(attn16p, WoT, bo, tmpp, DM, DM);
    add_ln<true><<<NT / 8, 256>>>(x, tmpp, g1, b1, x1p, x116p);

    gemm16<1><<<dim3(DFF / 128, NT / 64), blk>>>(x116p, W1T, c1, hid16p, DFF, DM);
    gemm16<0><<<dim3(DM / 128, NT / 64), blk>>>(hid16p, W2T, c2, tmpp, DM, DFF);
    add_ln<false><<<NT / 8, 256>>>(x1p, tmpp, g2, b2, out, nullptr);
}